// round 12
// baseline (speedup 1.0000x reference)
#include <cuda_runtime.h>
#include <cuda_bf16.h>
#include <cstdint>
#include <math.h>

#define NG 16384
#define OFFN (18*16384)
#define KDIM 2304
#define WSZ (256*256*9)
#define PL 589824
#define COL_SMEM 197632
#define SPL 25344
#define BIG_SMEM 135168
#define SMALL_SMEM 110592

// ---------------- scratch ----------------
__device__ __nv_bfloat16 g_wahi[(size_t)12*PL];
__device__ __nv_bfloat16 g_walo[(size_t)12*PL];
__device__ __nv_bfloat16 g_fhi[(size_t)NG*256];
__device__ __nv_bfloat16 g_flo[(size_t)NG*256];
// stream-1 planes + scratch
__device__ __nv_bfloat16 g_t1hi[(size_t)NG*256];
__device__ __nv_bfloat16 g_t1lo[(size_t)NG*256];
__device__ __nv_bfloat16 g_u1hi[(size_t)NG*256];
__device__ __nv_bfloat16 g_u1lo[(size_t)NG*256];
__device__ __nv_bfloat16 g_col1h[(size_t)NG*KDIM];
__device__ __nv_bfloat16 g_col1l[(size_t)NG*KDIM];
__device__ __nv_bfloat16 g_ws1hi[(size_t)4*PL];
__device__ __nv_bfloat16 g_ws1lo[(size_t)4*PL];
__device__ float g_st1[3*2048];
__device__ float g_scsh1[2048];
__device__ float g_bias1[1024];
__device__ __nv_bfloat16 g_pad1h[1024];
__device__ __nv_bfloat16 g_pad1l[1024];
// stream-2 planes + scratch
__device__ __nv_bfloat16 g_t2hi[(size_t)NG*256];
__device__ __nv_bfloat16 g_t2lo[(size_t)NG*256];
__device__ __nv_bfloat16 g_u2hi[(size_t)NG*256];
__device__ __nv_bfloat16 g_u2lo[(size_t)NG*256];
__device__ __nv_bfloat16 g_col2h[(size_t)NG*KDIM];
__device__ __nv_bfloat16 g_col2l[(size_t)NG*KDIM];
__device__ __nv_bfloat16 g_ws2hi[(size_t)4*PL];
__device__ __nv_bfloat16 g_ws2lo[(size_t)4*PL];
__device__ float g_st2[3*2048];
__device__ float g_scsh2[2048];
__device__ float g_bias2[1024];
__device__ __nv_bfloat16 g_pad2h[1024];
__device__ __nv_bfloat16 g_pad2l[1024];
__device__ float g_off1[OFFN];
__device__ float g_off2[OFFN];

// ---------------- PTX helpers ----------------
__device__ __forceinline__ uint32_t smem_u32(const void* p) {
    uint32_t a;
    asm("{ .reg .u64 t; cvta.to.shared.u64 t, %1; cvt.u32.u64 %0, t; }" : "=r"(a) : "l"(p));
    return a;
}
#define SWZ(o)   ((o) ^ (((o) >> 3) & 0x70))
#define SWZ64(o) ((o) ^ (((o) >> 3) & 0x30))

__device__ __forceinline__ void cp16(uint32_t dst, const void* src, int ss) {
    asm volatile("cp.async.cg.shared.global [%0], [%1], 16, %2;\n" :: "r"(dst), "l"(src), "r"(ss));
}
__device__ __forceinline__ void cp_commit() { asm volatile("cp.async.commit_group;\n" ::: "memory"); }
__device__ __forceinline__ void cp_wait0()  { asm volatile("cp.async.wait_group 0;\n" ::: "memory"); }
__device__ __forceinline__ void cp_wait1()  { asm volatile("cp.async.wait_group 1;\n" ::: "memory"); }

__device__ __forceinline__ void ldm4(uint32_t* r, uint32_t addr) {
    asm volatile("ldmatrix.sync.aligned.m8n8.x4.shared.b16 {%0,%1,%2,%3}, [%4];"
        : "=r"(r[0]), "=r"(r[1]), "=r"(r[2]), "=r"(r[3]) : "r"(addr));
}
__device__ __forceinline__ void mma16816(float* d, const uint32_t* a, const uint32_t* b) {
    asm volatile("mma.sync.aligned.m16n8k16.row.col.f32.bf16.bf16.f32 "
        "{%0,%1,%2,%3}, {%4,%5,%6,%7}, {%8,%9}, {%0,%1,%2,%3};"
        : "+f"(d[0]), "+f"(d[1]), "+f"(d[2]), "+f"(d[3])
        : "r"(a[0]), "r"(a[1]), "r"(a[2]), "r"(a[3]), "r"(b[0]), "r"(b[1]));
}
__device__ __forceinline__ unsigned short bfbits(float x) {
    __nv_bfloat16 h = __float2bfloat16(x);
    return *reinterpret_cast<unsigned short*>(&h);
}

// ---------------- epilogues ----------------
template<int IM>
__device__ __forceinline__ void epilogue_nchw(float acc[IM][4][4], float* out, int bstride,
                                              int M, int m0, int n0, int wm, int wn, int lane) {
    int b = n0 >> 12, ij0 = n0 & 4095;
    float* outb = out + (size_t)b * bstride + ij0;
#pragma unroll
    for (int im = 0; im < IM; im++) {
        int mrow = m0 + wm + im * 16 + (lane >> 2);
#pragma unroll
        for (int jn = 0; jn < 4; jn++) {
            int ncol = wn + jn * 8 + (lane & 3) * 2;
            if (mrow < M) {
                float2 v = make_float2(acc[im][jn][0], acc[im][jn][1]);
                *(float2*)(outb + (size_t)mrow * 4096 + ncol) = v;
            }
            if (mrow + 8 < M) {
                float2 v = make_float2(acc[im][jn][2], acc[im][jn][3]);
                *(float2*)(outb + (size_t)(mrow + 8) * 4096 + ncol) = v;
            }
        }
    }
}

// split planes (+optional bias, +optional GN stats). 512-thread CTA, IM=4.
__device__ __forceinline__ void epilogue_split2(float acc[4][4][4],
                                                __nv_bfloat16* ohi, __nv_bfloat16* olo,
                                                char* smraw, int m0, int n0,
                                                int tid, int wid, int wm, int wn, int lane,
                                                const float* bias, float* stat) {
    int b = n0 >> 12;
    if (bias) {
#pragma unroll
        for (int im = 0; im < 4; im++) {
            int r0 = m0 + wm + im * 16 + (lane >> 2);
            float b0 = bias[b * 256 + r0];
            float b1 = bias[b * 256 + r0 + 8];
#pragma unroll
            for (int jn = 0; jn < 4; jn++) {
                acc[im][jn][0] += b0; acc[im][jn][1] += b0;
                acc[im][jn][2] += b1; acc[im][jn][3] += b1;
            }
        }
    }
    float* smemf = (float*)smraw;
    if (stat) {
        float* ssum = smemf + 4224;
        float* ssq  = smemf + 4352;
        if (tid < 128) { ssum[tid] = 0.f; ssq[tid] = 0.f; }
        __syncthreads();
#pragma unroll
        for (int im = 0; im < 4; im++) {
#pragma unroll
            for (int h2 = 0; h2 < 2; h2++) {
                int rl = wm + im * 16 + (lane >> 2) + h2 * 8;
                float s = 0.f, q = 0.f;
#pragma unroll
                for (int jn = 0; jn < 4; jn++) {
                    float v0 = acc[im][jn][h2 * 2], v1 = acc[im][jn][h2 * 2 + 1];
                    s += v0 + v1;
                    q += v0 * v0 + v1 * v1;
                }
                atomicAdd(&ssum[rl], s);
                atomicAdd(&ssq[rl], q);
            }
        }
        __syncthreads();
        if (tid < 128) {
            atomicAdd(&stat[(b * 256 + m0 + tid) * 2], ssum[tid]);
            atomicAdd(&stat[(b * 256 + m0 + tid) * 2 + 1], ssq[tid]);
        }
    }
    for (int ch = 0; ch < 8; ch++) {
        __syncthreads();
        if ((wid & 7) == ch) {
#pragma unroll
            for (int im = 0; im < 4; im++) {
                int m = wm + im * 16 + (lane >> 2);
#pragma unroll
                for (int jn = 0; jn < 4; jn++) {
                    int nl = jn * 8 + (lane & 3) * 2;
                    smemf[m * 33 + nl] = acc[im][jn][0];
                    smemf[m * 33 + nl + 1] = acc[im][jn][1];
                    smemf[(m + 8) * 33 + nl] = acc[im][jn][2];
                    smemf[(m + 8) * 33 + nl + 1] = acc[im][jn][3];
                }
            }
        }
        __syncthreads();
        int p = tid >> 4;
        int cq = (tid & 15) * 8;
        size_t base = (size_t)(n0 + ch * 32 + p) * 256 + m0 + cq;
        uint32_t hw[4], lw[4];
#pragma unroll
        for (int i = 0; i < 4; i++) {
            float v0 = smemf[(cq + 2 * i) * 33 + p];
            float v1 = smemf[(cq + 2 * i + 1) * 33 + p];
            unsigned short h0 = bfbits(v0), h1 = bfbits(v1);
            float r0 = v0 - __bfloat162float(*reinterpret_cast<__nv_bfloat16*>(&h0));
            float r1 = v1 - __bfloat162float(*reinterpret_cast<__nv_bfloat16*>(&h1));
            hw[i] = (uint32_t)h0 | ((uint32_t)h1 << 16);
            lw[i] = (uint32_t)bfbits(r0) | ((uint32_t)bfbits(r1) << 16);
        }
        *(uint4*)(ohi + base) = make_uint4(hw[0], hw[1], hw[2], hw[3]);
        *(uint4*)(olo + base) = make_uint4(lw[0], lw[1], lw[2], lw[3]);
    }
}

// ---------------- weight convert (plain) ----------------
struct W12 { const float* p[12]; int m[12]; };
__global__ __launch_bounds__(256) void wconv_all_k(W12 w,
                                                   __nv_bfloat16* __restrict__ hi,
                                                   __nv_bfloat16* __restrict__ lo) {
    __shared__ float rows[4][KDIM];
    int t = blockIdx.x >> 6;
    int rb = blockIdx.x & 63;
    int tid = threadIdx.x;
    int m0 = rb * 4;
    const float* src = w.p[t];
    int Mv = w.m[t];
    for (int i = tid; i < 4 * KDIM; i += 256) {
        int r = i / KDIM, k = i - r * KDIM;
        int m = m0 + r;
        rows[r][k] = (m < Mv) ? src[(size_t)m * KDIM + k] : 0.f;
    }
    __syncthreads();
    for (int i = tid; i < 4 * KDIM; i += 256) {
        int r = i / KDIM, k = i - r * KDIM;
        int kk = k >> 8, c = k & 255;
        float v = rows[r][c * 9 + kk];
        size_t dst = (size_t)t * PL + (size_t)(m0 + r) * KDIM + k;
        __nv_bfloat16 h = __float2bfloat16(v);
        hi[dst] = h;
        lo[dst] = __float2bfloat16(v - __bfloat162float(h));
    }
}

// ---------------- zero stats ----------------
__global__ __launch_bounds__(256) void zerostat_k(float* a, float* b, int n) {
    int i = blockIdx.x * 256 + threadIdx.x;
    if (i < n) { a[i] = 0.f; b[i] = 0.f; }
}

// ---------------- GN finalize: stats -> sc/sh + pad = -sh/sc (bf16 hi/lo) ----------------
__global__ __launch_bounds__(256) void gnfin_k(const float* __restrict__ st,
                                               const float* __restrict__ gamma,
                                               const float* __restrict__ beta,
                                               float* __restrict__ scsh,
                                               __nv_bfloat16* __restrict__ padh,
                                               __nv_bfloat16* __restrict__ padl) {
    int b = blockIdx.x;
    int tid = threadIdx.x;
    __shared__ float gm[32], gr[32];
    if (tid < 32) {
        float s = 0.f, q = 0.f;
        for (int i = 0; i < 8; i++) {
            int idx = (b * 256 + tid * 8 + i) * 2;
            s += st[idx];
            q += st[idx + 1];
        }
        float mean = s * (1.f / 32768.f);
        float var = q * (1.f / 32768.f) - mean * mean;
        gm[tid] = mean;
        gr[tid] = rsqrtf(var + 1e-5f);
    }
    __syncthreads();
    int c = tid;
    float sc = gr[c >> 3] * gamma[c];
    float sh = beta[c] - gm[c >> 3] * sc;
    scsh[(b * 256 + c) * 2] = sc;
    scsh[(b * 256 + c) * 2 + 1] = sh;
    float pad = -sh / sc;
    __nv_bfloat16 h = __float2bfloat16(pad);
    padh[b * 256 + c] = h;
    padl[b * 256 + c] = __float2bfloat16(pad - __bfloat162float(h));
}

// ---------------- wscale: fold GN affine into next conv's weights ----------------
__global__ __launch_bounds__(256) void wscale_k(const float* __restrict__ w,
                                                const float* __restrict__ scsh,
                                                __nv_bfloat16* __restrict__ whi,
                                                __nv_bfloat16* __restrict__ wlo,
                                                float* __restrict__ biasOut) {
    __shared__ float rows[4][KDIM];
    __shared__ float scs[256], shs[256];
    __shared__ float biasAcc[4];
    int b = blockIdx.x >> 6;
    int rb = blockIdx.x & 63;
    int tid = threadIdx.x;
    int m0 = rb * 4;
    scs[tid] = scsh[(b * 256 + tid) * 2];
    shs[tid] = scsh[(b * 256 + tid) * 2 + 1];
    if (tid < 4) biasAcc[tid] = 0.f;
    for (int i = tid; i < 4 * KDIM; i += 256) {
        int r = i / KDIM, k = i - r * KDIM;
        rows[r][k] = w[(size_t)(m0 + r) * KDIM + k];
    }
    __syncthreads();
    for (int i = tid; i < 4 * KDIM; i += 256) {
        int r = i / KDIM, k = i - r * KDIM;
        int kk = k >> 8, c = k & 255;
        float wv = rows[r][c * 9 + kk];
        float v = wv * scs[c];
        size_t dst = (size_t)b * PL + (size_t)(m0 + r) * KDIM + k;
        __nv_bfloat16 h = __float2bfloat16(v);
        whi[dst] = h;
        wlo[dst] = __float2bfloat16(v - __bfloat162float(h));
        atomicAdd(&biasAcc[r], wv * shs[c]);
    }
    __syncthreads();
    if (tid < 4) biasOut[b * 256 + m0 + tid] = biasAcc[tid];
}

// ---------------- feature NCHW fp32 -> NHWC hi/lo ----------------
__global__ void tsplit_k(const float* __restrict__ in,
                         __nv_bfloat16* __restrict__ hi, __nv_bfloat16* __restrict__ lo) {
    __shared__ float t[32][33];
    int b = blockIdx.z, hw0 = blockIdx.x * 32, c0 = blockIdx.y * 32;
    int tx = threadIdx.x, ty = threadIdx.y;
    const float* ip = in + (size_t)b * 256 * 4096;
    for (int r = ty; r < 32; r += 8)
        t[r][tx] = ip[(size_t)(c0 + r) * 4096 + hw0 + tx];
    __syncthreads();
    for (int r = ty; r < 32; r += 8) {
        float v = t[tx][r];
        size_t idx = (size_t)b * 4096 * 256 + (size_t)(hw0 + r) * 256 + c0 + tx;
        __nv_bfloat16 h = __float2bfloat16(v);
        hi[idx] = h;
        lo[idx] = __float2bfloat16(v - __bfloat162float(h));
    }
}

// ---------------- slab-based implicit-conv GEMM ----------------
// EPI: 0 = NCHW fp32, 1 = split planes (+bias), 2 = split planes + stats (+bias)
// padhi/padlo: per-(b,c) substitute value for OOB taps (folded-GN pad); nullptr = zfill.
template<int MROWS, int NTHREADS, int EPI>
__global__ __launch_bounds__(NTHREADS, 1) void gemm_conv_k(
    const __nv_bfloat16* __restrict__ Ahi, const __nv_bfloat16* __restrict__ Alo,
    const __nv_bfloat16* __restrict__ Bhi, const __nv_bfloat16* __restrict__ Blo,
    const __nv_bfloat16* __restrict__ padhi, const __nv_bfloat16* __restrict__ padlo,
    float* __restrict__ out, __nv_bfloat16* __restrict__ ohi, __nv_bfloat16* __restrict__ olo,
    const float* __restrict__ bias, float* __restrict__ stat, int a_bstride,
    int M, int bstride) {
    constexpr int MW = NTHREADS / 256;
    constexpr int IM = MROWS / (MW * 16);
    constexpr int APL = MROWS * 64;
    constexpr int AST = 2 * APL;
    constexpr int SST = 2 * SPL;

    extern __shared__ char smx[];
    uint32_t smb = (smem_u32(smx) + 1023) & ~1023u;
    uint32_t aB = smb, sB = smb + 2 * AST;

    int tid = threadIdx.x;
    int lane = tid & 31;
    int wid = tid >> 5;
    int wm = (wid >> 3) * (IM * 16);
    int wn = (wid & 7) * 32;
    int n0 = blockIdx.x * 256;
    int m0 = blockIdx.y * MROWS;
    int b = n0 >> 12, ij0 = n0 & 4095;
    int i0 = ij0 >> 6;
    const __nv_bfloat16* Ah = Ahi + (size_t)b * a_bstride;
    const __nv_bfloat16* Al = Alo + (size_t)b * a_bstride;

    auto load_A = [&](int t, uint32_t dst) {
        int cg = t / 9, tap = t - cg * 9;
        int koff = tap * 256 + cg * 32;
#pragma unroll
        for (int idx = tid; idx < MROWS * 8; idx += NTHREADS) {
            int plane = idx >= MROWS * 4;
            int q = idx - plane * (MROWS * 4);
            int row = q >> 2, c16 = q & 3;
            const __nv_bfloat16* src =
                (plane ? Al : Ah) + (size_t)(m0 + row) * KDIM + koff + c16 * 8;
            cp16(dst + plane * APL + SWZ64(row * 64 + c16 * 16), src, 16);
        }
    };
    auto load_slab = [&](int cg, uint32_t dst) {
        for (int idx = tid; idx < 3168; idx += NTHREADS) {
            int plane = idx >= 1584;
            int q = idx - plane * 1584;
            int pix = q >> 2, c16 = q & 3;
            int sy = pix / 66, sx = pix - sy * 66;
            int y = i0 - 1 + sy, x = sx - 1;
            bool v = ((unsigned)y < 64u) && ((unsigned)x < 64u);
            const __nv_bfloat16* src;
            int ss = 16;
            if (v) {
                src = (plane ? Blo : Bhi) +
                    ((((size_t)b * 64 + y) * 64 + x) << 8) + cg * 32 + c16 * 8;
            } else if (padhi) {
                src = (plane ? padlo : padhi) + b * 256 + cg * 32 + c16 * 8;
            } else {
                src = (plane ? Blo : Bhi) + ((size_t)b << 20) + cg * 32 + c16 * 8;
                ss = 0;
            }
            cp16(dst + plane * SPL + SWZ64(pix * 64 + c16 * 16), src, ss);
        }
    };

    float acc[IM][4][4];
#pragma unroll
    for (int im = 0; im < IM; im++)
#pragma unroll
        for (int jn = 0; jn < 4; jn++)
#pragma unroll
            for (int q = 0; q < 4; q++) acc[im][jn][q] = 0.f;

    int arow = lane & 15;
    int abyte = (lane >> 4) * 16;
    int mi = lane >> 3;
    int brow_off = (mi >> 1) * 8 + (lane & 7);
    int bbyte = (mi & 1) * 16;
    int b66[2];
#pragma unroll
    for (int jp = 0; jp < 2; jp++) {
        int rowb = wn + jp * 16 + brow_off;
        b66[jp] = (rowb >> 6) * 66 + (rowb & 63);
    }

    load_slab(0, sB);
    load_A(0, aB);
    cp_commit();

    for (int t = 0; t < 72; t++) {
        int cg = t / 9, tap = t - cg * 9;
        if (t + 1 < 72) {
            load_A(t + 1, aB + ((t + 1) & 1) * AST);
            if (tap == 4 && cg < 7) load_slab(cg + 1, sB + ((cg + 1) & 1) * SST);
            cp_commit();
            cp_wait1();
        } else {
            cp_wait0();
        }
        __syncthreads();

        uint32_t ab = aB + (t & 1) * AST;
        uint32_t sb = sB + (cg & 1) * SST;
        int kd = (tap * 11) >> 5;
        int tapoff = kd * 66 + (tap - kd * 3);
#pragma unroll
        for (int s = 0; s < 2; s++) {
            uint32_t bh[4][2], bl[4][2];
#pragma unroll
            for (int jp = 0; jp < 2; jp++) {
                int pix = b66[jp] + tapoff;
                uint32_t off = SWZ64(pix * 64 + s * 32 + bbyte);
                uint32_t r4[4];
                ldm4(r4, sb + off);
                bh[jp * 2][0] = r4[0]; bh[jp * 2][1] = r4[1];
                bh[jp * 2 + 1][0] = r4[2]; bh[jp * 2 + 1][1] = r4[3];
                ldm4(r4, sb + SPL + off);
                bl[jp * 2][0] = r4[0]; bl[jp * 2][1] = r4[1];
                bl[jp * 2 + 1][0] = r4[2]; bl[jp * 2 + 1][1] = r4[3];
            }
#pragma unroll
            for (int im = 0; im < IM; im++) {
                int rowa = wm + im * 16 + arow;
                uint32_t offa = SWZ64(rowa * 64 + s * 32 + abyte);
                uint32_t ah[4], al[4];
                ldm4(ah, ab + offa);
                ldm4(al, ab + APL + offa);
#pragma unroll
                for (int jn = 0; jn < 4; jn++) {
                    mma16816(acc[im][jn], ah, bh[jn]);
                    mma16816(acc[im][jn], ah, bl[jn]);
                    mma16816(acc[im][jn], al, bh[jn]);
                }
            }
        }
        __syncthreads();
    }

    if (EPI == 0) {
        epilogue_nchw<IM>(acc, out, bstride, M, m0, n0, wm, wn, lane);
    } else {
        epilogue_split2(acc, ohi, olo, smx, m0, n0, tid, wid, wm, wn, lane,
                        bias, EPI == 2 ? stat : nullptr);
    }
}

// ---------------- col-based GEMM for deform convs ----------------
template<int EPI>
__global__ __launch_bounds__(512, 1) void gemm_col_k(const __nv_bfloat16* __restrict__ Ahi,
                                                     const __nv_bfloat16* __restrict__ Alo,
                                                     const __nv_bfloat16* __restrict__ Bhi,
                                                     const __nv_bfloat16* __restrict__ Blo,
                                                     float* __restrict__ out,
                                                     __nv_bfloat16* __restrict__ ohi,
                                                     __nv_bfloat16* __restrict__ olo,
                                                     int M, int bstride) {
    extern __shared__ char smx[];
    uint32_t smb = (smem_u32(smx) + 1023) & ~1023u;
    int tid = threadIdx.x;
    int lane = tid & 31;
    int wid = tid >> 5;
    int wm = (wid >> 3) * 64;
    int wn = (wid & 7) * 32;
    int n0 = blockIdx.x * 256;
    int m0 = blockIdx.y * 128;

    auto load_stage = [&](int t, uint32_t sb) {
        int kk = t >> 2, cg = t & 3;
        int koff = kk * 256 + cg * 64;
#pragma unroll
        for (int qi = 0; qi < 12; qi++) {
            int q = qi * 512 + tid;
            if (qi < 4) {
                int plane = (q >> 10) & 1;
                int qq = q & 1023;
                int row = qq >> 3, c16 = qq & 7;
                const __nv_bfloat16* src =
                    (plane ? Alo : Ahi) + (size_t)(m0 + row) * KDIM + koff + c16 * 8;
                cp16(sb + plane * 16384 + SWZ(row * 128 + c16 * 16), src, 16);
            } else {
                int qb = q - 2048;
                int plane = qb >> 11;
                int qq = qb & 2047;
                int row = qq >> 3, c16 = qq & 7;
                const __nv_bfloat16* src =
                    (plane ? Blo : Bhi) + (size_t)(n0 + row) * KDIM + koff + c16 * 8;
                cp16(sb + 32768 + plane * 32768 + SWZ(row * 128 + c16 * 16), src, 16);
            }
        }
    };

    float acc[4][4][4];
#pragma unroll
    for (int im = 0; im < 4; im++)
#pragma unroll
        for (int jn = 0; jn < 4; jn++)
#pragma unroll
            for (int q = 0; q < 4; q++) acc[im][jn][q] = 0.f;

    load_stage(0, smb);
    cp_commit();

    int arow_off = (lane & 15);
    int abyte = (lane >> 4) * 16;
    int mi = lane >> 3;
    int brow_off = (mi >> 1) * 8 + (lane & 7);
    int bbyte = (mi & 1) * 16;

    for (int t = 0; t < 36; t++) {
        if (t + 1 < 36) {
            load_stage(t + 1, smb + ((t + 1) & 1) * 98304);
            cp_commit();
            cp_wait1();
        } else {
            cp_wait0();
        }
        __syncthreads();

        uint32_t sb = smb + (t & 1) * 98304;
        uint32_t ahB = sb, alB = sb + 16384, bhB = sb + 32768, blB = sb + 65536;
#pragma unroll
        for (int s = 0; s < 4; s++) {
            uint32_t bh[4][2], bl[4][2];
#pragma unroll
            for (int jp = 0; jp < 2; jp++) {
                int rowb = wn + jp * 16 + brow_off;
                uint32_t off = SWZ(rowb * 128 + s * 32 + bbyte);
                uint32_t r4[4];
                ldm4(r4, bhB + off);
                bh[jp * 2][0] = r4[0]; bh[jp * 2][1] = r4[1];
                bh[jp * 2 + 1][0] = r4[2]; bh[jp * 2 + 1][1] = r4[3];
                ldm4(r4, blB + off);
                bl[jp * 2][0] = r4[0]; bl[jp * 2][1] = r4[1];
                bl[jp * 2 + 1][0] = r4[2]; bl[jp * 2 + 1][1] = r4[3];
            }
#pragma unroll
            for (int im = 0; im < 4; im++) {
                int rowa = wm + im * 16 + arow_off;
                uint32_t off = SWZ(rowa * 128 + s * 32 + abyte);
                uint32_t ah[4], al[4];
                ldm4(ah, ahB + off);
                ldm4(al, alB + off);
#pragma unroll
                for (int jn = 0; jn < 4; jn++) {
                    mma16816(acc[im][jn], ah, bh[jn]);
                    mma16816(acc[im][jn], ah, bl[jn]);
                    mma16816(acc[im][jn], al, bh[jn]);
                }
            }
        }
        __syncthreads();
    }

    if (EPI == 0) {
        epilogue_nchw<4>(acc, out, bstride, M, m0, n0, wm, wn, lane);
    } else {
        epilogue_split2(acc, ohi, olo, smx, m0, n0, tid, wid, wm, wn, lane,
                        nullptr, nullptr);
    }
}

// ---------------- deformable gather with inline GN affine ----------------
__global__ __launch_bounds__(256) void deform_col_k(const __nv_bfloat16* __restrict__ xhi,
                                                    const __nv_bfloat16* __restrict__ xlo,
                                                    const float* __restrict__ scsh,
                                                    const float* __restrict__ off,
                                                    __nv_bfloat16* __restrict__ colh,
                                                    __nv_bfloat16* __restrict__ coll) {
    int warp = (blockIdx.x * 256 + threadIdx.x) >> 5;
    int lane = threadIdx.x & 31;
    if (warp >= NG) return;
    int n = warp;
    int b = n >> 12, ij = n & 4095, i = ij >> 6, j = ij & 63;
    const float* offb = off + (size_t)b * 18 * 4096 + ij;
    float scv[8], shv[8];
#pragma unroll
    for (int it = 0; it < 8; it++) {
        int c = lane + it * 32;
        scv[it] = scsh[(b * 256 + c) * 2];
        shv[it] = scsh[(b * 256 + c) * 2 + 1];
    }
#pragma unroll
    for (int k = 0; k < 9; k++) {
        float dy = offb[(size_t)(2 * k) << 12];
        float dx = offb[(size_t)(2 * k + 1) << 12];
        float y = dy + (float)(i - 1 + k / 3);
        float x = dx + (float)(j - 1 + k % 3);
        float y0f = floorf(y), x0f = floorf(x);
        int y0 = (int)y0f, x0 = (int)x0f;
        float wy = y - y0f, wx = x - x0f;
        bool vy0 = (unsigned)y0 < 64u;
        bool vy1 = (unsigned)(y0 + 1) < 64u;
        bool vx0 = (unsigned)x0 < 64u;
        bool vx1 = (unsigned)(x0 + 1) < 64u;
        float w00 = (vy0 && vx0) ? (1.f - wy) * (1.f - wx) : 0.f;
        float w01 = (vy0 && vx1) ? (1.f - wy) * wx : 0.f;
        float w10 = (vy1 && vx0) ? wy * (1.f - wx) : 0.f;
        float w11 = (vy1 && vx1) ? wy * wx : 0.f;
        float wsum = w00 + w01 + w10 + w11;
        int cy0 = min(max(y0, 0), 63), cy1 = min(max(y0 + 1, 0), 63);
        int cx0 = min(max(x0, 0), 63), cx1 = min(max(x0 + 1, 0), 63);
        size_t i00 = (((size_t)b * 64 + cy0) * 64 + cx0) * 256;
        size_t i01 = (((size_t)b * 64 + cy0) * 64 + cx1) * 256;
        size_t i10 = (((size_t)b * 64 + cy1) * 64 + cx0) * 256;
        size_t i11 = (((size_t)b * 64 + cy1) * 64 + cx1) * 256;
        __nv_bfloat16* ch = colh + (size_t)n * KDIM + k * 256;
        __nv_bfloat16* cl = coll + (size_t)n * KDIM + k * 256;
#pragma unroll
        for (int it = 0; it < 8; it++) {
            int c = lane + it * 32;
            float x00 = __bfloat162float(xhi[i00 + c]) + __bfloat162float(xlo[i00 + c]);
            float x01 = __bfloat162float(xhi[i01 + c]) + __bfloat162float(xlo[i01 + c]);
            float x10 = __bfloat162float(xhi[i10 + c]) + __bfloat162float(xlo[i10 + c]);
            float x11 = __bfloat162float(xhi[i11 + c]) + __bfloat162float(xlo[i11 + c]);
            float bilin = w00 * x00 + w01 * x01 + w10 * x10 + w11 * x11;
            float v = scv[it] * bilin + shv[it] * wsum;
            __nv_bfloat16 h = __float2bfloat16(v);
            ch[c] = h;
            cl[c] = __float2bfloat16(v - __bfloat162float(h));
        }
    }
}

// ---------------- rep-points epilogue ----------------
__global__ __launch_bounds__(256) void reppoints_k(const float* __restrict__ off1,
                                                   const float* __restrict__ off2,
                                                   float* __restrict__ out) {
    int idx = blockIdx.x * 256 + threadIdx.x;
    if (idx >= OFFN) return;
    int rem = idx % 73728;
    int ch = rem >> 12;
    int ij = rem & 4095;
    int i = ij >> 6, j = ij & 63;
    int k = ch >> 1;
    float init = (ch & 1) ? (float)(j + (k % 3) - 1) : (float)(i + (k / 3) - 1);
    float r1 = init + off1[idx];
    out[idx] = r1;
    out[OFFN + idx] = r1 + off2[idx];
}

// ---------------- host orchestration ----------------
extern "C" void kernel_launch(void* const* d_in, const int* in_sizes, int n_in,
                              void* d_out, int out_size) {
    const float* feature = (const float*)d_in[0];
    const float* loc_ws  = (const float*)d_in[1];
    const float* loc_g   = (const float*)d_in[2];
    const float* loc_b   = (const float*)d_in[3];
    const float* cls_ws  = (const float*)d_in[4];
    const float* cls_g   = (const float*)d_in[5];
    const float* cls_b   = (const float*)d_in[6];
    const float* pi_w    = (const float*)d_in[7];
    const float* pio_w   = (const float*)d_in[8];
    const float* prd_w   = (const float*)d_in[9];
    const float* pro_w   = (const float*)d_in[10];
    const float* cd_w    = (const float*)d_in[11];
    const float* co_w    = (const float*)d_in[12];
    float* out = (float*)d_out;

    static int init_done = 0;
    static cudaStream_t s1, s2;
    static cudaEvent_t evRoot, evW, evF, evOff1, evE1, evE2;
    if (!init_done) {
        cudaFuncSetAttribute(gemm_conv_k<128, 512, 0>, cudaFuncAttributeMaxDynamicSharedMemorySize, BIG_SMEM);
        cudaFuncSetAttribute(gemm_conv_k<128, 512, 1>, cudaFuncAttributeMaxDynamicSharedMemorySize, BIG_SMEM);
        cudaFuncSetAttribute(gemm_conv_k<128, 512, 2>, cudaFuncAttributeMaxDynamicSharedMemorySize, BIG_SMEM);
        cudaFuncSetAttribute(gemm_conv_k<32, 256, 0>, cudaFuncAttributeMaxDynamicSharedMemorySize, SMALL_SMEM);
        cudaFuncSetAttribute(gemm_col_k<0>, cudaFuncAttributeMaxDynamicSharedMemorySize, COL_SMEM);
        cudaFuncSetAttribute(gemm_col_k<1>, cudaFuncAttributeMaxDynamicSharedMemorySize, COL_SMEM);
        cudaStreamCreateWithFlags(&s1, cudaStreamNonBlocking);
        cudaStreamCreateWithFlags(&s2, cudaStreamNonBlocking);
        cudaEventCreateWithFlags(&evRoot, cudaEventDisableTiming);
        cudaEventCreateWithFlags(&evW, cudaEventDisableTiming);
        cudaEventCreateWithFlags(&evF, cudaEventDisableTiming);
        cudaEventCreateWithFlags(&evOff1, cudaEventDisableTiming);
        cudaEventCreateWithFlags(&evE1, cudaEventDisableTiming);
        cudaEventCreateWithFlags(&evE2, cudaEventDisableTiming);
        init_done = 1;
    }

    __nv_bfloat16 *wahi, *walo, *fhi, *flo;
    __nv_bfloat16 *t1hi, *t1lo, *u1hi, *u1lo, *col1h, *col1l, *ws1h, *ws1l, *pad1h, *pad1l;
    __nv_bfloat16 *t2hi, *t2lo, *u2hi, *u2lo, *col2h, *col2l, *ws2h, *ws2l, *pad2h, *pad2l;
    float *st1, *st2, *scsh1, *scsh2, *bias1, *bias2, *off1, *off2;
    cudaGetSymbolAddress((void**)&wahi,  g_wahi);
    cudaGetSymbolAddress((void**)&walo,  g_walo);
    cudaGetSymbolAddress((void**)&fhi,   g_fhi);
    cudaGetSymbolAddress((void**)&flo,   g_flo);
    cudaGetSymbolAddress((void**)&t1hi,  g_t1hi);
    cudaGetSymbolAddress((void**)&t1lo,  g_t1lo);
    cudaGetSymbolAddress((void**)&u1hi,  g_u1hi);
    cudaGetSymbolAddress((void**)&u1lo,  g_u1lo);
    cudaGetSymbolAddress((void**)&col1h, g_col1h);
    cudaGetSymbolAddress((void**)&col1l, g_col1l);
    cudaGetSymbolAddress((void**)&ws1h,  g_ws1hi);
    cudaGetSymbolAddress((void**)&ws1l,  g_ws1lo);
    cudaGetSymbolAddress((void**)&pad1h, g_pad1h);
    cudaGetSymbolAddress((void**)&pad1l, g_pad1l);
    cudaGetSymbolAddress((void**)&t2hi,  g_t2hi);
    cudaGetSymbolAddress((void**)&t2lo,  g_t2lo);
    cudaGetSymbolAddress((void**)&u2hi,  g_u2hi);
    cudaGetSymbolAddress((void**)&u2lo,  g_u2lo);
    cudaGetSymbolAddress((void**)&col2h, g_col2h);
    cudaGetSymbolAddress((void**)&col2l, g_col2l);
    cudaGetSymbolAddress((void**)&ws2h,  g_ws2hi);
    cudaGetSymbolAddress((void**)&ws2l,  g_ws2lo);
    cudaGetSymbolAddress((void**)&pad2h, g_pad2h);
    cudaGetSymbolAddress((void**)&pad2l, g_pad2l);
    cudaGetSymbolAddress((void**)&st1,   g_st1);
    cudaGetSymbolAddress((void**)&st2,   g_st2);
    cudaGetSymbolAddress((void**)&scsh1, g_scsh1);
    cudaGetSymbolAddress((void**)&scsh2, g_scsh2);
    cudaGetSymbolAddress((void**)&bias1, g_bias1);
    cudaGetSymbolAddress((void**)&bias2, g_bias2);
    cudaGetSymbolAddress((void**)&off1,  g_off1);
    cudaGetSymbolAddress((void**)&off2,  g_off2);

    W12 w12;
    w12.p[0] = loc_ws;           w12.m[0] = 256;
    w12.p[1] = loc_ws + WSZ;     w12.m[1] = 256;
    w12.p[2] = loc_ws + 2 * WSZ; w12.m[2] = 256;
    w12.p[3] = cls_ws;           w12.m[3] = 256;
    w12.p[4] = cls_ws + WSZ;     w12.m[4] = 256;
    w12.p[5] = cls_ws + 2 * WSZ; w12.m[5] = 256;
    w12.p[6] = pi_w;             w12.m[6] = 256;
    w12.p[7] = pio_w;            w12.m[7] = 18;
    w12.p[8] = prd_w;            w12.m[8] = 256;
    w12.p[9] = pro_w;            w12.m[9] = 18;
    w12.p[10] = cd_w;            w12.m[10] = 256;
    w12.p[11] = co_w;            w12.m[11] = 15;

    dim3 tgrid(128, 8, 4), tblk(32, 8);
    dim3 gBig(64, 2), gSmall(64, 1);

    cudaEventRecord(evRoot, 0);
    cudaStreamWaitEvent(s1, evRoot, 0);
    cudaStreamWaitEvent(s2, evRoot, 0);

    zerostat_k<<<24, 256, 0, s1>>>(st1, st2, 3 * 2048);
    wconv_all_k<<<768, 256, 0, s1>>>(w12, wahi, walo);
    cudaEventRecord(evW, s1);
    tsplit_k<<<tgrid, tblk, 0, s2>>>(feature, fhi, flo);
    cudaEventRecord(evF, s2);
    cudaStreamWaitEvent(s1, evF, 0);
    cudaStreamWaitEvent(s2, evW, 0);

    // ---- s1: loc subnet (fused GN) -> offset1 -> offset2 -> reppoints ----
    gemm_conv_k<128, 512, 2><<<gBig, 512, BIG_SMEM, s1>>>(
        wahi + 0 * (size_t)PL, walo + 0 * (size_t)PL, fhi, flo, nullptr, nullptr,
        nullptr, t1hi, t1lo, nullptr, st1 + 0 * 2048, 0, 256, 0);
    gnfin_k<<<4, 256, 0, s1>>>(st1 + 0 * 2048, loc_g + 0, loc_b + 0, scsh1, pad1h, pad1l);
    wscale_k<<<256, 256, 0, s1>>>(loc_ws + WSZ, scsh1, ws1h, ws1l, bias1);
    gemm_conv_k<128, 512, 2><<<gBig, 512, BIG_SMEM, s1>>>(
        ws1h, ws1l, t1hi, t1lo, pad1h, pad1l,
        nullptr, u1hi, u1lo, bias1, st1 + 1 * 2048, PL, 256, 0);
    gnfin_k<<<4, 256, 0, s1>>>(st1 + 1 * 2048, loc_g + 256, loc_b + 256, scsh1, pad1h, pad1l);
    wscale_k<<<256, 256, 0, s1>>>(loc_ws + 2 * WSZ, scsh1, ws1h, ws1l, bias1);
    gemm_conv_k<128, 512, 2><<<gBig, 512, BIG_SMEM, s1>>>(
        ws1h, ws1l, u1hi, u1lo, pad1h, pad1l,
        nullptr, t1hi, t1lo, bias1, st1 + 2 * 2048, PL, 256, 0);
    gnfin_k<<<4, 256, 0, s1>>>(st1 + 2 * 2048, loc_g + 512, loc_b + 512, scsh1, pad1h, pad1l);
    wscale_k<<<256, 256, 0, s1>>>(pi_w, scsh1, ws1h, ws1l, bias1);
    gemm_conv_k<128, 512, 1><<<gBig, 512, BIG_SMEM, s1>>>(
        ws1h, ws1l, t1hi, t1lo, pad1h, pad1l,
        nullptr, u1hi, u1lo, bias1, nullptr, PL, 256, 0);
    gemm_conv_k<32, 256, 0><<<gSmall, 256, SMALL_SMEM, s1>>>(
        wahi + 7 * (size_t)PL, walo + 7 * (size_t)PL, u1hi, u1lo, nullptr, nullptr,
        off1, nullptr, nullptr, nullptr, nullptr, 0, 18, 18 * 4096);
    cudaEventRecord(evOff1, s1);

    deform_col_k<<<2048, 256, 0, s1>>>(t1hi, t1lo, scsh1, off1, col1h, col1l);
    gemm_col_k<1><<<gBig, 512, COL_SMEM, s1>>>(
        wahi + 8 * (size_t)PL, walo + 8 * (size_t)PL, col1h, col1l,
        nullptr, u1hi, u1lo, 256, 0);
    gemm_conv_k<32, 256, 0><<<gSmall, 256, SMALL_SMEM, s1>>>(
        wahi + 9 * (size_t)PL, walo + 9 * (size_t)PL, u1hi, u1lo, nullptr, nullptr,
        off2, nullptr, nullptr, nullptr, nullptr, 0, 18, 18 * 4096);
    reppoints_k<<<(OFFN + 255) / 256, 256, 0, s1>>>(off1, off2, out);
    cudaEventRecord(evE1, s1);

    // ---- s2: cls subnet (fused GN) -> classification ----
    gemm_conv_k<128, 512, 2><<<gBig, 512, BIG_SMEM, s2>>>(
        wahi + 3 * (size_t)PL, walo + 3 * (size_t)PL, fhi, flo, nullptr, nullptr,
        nullptr, t2hi, t2lo, nullptr, st2 + 0 * 2048, 0, 256, 0);
    gnfin_k<<<4, 256, 0, s2>>>(st2 + 0 * 2048, cls_g + 0, cls_b + 0, scsh2, pad2h, pad2l);
    wscale_k<<<256, 256, 0, s2>>>(cls_ws + WSZ, scsh2, ws2h, ws2l, bias2);
    gemm_conv_k<128, 512, 2><<<gBig, 512, BIG_SMEM, s2>>>(
        ws2h, ws2l, t2hi, t2lo, pad2h, pad2l,
        nullptr, u2hi, u2lo, bias2, st2 + 1 * 2048, PL, 256, 0);
    gnfin_k<<<4, 256, 0, s2>>>(st2 + 1 * 2048, cls_g + 256, cls_b + 256, scsh2, pad2h, pad2l);
    wscale_k<<<256, 256, 0, s2>>>(cls_ws + 2 * WSZ, scsh2, ws2h, ws2l, bias2);
    gemm_conv_k<128, 512, 2><<<gBig, 512, BIG_SMEM, s2>>>(
        ws2h, ws2l, u2hi, u2lo, pad2h, pad2l,
        nullptr, t2hi, t2lo, bias2, st2 + 2 * 2048, PL, 256, 0);
    gnfin_k<<<4, 256, 0, s2>>>(st2 + 2 * 2048, cls_g + 512, cls_b + 512, scsh2, pad2h, pad2l);

    cudaStreamWaitEvent(s2, evOff1, 0);
    deform_col_k<<<2048, 256, 0, s2>>>(t2hi, t2lo, scsh2, off1, col2h, col2l);
    gemm_col_k<1><<<gBig, 512, COL_SMEM, s2>>>(
        wahi + 10 * (size_t)PL, walo + 10 * (size_t)PL, col2h, col2l,
        nullptr, u2hi, u2lo, 256, 0);
    gemm_conv_k<32, 256, 0><<<gSmall, 256, SMALL_SMEM, s2>>>(
        wahi + 11 * (size_t)PL, walo + 11 * (size_t)PL, u2hi, u2lo, nullptr, nullptr,
        out + 2 * OFFN, nullptr, nullptr, nullptr, nullptr, 0, 15, 15 * 4096);
    cudaEventRecord(evE2, s2);

    cudaStreamWaitEvent(0, evE1, 0);
    cudaStreamWaitEvent(0, evE2, 0);
}

// round 13
// speedup vs baseline: 1.5427x; 1.5427x over previous
#include <cuda_runtime.h>
#include <cuda_bf16.h>
#include <cstdint>
#include <math.h>

#define NG 16384
#define OFFN (18*16384)
#define KDIM 2304
#define WSZ (256*256*9)
#define PL 589824            // 256*2304 per weight tensor
#define COL_SMEM 197632      // deform col GEMM: 2*96KB + pad
#define SPL 25344            // slab plane bytes: 396 pix * 64B
#define BIG_SMEM 135168
#define SMALL_SMEM 110592

// ---------------- scratch (device globals; no allocation) ----------------
__device__ __nv_bfloat16 g_wahi[(size_t)12*PL];
__device__ __nv_bfloat16 g_walo[(size_t)12*PL];
__device__ __nv_bfloat16 g_fhi[(size_t)NG*256];
__device__ __nv_bfloat16 g_flo[(size_t)NG*256];
// stream-1 (loc / offsets) scratch
__device__ __nv_bfloat16 g_t1hi[(size_t)NG*256];
__device__ __nv_bfloat16 g_t1lo[(size_t)NG*256];
__device__ __nv_bfloat16 g_u1hi[(size_t)NG*256];
__device__ __nv_bfloat16 g_u1lo[(size_t)NG*256];
__device__ float g_buf1[(size_t)NG*256];
__device__ float g_nh1[(size_t)NG*256];
__device__ __nv_bfloat16 g_col1h[(size_t)NG*KDIM];
__device__ __nv_bfloat16 g_col1l[(size_t)NG*KDIM];
__device__ float g_st1[3*2048];
// stream-2 (cls) scratch
__device__ __nv_bfloat16 g_t2hi[(size_t)NG*256];
__device__ __nv_bfloat16 g_t2lo[(size_t)NG*256];
__device__ float g_buf2[(size_t)NG*256];
__device__ float g_nh2[(size_t)NG*256];
__device__ __nv_bfloat16 g_col2h[(size_t)NG*KDIM];
__device__ __nv_bfloat16 g_col2l[(size_t)NG*KDIM];
__device__ float g_st2[3*2048];
__device__ float g_off1[OFFN];
__device__ float g_off2[OFFN];

// ---------------- PTX helpers ----------------
__device__ __forceinline__ uint32_t smem_u32(const void* p) {
    uint32_t a;
    asm("{ .reg .u64 t; cvta.to.shared.u64 t, %1; cvt.u32.u64 %0, t; }" : "=r"(a) : "l"(p));
    return a;
}
#define SWZ(o)   ((o) ^ (((o) >> 3) & 0x70))
#define SWZ64(o) ((o) ^ (((o) >> 3) & 0x30))

__device__ __forceinline__ void cp16(uint32_t dst, const void* src, int ss) {
    asm volatile("cp.async.cg.shared.global [%0], [%1], 16, %2;\n" :: "r"(dst), "l"(src), "r"(ss));
}
__device__ __forceinline__ void cp_commit() { asm volatile("cp.async.commit_group;\n" ::: "memory"); }
__device__ __forceinline__ void cp_wait0()  { asm volatile("cp.async.wait_group 0;\n" ::: "memory"); }
__device__ __forceinline__ void cp_wait1()  { asm volatile("cp.async.wait_group 1;\n" ::: "memory"); }

__device__ __forceinline__ void ldm4(uint32_t* r, uint32_t addr) {
    asm volatile("ldmatrix.sync.aligned.m8n8.x4.shared.b16 {%0,%1,%2,%3}, [%4];"
        : "=r"(r[0]), "=r"(r[1]), "=r"(r[2]), "=r"(r[3]) : "r"(addr));
}
__device__ __forceinline__ void mma16816(float* d, const uint32_t* a, const uint32_t* b) {
    asm volatile("mma.sync.aligned.m16n8k16.row.col.f32.bf16.bf16.f32 "
        "{%0,%1,%2,%3}, {%4,%5,%6,%7}, {%8,%9}, {%0,%1,%2,%3};"
        : "+f"(d[0]), "+f"(d[1]), "+f"(d[2]), "+f"(d[3])
        : "r"(a[0]), "r"(a[1]), "r"(a[2]), "r"(a[3]), "r"(b[0]), "r"(b[1]));
}
__device__ __forceinline__ unsigned short bfbits(float x) {
    __nv_bfloat16 h = __float2bfloat16(x);
    return *reinterpret_cast<unsigned short*>(&h);
}

// ---------------- shared epilogues ----------------
template<int IM>
__device__ __forceinline__ void epilogue_nchw(float acc[IM][4][4], float* out, int bstride,
                                              int M, int m0, int n0, int wm, int wn, int lane) {
    int b = n0 >> 12, ij0 = n0 & 4095;
    float* outb = out + (size_t)b * bstride + ij0;
#pragma unroll
    for (int im = 0; im < IM; im++) {
        int mrow = m0 + wm + im * 16 + (lane >> 2);
#pragma unroll
        for (int jn = 0; jn < 4; jn++) {
            int ncol = wn + jn * 8 + (lane & 3) * 2;
            if (mrow < M) {
                float2 v = make_float2(acc[im][jn][0], acc[im][jn][1]);
                *(float2*)(outb + (size_t)mrow * 4096 + ncol) = v;
            }
            if (mrow + 8 < M) {
                float2 v = make_float2(acc[im][jn][2], acc[im][jn][3]);
                *(float2*)(outb + (size_t)(mrow + 8) * 4096 + ncol) = v;
            }
        }
    }
}

// per-channel sum/sumsq accumulation for GN (512-thread CTA, IM=4, MW=2)
__device__ __forceinline__ void epilogue_stats(float acc[4][4][4], float* stat, char* smraw,
                                               int m0, int n0, int tid, int wm, int lane) {
    int b = n0 >> 12;
    float* ssum = (float*)smraw;
    float* ssq = ssum + 128;
    if (tid < 128) { ssum[tid] = 0.f; ssq[tid] = 0.f; }
    __syncthreads();
#pragma unroll
    for (int im = 0; im < 4; im++) {
#pragma unroll
        for (int h2 = 0; h2 < 2; h2++) {
            int rl = wm + im * 16 + (lane >> 2) + h2 * 8;
            float s = 0.f, q = 0.f;
#pragma unroll
            for (int jn = 0; jn < 4; jn++) {
                float v0 = acc[im][jn][h2 * 2], v1 = acc[im][jn][h2 * 2 + 1];
                s += v0 + v1;
                q += v0 * v0 + v1 * v1;
            }
            atomicAdd(&ssum[rl], s);
            atomicAdd(&ssq[rl], q);
        }
    }
    __syncthreads();
    if (tid < 128) {
        atomicAdd(&stat[(b * 256 + m0 + tid) * 2], ssum[tid]);
        atomicAdd(&stat[(b * 256 + m0 + tid) * 2 + 1], ssq[tid]);
    }
}

// 512-thread CTA, 16 warps (wm in {0,64}, wn = (wid&7)*32), IM=4, tile 128m x 256n.
__device__ __forceinline__ void epilogue_split(float acc[4][4][4],
                                               __nv_bfloat16* ohi, __nv_bfloat16* olo,
                                               float* smemf, int m0, int n0,
                                               int tid, int wid, int wm, int wn, int lane) {
    for (int ch = 0; ch < 8; ch++) {
        __syncthreads();
        if ((wid & 7) == ch) {
#pragma unroll
            for (int im = 0; im < 4; im++) {
                int m = wm + im * 16 + (lane >> 2);
#pragma unroll
                for (int jn = 0; jn < 4; jn++) {
                    int nl = jn * 8 + (lane & 3) * 2;
                    smemf[m * 33 + nl] = acc[im][jn][0];
                    smemf[m * 33 + nl + 1] = acc[im][jn][1];
                    smemf[(m + 8) * 33 + nl] = acc[im][jn][2];
                    smemf[(m + 8) * 33 + nl + 1] = acc[im][jn][3];
                }
            }
        }
        __syncthreads();
        int p = tid >> 4;             // 0..31 pixel in chunk
        int cq = (tid & 15) * 8;      // 8 channels
        size_t base = (size_t)(n0 + ch * 32 + p) * 256 + m0 + cq;
        uint32_t hw[4], lw[4];
#pragma unroll
        for (int i = 0; i < 4; i++) {
            float v0 = smemf[(cq + 2 * i) * 33 + p];
            float v1 = smemf[(cq + 2 * i + 1) * 33 + p];
            unsigned short h0 = bfbits(v0), h1 = bfbits(v1);
            float r0 = v0 - __bfloat162float(*reinterpret_cast<__nv_bfloat16*>(&h0));
            float r1 = v1 - __bfloat162float(*reinterpret_cast<__nv_bfloat16*>(&h1));
            hw[i] = (uint32_t)h0 | ((uint32_t)h1 << 16);
            lw[i] = (uint32_t)bfbits(r0) | ((uint32_t)bfbits(r1) << 16);
        }
        *(uint4*)(ohi + base) = make_uint4(hw[0], hw[1], hw[2], hw[3]);
        *(uint4*)(olo + base) = make_uint4(lw[0], lw[1], lw[2], lw[3]);
    }
}

// ---------------- all-weights convert (coalesced, smem-staged) ----------------
struct W12 { const float* p[12]; int m[12]; };
__global__ __launch_bounds__(256) void wconv_all_k(W12 w,
                                                   __nv_bfloat16* __restrict__ hi,
                                                   __nv_bfloat16* __restrict__ lo) {
    __shared__ float rows[4][KDIM];
    int t = blockIdx.x >> 6;          // 12 tensors
    int rb = blockIdx.x & 63;         // 64 blocks of 4 rows
    int tid = threadIdx.x;
    int m0 = rb * 4;
    const float* src = w.p[t];
    int Mv = w.m[t];
    for (int i = tid; i < 4 * KDIM; i += 256) {
        int r = i / KDIM, k = i - r * KDIM;
        int m = m0 + r;
        rows[r][k] = (m < Mv) ? src[(size_t)m * KDIM + k] : 0.f;
    }
    __syncthreads();
    for (int i = tid; i < 4 * KDIM; i += 256) {
        int r = i / KDIM, k = i - r * KDIM;
        int kk = k >> 8, c = k & 255;
        float v = rows[r][c * 9 + kk];
        size_t dst = (size_t)t * PL + (size_t)(m0 + r) * KDIM + k;
        __nv_bfloat16 h = __float2bfloat16(v);
        hi[dst] = h;
        lo[dst] = __float2bfloat16(v - __bfloat162float(h));
    }
}

// ---------------- zero stats ----------------
__global__ __launch_bounds__(256) void zerostat_k(float* a, float* b, int n) {
    int i = blockIdx.x * 256 + threadIdx.x;
    if (i < n) { a[i] = 0.f; b[i] = 0.f; }
}

// ---------------- NCHW fp32 -> (GN affine from raw stats) -> NHWC hi/lo bf16 (+fp32) ----
__global__ void tsplit_k(const float* __restrict__ in,
                         __nv_bfloat16* __restrict__ hi, __nv_bfloat16* __restrict__ lo,
                         float* __restrict__ f32o,
                         const float* __restrict__ stat,
                         const float* __restrict__ gamma, const float* __restrict__ beta) {
    __shared__ float t[32][33];
    int b = blockIdx.z, hw0 = blockIdx.x * 32, c0 = blockIdx.y * 32;
    int tx = threadIdx.x, ty = threadIdx.y;
    const float* ip = in + (size_t)b * 256 * 4096;
    for (int r = ty; r < 32; r += 8)
        t[r][tx] = ip[(size_t)(c0 + r) * 4096 + hw0 + tx];
    __syncthreads();
    int ch = c0 + tx;
    float sc = 1.f, sh = 0.f;
    if (stat) {
        int g = ch >> 3;
        float s = 0.f, q = 0.f;
#pragma unroll
        for (int i = 0; i < 8; i++) {
            s += stat[(b * 256 + g * 8 + i) * 2];
            q += stat[(b * 256 + g * 8 + i) * 2 + 1];
        }
        float mean = s * (1.f / 32768.f);
        float var = q * (1.f / 32768.f) - mean * mean;
        float rstd = rsqrtf(var + 1e-5f);
        sc = rstd * gamma[ch];
        sh = beta[ch] - mean * sc;
    }
    for (int r = ty; r < 32; r += 8) {
        float v = t[tx][r] * sc + sh;
        size_t idx = (size_t)b * 4096 * 256 + (size_t)(hw0 + r) * 256 + ch;
        if (hi) {
            __nv_bfloat16 h = __float2bfloat16(v);
            hi[idx] = h;
            lo[idx] = __float2bfloat16(v - __bfloat162float(h));
        }
        if (f32o) f32o[idx] = v;
    }
}

// ---------------- slab-based implicit-conv GEMM ----------------
// EPI: 0 = NCHW fp32, 1 = split planes, 3 = NCHW fp32 + GN stats
template<int MROWS, int NTHREADS, int EPI>
__global__ __launch_bounds__(NTHREADS, 1) void gemm_conv_k(
    const __nv_bfloat16* __restrict__ Ahi, const __nv_bfloat16* __restrict__ Alo,
    const __nv_bfloat16* __restrict__ Bhi, const __nv_bfloat16* __restrict__ Blo,
    float* __restrict__ out, __nv_bfloat16* __restrict__ ohi, __nv_bfloat16* __restrict__ olo,
    float* __restrict__ stat, int M, int bstride) {
    constexpr int MW = NTHREADS / 256;
    constexpr int IM = MROWS / (MW * 16);
    constexpr int APL = MROWS * 64;
    constexpr int AST = 2 * APL;
    constexpr int SST = 2 * SPL;

    extern __shared__ char smx[];
    uint32_t smb = (smem_u32(smx) + 1023) & ~1023u;
    uint32_t aB = smb, sB = smb + 2 * AST;

    int tid = threadIdx.x;
    int lane = tid & 31;
    int wid = tid >> 5;
    int wm = (wid >> 3) * (IM * 16);
    int wn = (wid & 7) * 32;
    int n0 = blockIdx.x * 256;
    int m0 = blockIdx.y * MROWS;
    int b = n0 >> 12, ij0 = n0 & 4095;
    int i0 = ij0 >> 6;

    auto load_A = [&](int t, uint32_t dst) {
        int cg = t / 9, tap = t - cg * 9;
        int koff = tap * 256 + cg * 32;
#pragma unroll
        for (int idx = tid; idx < MROWS * 8; idx += NTHREADS) {
            int plane = idx >= MROWS * 4;
            int q = idx - plane * (MROWS * 4);
            int row = q >> 2, c16 = q & 3;
            const __nv_bfloat16* src =
                (plane ? Alo : Ahi) + (size_t)(m0 + row) * KDIM + koff + c16 * 8;
            cp16(dst + plane * APL + SWZ64(row * 64 + c16 * 16), src, 16);
        }
    };
    auto load_slab = [&](int cg, uint32_t dst) {
        for (int idx = tid; idx < 3168; idx += NTHREADS) {
            int plane = idx >= 1584;
            int q = idx - plane * 1584;
            int pix = q >> 2, c16 = q & 3;
            int sy = pix / 66, sx = pix - sy * 66;
            int y = i0 - 1 + sy, x = sx - 1;
            bool v = ((unsigned)y < 64u) && ((unsigned)x < 64u);
            int yy = v ? y : 0, xx = v ? x : 0;
            const __nv_bfloat16* src = (plane ? Blo : Bhi) +
                ((((size_t)b * 64 + yy) * 64 + xx) << 8) + cg * 32 + c16 * 8;
            cp16(dst + plane * SPL + SWZ64(pix * 64 + c16 * 16), src, v ? 16 : 0);
        }
    };

    float acc[IM][4][4];
#pragma unroll
    for (int im = 0; im < IM; im++)
#pragma unroll
        for (int jn = 0; jn < 4; jn++)
#pragma unroll
            for (int q = 0; q < 4; q++) acc[im][jn][q] = 0.f;

    int arow = lane & 15;
    int abyte = (lane >> 4) * 16;
    int mi = lane >> 3;
    int brow_off = (mi >> 1) * 8 + (lane & 7);
    int bbyte = (mi & 1) * 16;
    int b66[2];
#pragma unroll
    for (int jp = 0; jp < 2; jp++) {
        int rowb = wn + jp * 16 + brow_off;
        b66[jp] = (rowb >> 6) * 66 + (rowb & 63);
    }

    load_slab(0, sB);
    load_A(0, aB);
    cp_commit();

    for (int t = 0; t < 72; t++) {
        int cg = t / 9, tap = t - cg * 9;
        if (t + 1 < 72) {
            load_A(t + 1, aB + ((t + 1) & 1) * AST);
            if (tap == 4 && cg < 7) load_slab(cg + 1, sB + ((cg + 1) & 1) * SST);
            cp_commit();
            cp_wait1();
        } else {
            cp_wait0();
        }
        __syncthreads();

        uint32_t ab = aB + (t & 1) * AST;
        uint32_t sb = sB + (cg & 1) * SST;
        int kd = (tap * 11) >> 5;
        int tapoff = kd * 66 + (tap - kd * 3);
#pragma unroll
        for (int s = 0; s < 2; s++) {
            uint32_t bh[4][2], bl[4][2];
#pragma unroll
            for (int jp = 0; jp < 2; jp++) {
                int pix = b66[jp] + tapoff;
                uint32_t off = SWZ64(pix * 64 + s * 32 + bbyte);
                uint32_t r4[4];
                ldm4(r4, sb + off);
                bh[jp * 2][0] = r4[0]; bh[jp * 2][1] = r4[1];
                bh[jp * 2 + 1][0] = r4[2]; bh[jp * 2 + 1][1] = r4[3];
                ldm4(r4, sb + SPL + off);
                bl[jp * 2][0] = r4[0]; bl[jp * 2][1] = r4[1];
                bl[jp * 2 + 1][0] = r4[2]; bl[jp * 2 + 1][1] = r4[3];
            }
#pragma unroll
            for (int im = 0; im < IM; im++) {
                int rowa = wm + im * 16 + arow;
                uint32_t offa = SWZ64(rowa * 64 + s * 32 + abyte);
                uint32_t ah[4], al[4];
                ldm4(ah, ab + offa);
                ldm4(al, ab + APL + offa);
#pragma unroll
                for (int jn = 0; jn < 4; jn++) {
                    mma16816(acc[im][jn], ah, bh[jn]);
                    mma16816(acc[im][jn], ah, bl[jn]);
                    mma16816(acc[im][jn], al, bh[jn]);
                }
            }
        }
        __syncthreads();
    }

    if (EPI == 0) {
        epilogue_nchw<IM>(acc, out, bstride, M, m0, n0, wm, wn, lane);
    } else if (EPI == 3) {
        epilogue_nchw<IM>(acc, out, bstride, M, m0, n0, wm, wn, lane);
        epilogue_stats(acc, stat, smx, m0, n0, tid, wm, lane);
    } else {
        epilogue_split(acc, ohi, olo, (float*)smx, m0, n0, tid, wid, wm, wn, lane);
    }
}

// ---------------- col-based GEMM for deform convs ----------------
template<int EPI>
__global__ __launch_bounds__(512, 1) void gemm_col_k(const __nv_bfloat16* __restrict__ Ahi,
                                                     const __nv_bfloat16* __restrict__ Alo,
                                                     const __nv_bfloat16* __restrict__ Bhi,
                                                     const __nv_bfloat16* __restrict__ Blo,
                                                     float* __restrict__ out,
                                                     __nv_bfloat16* __restrict__ ohi,
                                                     __nv_bfloat16* __restrict__ olo,
                                                     int M, int bstride) {
    extern __shared__ char smx[];
    uint32_t smb = (smem_u32(smx) + 1023) & ~1023u;
    int tid = threadIdx.x;
    int lane = tid & 31;
    int wid = tid >> 5;
    int wm = (wid >> 3) * 64;
    int wn = (wid & 7) * 32;
    int n0 = blockIdx.x * 256;
    int m0 = blockIdx.y * 128;

    auto load_stage = [&](int t, uint32_t sb) {
        int kk = t >> 2, cg = t & 3;
        int koff = kk * 256 + cg * 64;
#pragma unroll
        for (int qi = 0; qi < 12; qi++) {
            int q = qi * 512 + tid;
            if (qi < 4) {
                int plane = (q >> 10) & 1;
                int qq = q & 1023;
                int row = qq >> 3, c16 = qq & 7;
                const __nv_bfloat16* src =
                    (plane ? Alo : Ahi) + (size_t)(m0 + row) * KDIM + koff + c16 * 8;
                cp16(sb + plane * 16384 + SWZ(row * 128 + c16 * 16), src, 16);
            } else {
                int qb = q - 2048;
                int plane = qb >> 11;
                int qq = qb & 2047;
                int row = qq >> 3, c16 = qq & 7;
                const __nv_bfloat16* src =
                    (plane ? Blo : Bhi) + (size_t)(n0 + row) * KDIM + koff + c16 * 8;
                cp16(sb + 32768 + plane * 32768 + SWZ(row * 128 + c16 * 16), src, 16);
            }
        }
    };

    float acc[4][4][4];
#pragma unroll
    for (int im = 0; im < 4; im++)
#pragma unroll
        for (int jn = 0; jn < 4; jn++)
#pragma unroll
            for (int q = 0; q < 4; q++) acc[im][jn][q] = 0.f;

    load_stage(0, smb);
    cp_commit();

    int arow_off = (lane & 15);
    int abyte = (lane >> 4) * 16;
    int mi = lane >> 3;
    int brow_off = (mi >> 1) * 8 + (lane & 7);
    int bbyte = (mi & 1) * 16;

    for (int t = 0; t < 36; t++) {
        if (t + 1 < 36) {
            load_stage(t + 1, smb + ((t + 1) & 1) * 98304);
            cp_commit();
            cp_wait1();
        } else {
            cp_wait0();
        }
        __syncthreads();

        uint32_t sb = smb + (t & 1) * 98304;
        uint32_t ahB = sb, alB = sb + 16384, bhB = sb + 32768, blB = sb + 65536;
#pragma unroll
        for (int s = 0; s < 4; s++) {
            uint32_t bh[4][2], bl[4][2];
#pragma unroll
            for (int jp = 0; jp < 2; jp++) {
                int rowb = wn + jp * 16 + brow_off;
                uint32_t off = SWZ(rowb * 128 + s * 32 + bbyte);
                uint32_t r4[4];
                ldm4(r4, bhB + off);
                bh[jp * 2][0] = r4[0]; bh[jp * 2][1] = r4[1];
                bh[jp * 2 + 1][0] = r4[2]; bh[jp * 2 + 1][1] = r4[3];
                ldm4(r4, blB + off);
                bl[jp * 2][0] = r4[0]; bl[jp * 2][1] = r4[1];
                bl[jp * 2 + 1][0] = r4[2]; bl[jp * 2 + 1][1] = r4[3];
            }
#pragma unroll
            for (int im = 0; im < 4; im++) {
                int rowa = wm + im * 16 + arow_off;
                uint32_t off = SWZ(rowa * 128 + s * 32 + abyte);
                uint32_t ah[4], al[4];
                ldm4(ah, ahB + off);
                ldm4(al, alB + off);
#pragma unroll
                for (int jn = 0; jn < 4; jn++) {
                    mma16816(acc[im][jn], ah, bh[jn]);
                    mma16816(acc[im][jn], ah, bl[jn]);
                    mma16816(acc[im][jn], al, bh[jn]);
                }
            }
        }
        __syncthreads();
    }

    if (EPI == 0) {
        epilogue_nchw<4>(acc, out, bstride, M, m0, n0, wm, wn, lane);
    } else {
        epilogue_split(acc, ohi, olo, (float*)smx, m0, n0, tid, wid, wm, wn, lane);
    }
}

// ---------------- deformable bilinear gather -> bf16 hi/lo col planes ----------------
__global__ __launch_bounds__(256) void deform_col_k(const float* __restrict__ nhwc,
                                                    const float* __restrict__ off,
                                                    __nv_bfloat16* __restrict__ colh,
                                                    __nv_bfloat16* __restrict__ coll) {
    int warp = (blockIdx.x * 256 + threadIdx.x) >> 5;
    int lane = threadIdx.x & 31;
    if (warp >= NG) return;
    int n = warp;
    int b = n >> 12, ij = n & 4095, i = ij >> 6, j = ij & 63;
    const float* offb = off + (size_t)b * 18 * 4096 + ij;
#pragma unroll
    for (int k = 0; k < 9; k++) {
        float dy = offb[(size_t)(2 * k) << 12];
        float dx = offb[(size_t)(2 * k + 1) << 12];
        float y = dy + (float)(i - 1 + k / 3);
        float x = dx + (float)(j - 1 + k % 3);
        float y0f = floorf(y), x0f = floorf(x);
        int y0 = (int)y0f, x0 = (int)x0f;
        float wy = y - y0f, wx = x - x0f;
        bool vy0 = (unsigned)y0 < 64u;
        bool vy1 = (unsigned)(y0 + 1) < 64u;
        bool vx0 = (unsigned)x0 < 64u;
        bool vx1 = (unsigned)(x0 + 1) < 64u;
        float w00 = (vy0 && vx0) ? (1.f - wy) * (1.f - wx) : 0.f;
        float w01 = (vy0 && vx1) ? (1.f - wy) * wx : 0.f;
        float w10 = (vy1 && vx0) ? wy * (1.f - wx) : 0.f;
        float w11 = (vy1 && vx1) ? wy * wx : 0.f;
        int cy0 = min(max(y0, 0), 63), cy1 = min(max(y0 + 1, 0), 63);
        int cx0 = min(max(x0, 0), 63), cx1 = min(max(x0 + 1, 0), 63);
        const float* p00 = nhwc + (((size_t)b * 64 + cy0) * 64 + cx0) * 256;
        const float* p01 = nhwc + (((size_t)b * 64 + cy0) * 64 + cx1) * 256;
        const float* p10 = nhwc + (((size_t)b * 64 + cy1) * 64 + cx0) * 256;
        const float* p11 = nhwc + (((size_t)b * 64 + cy1) * 64 + cx1) * 256;
        __nv_bfloat16* ch = colh + (size_t)n * KDIM + k * 256;
        __nv_bfloat16* cl = coll + (size_t)n * KDIM + k * 256;
#pragma unroll
        for (int it = 0; it < 8; it++) {
            int c = lane + it * 32;
            float v = w00 * p00[c] + w01 * p01[c] + w10 * p10[c] + w11 * p11[c];
            __nv_bfloat16 h = __float2bfloat16(v);
            ch[c] = h;
            cl[c] = __float2bfloat16(v - __bfloat162float(h));
        }
    }
}

// ---------------- rep-points epilogue ----------------
__global__ __launch_bounds__(256) void reppoints_k(const float* __restrict__ off1,
                                                   const float* __restrict__ off2,
                                                   float* __restrict__ out) {
    int idx = blockIdx.x * 256 + threadIdx.x;
    if (idx >= OFFN) return;
    int rem = idx % 73728;
    int ch = rem >> 12;
    int ij = rem & 4095;
    int i = ij >> 6, j = ij & 63;
    int k = ch >> 1;
    float init = (ch & 1) ? (float)(j + (k % 3) - 1) : (float)(i + (k / 3) - 1);
    float r1 = init + off1[idx];
    out[idx] = r1;
    out[OFFN + idx] = r1 + off2[idx];
}

// ---------------- host orchestration (2-stream overlap) ----------------
extern "C" void kernel_launch(void* const* d_in, const int* in_sizes, int n_in,
                              void* d_out, int out_size) {
    const float* feature = (const float*)d_in[0];
    const float* loc_ws  = (const float*)d_in[1];
    const float* loc_g   = (const float*)d_in[2];
    const float* loc_b   = (const float*)d_in[3];
    const float* cls_ws  = (const float*)d_in[4];
    const float* cls_g   = (const float*)d_in[5];
    const float* cls_b   = (const float*)d_in[6];
    const float* pi_w    = (const float*)d_in[7];
    const float* pio_w   = (const float*)d_in[8];
    const float* prd_w   = (const float*)d_in[9];
    const float* pro_w   = (const float*)d_in[10];
    const float* cd_w    = (const float*)d_in[11];
    const float* co_w    = (const float*)d_in[12];
    float* out = (float*)d_out;

    static int init_done = 0;
    static cudaStream_t s1, s2;
    static cudaEvent_t evRoot, evW, evF, evOff1, evE1, evE2;
    if (!init_done) {
        cudaFuncSetAttribute(gemm_conv_k<128, 512, 0>, cudaFuncAttributeMaxDynamicSharedMemorySize, BIG_SMEM);
        cudaFuncSetAttribute(gemm_conv_k<128, 512, 1>, cudaFuncAttributeMaxDynamicSharedMemorySize, BIG_SMEM);
        cudaFuncSetAttribute(gemm_conv_k<128, 512, 3>, cudaFuncAttributeMaxDynamicSharedMemorySize, BIG_SMEM);
        cudaFuncSetAttribute(gemm_conv_k<32, 256, 0>, cudaFuncAttributeMaxDynamicSharedMemorySize, SMALL_SMEM);
        cudaFuncSetAttribute(gemm_col_k<0>, cudaFuncAttributeMaxDynamicSharedMemorySize, COL_SMEM);
        cudaFuncSetAttribute(gemm_col_k<1>, cudaFuncAttributeMaxDynamicSharedMemorySize, COL_SMEM);
        cudaStreamCreateWithFlags(&s1, cudaStreamNonBlocking);
        cudaStreamCreateWithFlags(&s2, cudaStreamNonBlocking);
        cudaEventCreateWithFlags(&evRoot, cudaEventDisableTiming);
        cudaEventCreateWithFlags(&evW, cudaEventDisableTiming);
        cudaEventCreateWithFlags(&evF, cudaEventDisableTiming);
        cudaEventCreateWithFlags(&evOff1, cudaEventDisableTiming);
        cudaEventCreateWithFlags(&evE1, cudaEventDisableTiming);
        cudaEventCreateWithFlags(&evE2, cudaEventDisableTiming);
        init_done = 1;
    }

    __nv_bfloat16 *wahi, *walo, *fhi, *flo;
    __nv_bfloat16 *t1hi, *t1lo, *u1hi, *u1lo, *col1h, *col1l, *t2hi, *t2lo, *col2h, *col2l;
    float *buf1, *buf2, *nh1, *nh2, *off1, *off2, *st1, *st2;
    cudaGetSymbolAddress((void**)&wahi,  g_wahi);
    cudaGetSymbolAddress((void**)&walo,  g_walo);
    cudaGetSymbolAddress((void**)&fhi,   g_fhi);
    cudaGetSymbolAddress((void**)&flo,   g_flo);
    cudaGetSymbolAddress((void**)&t1hi,  g_t1hi);
    cudaGetSymbolAddress((void**)&t1lo,  g_t1lo);
    cudaGetSymbolAddress((void**)&u1hi,  g_u1hi);
    cudaGetSymbolAddress((void**)&u1lo,  g_u1lo);
    cudaGetSymbolAddress((void**)&col1h, g_col1h);
    cudaGetSymbolAddress((void**)&col1l, g_col1l);
    cudaGetSymbolAddress((void**)&t2hi,  g_t2hi);
    cudaGetSymbolAddress((void**)&t2lo,  g_t2lo);
    cudaGetSymbolAddress((void**)&col2h, g_col2h);
    cudaGetSymbolAddress((void**)&col2l, g_col2l);
    cudaGetSymbolAddress((void**)&buf1,  g_buf1);
    cudaGetSymbolAddress((void**)&buf2,  g_buf2);
    cudaGetSymbolAddress((void**)&nh1,   g_nh1);
    cudaGetSymbolAddress((void**)&nh2,   g_nh2);
    cudaGetSymbolAddress((void**)&off1,  g_off1);
    cudaGetSymbolAddress((void**)&off2,  g_off2);
    cudaGetSymbolAddress((void**)&st1,   g_st1);
    cudaGetSymbolAddress((void**)&st2,   g_st2);

    W12 w12;
    w12.p[0] = loc_ws;           w12.m[0] = 256;
    w12.p[1] = loc_ws + WSZ;     w12.m[1] = 256;
    w12.p[2] = loc_ws + 2 * WSZ; w12.m[2] = 256;
    w12.p[3] = cls_ws;           w12.m[3] = 256;
    w12.p[4] = cls_ws + WSZ;     w12.m[4] = 256;
    w12.p[5] = cls_ws + 2 * WSZ; w12.m[5] = 256;
    w12.p[6] = pi_w;             w12.m[6] = 256;
    w12.p[7] = pio_w;            w12.m[7] = 18;
    w12.p[8] = prd_w;            w12.m[8] = 256;
    w12.p[9] = pro_w;            w12.m[9] = 18;
    w12.p[10] = cd_w;            w12.m[10] = 256;
    w12.p[11] = co_w;            w12.m[11] = 15;

    dim3 tgrid(128, 8, 4), tblk(32, 8);
    dim3 gBig(64, 2), gSmall(64, 1);

    // fork from the capturing (default) stream
    cudaEventRecord(evRoot, 0);
    cudaStreamWaitEvent(s1, evRoot, 0);
    cudaStreamWaitEvent(s2, evRoot, 0);

    zerostat_k<<<24, 256, 0, s1>>>(st1, st2, 3 * 2048);
    wconv_all_k<<<768, 256, 0, s1>>>(w12, wahi, walo);
    cudaEventRecord(evW, s1);
    tsplit_k<<<tgrid, tblk, 0, s2>>>(feature, fhi, flo, nullptr, nullptr, nullptr, nullptr);
    cudaEventRecord(evF, s2);
    cudaStreamWaitEvent(s1, evF, 0);
    cudaStreamWaitEvent(s2, evW, 0);

    // ---- s1: loc subnet -> offset1 -> offset2 branch -> reppoints ----
    for (int l = 0; l < 3; l++) {
        gemm_conv_k<128, 512, 3><<<gBig, 512, BIG_SMEM, s1>>>(
            wahi + (size_t)l * PL, walo + (size_t)l * PL,
            l == 0 ? fhi : t1hi, l == 0 ? flo : t1lo, buf1, nullptr, nullptr,
            st1 + l * 2048, 256, 256 * 4096);
        tsplit_k<<<tgrid, tblk, 0, s1>>>(buf1, t1hi, t1lo, l == 2 ? nh1 : nullptr,
                                         st1 + l * 2048, loc_g + l * 256, loc_b + l * 256);
    }
    // pi: split-epilogue -> u1 planes (no tsplit)
    gemm_conv_k<128, 512, 1><<<gBig, 512, BIG_SMEM, s1>>>(
        wahi + 6 * (size_t)PL, walo + 6 * (size_t)PL, t1hi, t1lo,
        nullptr, u1hi, u1lo, nullptr, 256, 0);
    gemm_conv_k<32, 256, 0><<<gSmall, 256, SMALL_SMEM, s1>>>(
        wahi + 7 * (size_t)PL, walo + 7 * (size_t)PL, u1hi, u1lo,
        off1, nullptr, nullptr, nullptr, 18, 18 * 4096);
    cudaEventRecord(evOff1, s1);

    deform_col_k<<<2048, 256, 0, s1>>>(nh1, off1, col1h, col1l);
    gemm_col_k<1><<<gBig, 512, COL_SMEM, s1>>>(
        wahi + 8 * (size_t)PL, walo + 8 * (size_t)PL, col1h, col1l,
        nullptr, t1hi, t1lo, 256, 0);
    gemm_conv_k<32, 256, 0><<<gSmall, 256, SMALL_SMEM, s1>>>(
        wahi + 9 * (size_t)PL, walo + 9 * (size_t)PL, t1hi, t1lo,
        off2, nullptr, nullptr, nullptr, 18, 18 * 4096);
    reppoints_k<<<(OFFN + 255) / 256, 256, 0, s1>>>(off1, off2, out);
    cudaEventRecord(evE1, s1);

    // ---- s2: cls subnet -> classification branch ----
    for (int l = 0; l < 3; l++) {
        gemm_conv_k<128, 512, 3><<<gBig, 512, BIG_SMEM, s2>>>(
            wahi + (size_t)(3 + l) * PL, walo + (size_t)(3 + l) * PL,
            l == 0 ? fhi : t2hi, l == 0 ? flo : t2lo, buf2, nullptr, nullptr,
            st2 + l * 2048, 256, 256 * 4096);
        tsplit_k<<<tgrid, tblk, 0, s2>>>(buf2, l == 2 ? nullptr : t2hi, l == 2 ? nullptr : t2lo,
                                         l == 2 ? nh2 : nullptr,
                                         st2 + l * 2048, cls_g + l * 256, cls_b + l * 256);
    }
    cudaStreamWaitEvent(s2, evOff1, 0);
    deform_col_k<<<2048, 256, 0, s2>>>(nh2, off1, col2h, col2l);
    gemm_col_k<1><<<gBig, 512, COL_SMEM, s2>>>(
        wahi + 10 * (size_t)PL, walo + 10 * (size_t)PL, col2h, col2l,
        nullptr, t2hi, t2lo, 256, 0);
    gemm_conv_k<32, 256, 0><<<gSmall, 256, SMALL_SMEM, s2>>>(
        wahi + 11 * (size_t)PL, walo + 11 * (size_t)PL, t2hi, t2lo,
        out + 2 * OFFN, nullptr, nullptr, nullptr, 15, 15 * 4096);
    cudaEventRecord(evE2, s2);

    // join back into the capturing stream
    cudaStreamWaitEvent(0, evE1, 0);
    cudaStreamWaitEvent(0, evE2, 0);
}

// round 14
// speedup vs baseline: 1.5553x; 1.0081x over previous
#include <cuda_runtime.h>
#include <cuda_bf16.h>
#include <cstdint>
#include <math.h>

#define NG 16384
#define OFFN (18*16384)
#define KDIM 2304
#define WSZ (256*256*9)
#define PL 589824
#define COL_SMEM 197632
#define SPL 25344            // slab plane bytes: 396 pix * 64B (198 wide rows * 128B)
#define BIG_SMEM 135168
#define SMALL_SMEM 110592

// ---------------- scratch ----------------
__device__ __nv_bfloat16 g_wahi[(size_t)12*PL];
__device__ __nv_bfloat16 g_walo[(size_t)12*PL];
__device__ __nv_bfloat16 g_fhi[(size_t)NG*256];
__device__ __nv_bfloat16 g_flo[(size_t)NG*256];
__device__ __nv_bfloat16 g_t1hi[(size_t)NG*256];
__device__ __nv_bfloat16 g_t1lo[(size_t)NG*256];
__device__ __nv_bfloat16 g_u1hi[(size_t)NG*256];
__device__ __nv_bfloat16 g_u1lo[(size_t)NG*256];
__device__ float g_buf1[(size_t)NG*256];
__device__ float g_nh1[(size_t)NG*256];
__device__ __nv_bfloat16 g_col1h[(size_t)NG*KDIM];
__device__ __nv_bfloat16 g_col1l[(size_t)NG*KDIM];
__device__ float g_ws1[256];
__device__ __nv_bfloat16 g_t2hi[(size_t)NG*256];
__device__ __nv_bfloat16 g_t2lo[(size_t)NG*256];
__device__ float g_buf2[(size_t)NG*256];
__device__ float g_nh2[(size_t)NG*256];
__device__ __nv_bfloat16 g_col2h[(size_t)NG*KDIM];
__device__ __nv_bfloat16 g_col2l[(size_t)NG*KDIM];
__device__ float g_ws2[256];
__device__ float g_off1[OFFN];
__device__ float g_off2[OFFN];

// ---------------- PTX helpers ----------------
__device__ __forceinline__ uint32_t smem_u32(const void* p) {
    uint32_t a;
    asm("{ .reg .u64 t; cvta.to.shared.u64 t, %1; cvt.u32.u64 %0, t; }" : "=r"(a) : "l"(p));
    return a;
}
#define SWZ(o)   ((o) ^ (((o) >> 3) & 0x70))
// paired-row layout: two 64B rows share one 128B swizzle row (conflict-free ldmatrix)
#define PR_OFF(row, inner) SWZ((((row) >> 1) * 128 + ((row) & 1) * 64 + (inner)))

__device__ __forceinline__ void cp16(uint32_t dst, const void* src, int ss) {
    asm volatile("cp.async.cg.shared.global [%0], [%1], 16, %2;\n" :: "r"(dst), "l"(src), "r"(ss));
}
__device__ __forceinline__ void cp_commit() { asm volatile("cp.async.commit_group;\n" ::: "memory"); }
__device__ __forceinline__ void cp_wait0()  { asm volatile("cp.async.wait_group 0;\n" ::: "memory"); }
__device__ __forceinline__ void cp_wait1()  { asm volatile("cp.async.wait_group 1;\n" ::: "memory"); }

__device__ __forceinline__ void ldm4(uint32_t* r, uint32_t addr) {
    asm volatile("ldmatrix.sync.aligned.m8n8.x4.shared.b16 {%0,%1,%2,%3}, [%4];"
        : "=r"(r[0]), "=r"(r[1]), "=r"(r[2]), "=r"(r[3]) : "r"(addr));
}
__device__ __forceinline__ void mma16816(float* d, const uint32_t* a, const uint32_t* b) {
    asm volatile("mma.sync.aligned.m16n8k16.row.col.f32.bf16.bf16.f32 "
        "{%0,%1,%2,%3}, {%4,%5,%6,%7}, {%8,%9}, {%0,%1,%2,%3};"
        : "+f"(d[0]), "+f"(d[1]), "+f"(d[2]), "+f"(d[3])
        : "r"(a[0]), "r"(a[1]), "r"(a[2]), "r"(a[3]), "r"(b[0]), "r"(b[1]));
}
__device__ __forceinline__ unsigned short bfbits(float x) {
    __nv_bfloat16 h = __float2bfloat16(x);
    return *reinterpret_cast<unsigned short*>(&h);
}

// ---------------- epilogues ----------------
template<int IM>
__device__ __forceinline__ void epilogue_nchw(float acc[IM][4][4], float* out, int bstride,
                                              int M, int m0, int n0, int wm, int wn, int lane) {
    int b = n0 >> 12, ij0 = n0 & 4095;
    float* outb = out + (size_t)b * bstride + ij0;
#pragma unroll
    for (int im = 0; im < IM; im++) {
        int mrow = m0 + wm + im * 16 + (lane >> 2);
#pragma unroll
        for (int jn = 0; jn < 4; jn++) {
            int ncol = wn + jn * 8 + (lane & 3) * 2;
            if (mrow < M) {
                float2 v = make_float2(acc[im][jn][0], acc[im][jn][1]);
                *(float2*)(outb + (size_t)mrow * 4096 + ncol) = v;
            }
            if (mrow + 8 < M) {
                float2 v = make_float2(acc[im][jn][2], acc[im][jn][3]);
                *(float2*)(outb + (size_t)(mrow + 8) * 4096 + ncol) = v;
            }
        }
    }
}

// 512-thread CTA, 16 warps, IM=4, tile 128m x 256n -> NHWC hi/lo planes.
__device__ __forceinline__ void epilogue_split(float acc[4][4][4],
                                               __nv_bfloat16* ohi, __nv_bfloat16* olo,
                                               float* smemf, int m0, int n0,
                                               int tid, int wid, int wm, int wn, int lane) {
    for (int ch = 0; ch < 8; ch++) {
        __syncthreads();
        if ((wid & 7) == ch) {
#pragma unroll
            for (int im = 0; im < 4; im++) {
                int m = wm + im * 16 + (lane >> 2);
#pragma unroll
                for (int jn = 0; jn < 4; jn++) {
                    int nl = jn * 8 + (lane & 3) * 2;
                    smemf[m * 33 + nl] = acc[im][jn][0];
                    smemf[m * 33 + nl + 1] = acc[im][jn][1];
                    smemf[(m + 8) * 33 + nl] = acc[im][jn][2];
                    smemf[(m + 8) * 33 + nl + 1] = acc[im][jn][3];
                }
            }
        }
        __syncthreads();
        int p = tid >> 4;
        int cq = (tid & 15) * 8;
        size_t base = (size_t)(n0 + ch * 32 + p) * 256 + m0 + cq;
        uint32_t hw[4], lw[4];
#pragma unroll
        for (int i = 0; i < 4; i++) {
            float v0 = smemf[(cq + 2 * i) * 33 + p];
            float v1 = smemf[(cq + 2 * i + 1) * 33 + p];
            unsigned short h0 = bfbits(v0), h1 = bfbits(v1);
            float r0 = v0 - __bfloat162float(*reinterpret_cast<__nv_bfloat16*>(&h0));
            float r1 = v1 - __bfloat162float(*reinterpret_cast<__nv_bfloat16*>(&h1));
            hw[i] = (uint32_t)h0 | ((uint32_t)h1 << 16);
            lw[i] = (uint32_t)bfbits(r0) | ((uint32_t)bfbits(r1) << 16);
        }
        *(uint4*)(ohi + base) = make_uint4(hw[0], hw[1], hw[2], hw[3]);
        *(uint4*)(olo + base) = make_uint4(lw[0], lw[1], lw[2], lw[3]);
    }
}

// ---------------- all-weights convert ----------------
struct W12 { const float* p[12]; int m[12]; };
__global__ __launch_bounds__(256) void wconv_all_k(W12 w,
                                                   __nv_bfloat16* __restrict__ hi,
                                                   __nv_bfloat16* __restrict__ lo) {
    __shared__ float rows[4][KDIM];
    int t = blockIdx.x >> 6;
    int rb = blockIdx.x & 63;
    int tid = threadIdx.x;
    int m0 = rb * 4;
    const float* src = w.p[t];
    int Mv = w.m[t];
    for (int i = tid; i < 4 * KDIM; i += 256) {
        int r = i / KDIM, k = i - r * KDIM;
        int m = m0 + r;
        rows[r][k] = (m < Mv) ? src[(size_t)m * KDIM + k] : 0.f;
    }
    __syncthreads();
    for (int i = tid; i < 4 * KDIM; i += 256) {
        int r = i / KDIM, k = i - r * KDIM;
        int kk = k >> 8, c = k & 255;
        float v = rows[r][c * 9 + kk];
        size_t dst = (size_t)t * PL + (size_t)(m0 + r) * KDIM + k;
        __nv_bfloat16 h = __float2bfloat16(v);
        hi[dst] = h;
        lo[dst] = __float2bfloat16(v - __bfloat162float(h));
    }
}

// ---------------- GN stats ----------------
__global__ __launch_bounds__(256) void gnstat_k(const float* __restrict__ in,
                                                float* __restrict__ ws) {
    int bg = blockIdx.x;
    int b = bg >> 5, g = bg & 31;
    int tid = threadIdx.x;
    const float4* p = (const float4*)(in + ((size_t)b * 256 + g * 8) * 4096);
    float s = 0.f, s2 = 0.f;
    for (int i = tid; i < 8192; i += 256) {
        float4 v = p[i];
        s += v.x + v.y + v.z + v.w;
        s2 += v.x * v.x + v.y * v.y + v.z * v.z + v.w * v.w;
    }
    __shared__ float sA[256], sB[256];
    sA[tid] = s; sB[tid] = s2;
    __syncthreads();
    for (int st = 128; st > 0; st >>= 1) {
        if (tid < st) { sA[tid] += sA[tid + st]; sB[tid] += sB[tid + st]; }
        __syncthreads();
    }
    if (tid == 0) {
        float mean = sA[0] * (1.f / 32768.f);
        float var = sB[0] * (1.f / 32768.f) - mean * mean;
        ws[bg * 2] = mean;
        ws[bg * 2 + 1] = rsqrtf(var + 1e-5f);
    }
}

// ---------------- NCHW fp32 -> (GN affine) -> NHWC hi/lo bf16 (+fp32) ----------------
__global__ void tsplit_k(const float* __restrict__ in,
                         __nv_bfloat16* __restrict__ hi, __nv_bfloat16* __restrict__ lo,
                         float* __restrict__ f32o,
                         const float* __restrict__ ws,
                         const float* __restrict__ gamma, const float* __restrict__ beta) {
    __shared__ float t[32][33];
    int b = blockIdx.z, hw0 = blockIdx.x * 32, c0 = blockIdx.y * 32;
    int tx = threadIdx.x, ty = threadIdx.y;
    const float* ip = in + (size_t)b * 256 * 4096;
    for (int r = ty; r < 32; r += 8)
        t[r][tx] = ip[(size_t)(c0 + r) * 4096 + hw0 + tx];
    __syncthreads();
    int ch = c0 + tx;
    float sc = 1.f, sh = 0.f;
    if (ws) {
        int bg = b * 32 + (ch >> 3);
        float mean = ws[bg * 2], rstd = ws[bg * 2 + 1];
        sc = rstd * gamma[ch];
        sh = beta[ch] - mean * sc;
    }
    for (int r = ty; r < 32; r += 8) {
        float v = t[tx][r] * sc + sh;
        size_t idx = (size_t)b * 4096 * 256 + (size_t)(hw0 + r) * 256 + ch;
        if (hi) {
            __nv_bfloat16 h = __float2bfloat16(v);
            hi[idx] = h;
            lo[idx] = __float2bfloat16(v - __bfloat162float(h));
        }
        if (f32o) f32o[idx] = v;
    }
}

// ---------------- slab-based implicit-conv GEMM (paired-row SWZ128) ----------------
template<int MROWS, int NTHREADS, int EPI>
__global__ __launch_bounds__(NTHREADS, 1) void gemm_conv_k(
    const __nv_bfloat16* __restrict__ Ahi, const __nv_bfloat16* __restrict__ Alo,
    const __nv_bfloat16* __restrict__ Bhi, const __nv_bfloat16* __restrict__ Blo,
    float* __restrict__ out, __nv_bfloat16* __restrict__ ohi, __nv_bfloat16* __restrict__ olo,
    int M, int bstride) {
    constexpr int MW = NTHREADS / 256;
    constexpr int IM = MROWS / (MW * 16);
    constexpr int APL = MROWS * 64;
    constexpr int AST = 2 * APL;
    constexpr int SST = 2 * SPL;

    extern __shared__ char smx[];
    uint32_t smb = (smem_u32(smx) + 1023) & ~1023u;
    uint32_t aB = smb, sB = smb + 2 * AST;

    int tid = threadIdx.x;
    int lane = tid & 31;
    int wid = tid >> 5;
    int wm = (wid >> 3) * (IM * 16);
    int wn = (wid & 7) * 32;
    int n0 = blockIdx.x * 256;
    int m0 = blockIdx.y * MROWS;
    int b = n0 >> 12, ij0 = n0 & 4095;
    int i0 = ij0 >> 6;

    auto load_A = [&](int t, uint32_t dst) {
        int cg = t / 9, tap = t - cg * 9;
        int koff = tap * 256 + cg * 32;
#pragma unroll
        for (int idx = tid; idx < MROWS * 8; idx += NTHREADS) {
            int plane = idx >= MROWS * 4;
            int q = idx - plane * (MROWS * 4);
            int row = q >> 2, c16 = q & 3;
            const __nv_bfloat16* src =
                (plane ? Alo : Ahi) + (size_t)(m0 + row) * KDIM + koff + c16 * 8;
            cp16(dst + plane * APL + PR_OFF(row, c16 * 16), src, 16);
        }
    };
    // slab: 396 pixels * 4 chunks = 1584 chunks per plane, 3168 total
    auto load_slab = [&](int cg, uint32_t dst) {
        for (int idx = tid; idx < 3168; idx += NTHREADS) {
            int plane = idx >= 1584;
            int q = idx - plane * 1584;
            int pix = q >> 2, c16 = q & 3;
            int sy = pix / 66, sx = pix - sy * 66;
            int y = i0 - 1 + sy, x = sx - 1;
            bool v = ((unsigned)y < 64u) && ((unsigned)x < 64u);
            int yy = v ? y : 0, xx = v ? x : 0;
            const __nv_bfloat16* src = (plane ? Blo : Bhi) +
                ((((size_t)b * 64 + yy) * 64 + xx) << 8) + cg * 32 + c16 * 8;
            cp16(dst + plane * SPL + PR_OFF(pix, c16 * 16), src, v ? 16 : 0);
        }
    };

    float acc[IM][4][4];
#pragma unroll
    for (int im = 0; im < IM; im++)
#pragma unroll
        for (int jn = 0; jn < 4; jn++)
#pragma unroll
            for (int q = 0; q < 4; q++) acc[im][jn][q] = 0.f;

    int arow = lane & 15;
    int abyte = (lane >> 4) * 16;
    int mi = lane >> 3;
    int brow_off = (mi >> 1) * 8 + (lane & 7);
    int bbyte = (mi & 1) * 16;
    int b66[2];
#pragma unroll
    for (int jp = 0; jp < 2; jp++) {
        int rowb = wn + jp * 16 + brow_off;
        b66[jp] = (rowb >> 6) * 66 + (rowb & 63);
    }

    load_slab(0, sB);
    load_A(0, aB);
    cp_commit();

    for (int t = 0; t < 72; t++) {
        int cg = t / 9, tap = t - cg * 9;
        if (t + 1 < 72) {
            load_A(t + 1, aB + ((t + 1) & 1) * AST);
            if (tap == 4 && cg < 7) load_slab(cg + 1, sB + ((cg + 1) & 1) * SST);
            cp_commit();
            cp_wait1();
        } else {
            cp_wait0();
        }
        __syncthreads();

        uint32_t ab = aB + (t & 1) * AST;
        uint32_t sb = sB + (cg & 1) * SST;
        int kd = (tap * 11) >> 5;
        int tapoff = kd * 66 + (tap - kd * 3);
#pragma unroll
        for (int s = 0; s < 2; s++) {
            uint32_t bh[4][2], bl[4][2];
#pragma unroll
            for (int jp = 0; jp < 2; jp++) {
                int pix = b66[jp] + tapoff;
                uint32_t off = PR_OFF(pix, s * 32 + bbyte);
                uint32_t r4[4];
                ldm4(r4, sb + off);
                bh[jp * 2][0] = r4[0]; bh[jp * 2][1] = r4[1];
                bh[jp * 2 + 1][0] = r4[2]; bh[jp * 2 + 1][1] = r4[3];
                ldm4(r4, sb + SPL + off);
                bl[jp * 2][0] = r4[0]; bl[jp * 2][1] = r4[1];
                bl[jp * 2 + 1][0] = r4[2]; bl[jp * 2 + 1][1] = r4[3];
            }
#pragma unroll
            for (int im = 0; im < IM; im++) {
                int rowa = wm + im * 16 + arow;
                uint32_t offa = PR_OFF(rowa, s * 32 + abyte);
                uint32_t ah[4], al[4];
                ldm4(ah, ab + offa);
                ldm4(al, ab + APL + offa);
#pragma unroll
                for (int jn = 0; jn < 4; jn++) {
                    mma16816(acc[im][jn], ah, bh[jn]);
                    mma16816(acc[im][jn], ah, bl[jn]);
                    mma16816(acc[im][jn], al, bh[jn]);
                }
            }
        }
        __syncthreads();
    }

    if (EPI == 0) {
        epilogue_nchw<IM>(acc, out, bstride, M, m0, n0, wm, wn, lane);
    } else {
        epilogue_split(acc, ohi, olo, (float*)smx, m0, n0, tid, wid, wm, wn, lane);
    }
}

// ---------------- col-based GEMM for deform convs (128B rows, already conflict-free) ----
template<int EPI>
__global__ __launch_bounds__(512, 1) void gemm_col_k(const __nv_bfloat16* __restrict__ Ahi,
                                                     const __nv_bfloat16* __restrict__ Alo,
                                                     const __nv_bfloat16* __restrict__ Bhi,
                                                     const __nv_bfloat16* __restrict__ Blo,
                                                     float* __restrict__ out,
                                                     __nv_bfloat16* __restrict__ ohi,
                                                     __nv_bfloat16* __restrict__ olo,
                                                     int M, int bstride) {
    extern __shared__ char smx[];
    uint32_t smb = (smem_u32(smx) + 1023) & ~1023u;
    int tid = threadIdx.x;
    int lane = tid & 31;
    int wid = tid >> 5;
    int wm = (wid >> 3) * 64;
    int wn = (wid & 7) * 32;
    int n0 = blockIdx.x * 256;
    int m0 = blockIdx.y * 128;

    auto load_stage = [&](int t, uint32_t sb) {
        int kk = t >> 2, cg = t & 3;
        int koff = kk * 256 + cg * 64;
#pragma unroll
        for (int qi = 0; qi < 12; qi++) {
            int q = qi * 512 + tid;
            if (qi < 4) {
                int plane = (q >> 10) & 1;
                int qq = q & 1023;
                int row = qq >> 3, c16 = qq & 7;
                const __nv_bfloat16* src =
                    (plane ? Alo : Ahi) + (size_t)(m0 + row) * KDIM + koff + c16 * 8;
                cp16(sb + plane * 16384 + SWZ(row * 128 + c16 * 16), src, 16);
            } else {
                int qb = q - 2048;
                int plane = qb >> 11;
                int qq = qb & 2047;
                int row = qq >> 3, c16 = qq & 7;
                const __nv_bfloat16* src =
                    (plane ? Blo : Bhi) + (size_t)(n0 + row) * KDIM + koff + c16 * 8;
                cp16(sb + 32768 + plane * 32768 + SWZ(row * 128 + c16 * 16), src, 16);
            }
        }
    };

    float acc[4][4][4];
#pragma unroll
    for (int im = 0; im < 4; im++)
#pragma unroll
        for (int jn = 0; jn < 4; jn++)
#pragma unroll
            for (int q = 0; q < 4; q++) acc[im][jn][q] = 0.f;

    load_stage(0, smb);
    cp_commit();

    int arow_off = (lane & 15);
    int abyte = (lane >> 4) * 16;
    int mi = lane >> 3;
    int brow_off = (mi >> 1) * 8 + (lane & 7);
    int bbyte = (mi & 1) * 16;

    for (int t = 0; t < 36; t++) {
        if (t + 1 < 36) {
            load_stage(t + 1, smb + ((t + 1) & 1) * 98304);
            cp_commit();
            cp_wait1();
        } else {
            cp_wait0();
        }
        __syncthreads();

        uint32_t sb = smb + (t & 1) * 98304;
        uint32_t ahB = sb, alB = sb + 16384, bhB = sb + 32768, blB = sb + 65536;
#pragma unroll
        for (int s = 0; s < 4; s++) {
            uint32_t bh[4][2], bl[4][2];
#pragma unroll
            for (int jp = 0; jp < 2; jp++) {
                int rowb = wn + jp * 16 + brow_off;
                uint32_t off = SWZ(rowb * 128 + s * 32 + bbyte);
                uint32_t r4[4];
                ldm4(r4, bhB + off);
                bh[jp * 2][0] = r4[0]; bh[jp * 2][1] = r4[1];
                bh[jp * 2 + 1][0] = r4[2]; bh[jp * 2 + 1][1] = r4[3];
                ldm4(r4, blB + off);
                bl[jp * 2][0] = r4[0]; bl[jp * 2][1] = r4[1];
                bl[jp * 2 + 1][0] = r4[2]; bl[jp * 2 + 1][1] = r4[3];
            }
#pragma unroll
            for (int im = 0; im < 4; im++) {
                int rowa = wm + im * 16 + arow_off;
                uint32_t off = SWZ(rowa * 128 + s * 32 + abyte);
                uint32_t ah[4], al[4];
                ldm4(ah, ahB + off);
                ldm4(al, alB + off);
#pragma unroll
                for (int jn = 0; jn < 4; jn++) {
                    mma16816(acc[im][jn], ah, bh[jn]);
                    mma16816(acc[im][jn], ah, bl[jn]);
                    mma16816(acc[im][jn], al, bh[jn]);
                }
            }
        }
        __syncthreads();
    }

    if (EPI == 0) {
        epilogue_nchw<4>(acc, out, bstride, M, m0, n0, wm, wn, lane);
    } else {
        epilogue_split(acc, ohi, olo, (float*)smx, m0, n0, tid, wid, wm, wn, lane);
    }
}

// ---------------- deformable bilinear gather -> bf16 hi/lo col planes ----------------
__global__ __launch_bounds__(256) void deform_col_k(const float* __restrict__ nhwc,
                                                    const float* __restrict__ off,
                                                    __nv_bfloat16* __restrict__ colh,
                                                    __nv_bfloat16* __restrict__ coll) {
    int warp = (blockIdx.x * 256 + threadIdx.x) >> 5;
    int lane = threadIdx.x & 31;
    if (warp >= NG) return;
    int n = warp;
    int b = n >> 12, ij = n & 4095, i = ij >> 6, j = ij & 63;
    const float* offb = off + (size_t)b * 18 * 4096 + ij;
#pragma unroll
    for (int k = 0; k < 9; k++) {
        float dy = offb[(size_t)(2 * k) << 12];
        float dx = offb[(size_t)(2 * k + 1) << 12];
        float y = dy + (float)(i - 1 + k / 3);
        float x = dx + (float)(j - 1 + k % 3);
        float y0f = floorf(y), x0f = floorf(x);
        int y0 = (int)y0f, x0 = (int)x0f;
        float wy = y - y0f, wx = x - x0f;
        bool vy0 = (unsigned)y0 < 64u;
        bool vy1 = (unsigned)(y0 + 1) < 64u;
        bool vx0 = (unsigned)x0 < 64u;
        bool vx1 = (unsigned)(x0 + 1) < 64u;
        float w00 = (vy0 && vx0) ? (1.f - wy) * (1.f - wx) : 0.f;
        float w01 = (vy0 && vx1) ? (1.f - wy) * wx : 0.f;
        float w10 = (vy1 && vx0) ? wy * (1.f - wx) : 0.f;
        float w11 = (vy1 && vx1) ? wy * wx : 0.f;
        int cy0 = min(max(y0, 0), 63), cy1 = min(max(y0 + 1, 0), 63);
        int cx0 = min(max(x0, 0), 63), cx1 = min(max(x0 + 1, 0), 63);
        const float* p00 = nhwc + (((size_t)b * 64 + cy0) * 64 + cx0) * 256;
        const float* p01 = nhwc + (((size_t)b * 64 + cy0) * 64 + cx1) * 256;
        const float* p10 = nhwc + (((size_t)b * 64 + cy1) * 64 + cx0) * 256;
        const float* p11 = nhwc + (((size_t)b * 64 + cy1) * 64 + cx1) * 256;
        __nv_bfloat16* ch = colh + (size_t)n * KDIM + k * 256;
        __nv_bfloat16* cl = coll + (size_t)n * KDIM + k * 256;
#pragma unroll
        for (int it = 0; it < 8; it++) {
            int c = lane + it * 32;
            float v = w00 * p00[c] + w01 * p01[c] + w10 * p10[c] + w11 * p11[c];
            __nv_bfloat16 h = __float2bfloat16(v);
            ch[c] = h;
            cl[c] = __float2bfloat16(v - __bfloat162float(h));
        }
    }
}

// ---------------- rep-points epilogue ----------------
__global__ __launch_bounds__(256) void reppoints_k(const float* __restrict__ off1,
                                                   const float* __restrict__ off2,
                                                   float* __restrict__ out) {
    int idx = blockIdx.x * 256 + threadIdx.x;
    if (idx >= OFFN) return;
    int rem = idx % 73728;
    int ch = rem >> 12;
    int ij = rem & 4095;
    int i = ij >> 6, j = ij & 63;
    int k = ch >> 1;
    float init = (ch & 1) ? (float)(j + (k % 3) - 1) : (float)(i + (k / 3) - 1);
    float r1 = init + off1[idx];
    out[idx] = r1;
    out[OFFN + idx] = r1 + off2[idx];
}

// ---------------- host orchestration (2-stream overlap) ----------------
extern "C" void kernel_launch(void* const* d_in, const int* in_sizes, int n_in,
                              void* d_out, int out_size) {
    const float* feature = (const float*)d_in[0];
    const float* loc_ws  = (const float*)d_in[1];
    const float* loc_g   = (const float*)d_in[2];
    const float* loc_b   = (const float*)d_in[3];
    const float* cls_ws  = (const float*)d_in[4];
    const float* cls_g   = (const float*)d_in[5];
    const float* cls_b   = (const float*)d_in[6];
    const float* pi_w    = (const float*)d_in[7];
    const float* pio_w   = (const float*)d_in[8];
    const float* prd_w   = (const float*)d_in[9];
    const float* pro_w   = (const float*)d_in[10];
    const float* cd_w    = (const float*)d_in[11];
    const float* co_w    = (const float*)d_in[12];
    float* out = (float*)d_out;

    static int init_done = 0;
    static cudaStream_t s1, s2;
    static cudaEvent_t evRoot, evW, evF, evOff1, evE1, evE2;
    if (!init_done) {
        cudaFuncSetAttribute(gemm_conv_k<128, 512, 0>, cudaFuncAttributeMaxDynamicSharedMemorySize, BIG_SMEM);
        cudaFuncSetAttribute(gemm_conv_k<128, 512, 1>, cudaFuncAttributeMaxDynamicSharedMemorySize, BIG_SMEM);
        cudaFuncSetAttribute(gemm_conv_k<32, 256, 0>, cudaFuncAttributeMaxDynamicSharedMemorySize, SMALL_SMEM);
        cudaFuncSetAttribute(gemm_col_k<0>, cudaFuncAttributeMaxDynamicSharedMemorySize, COL_SMEM);
        cudaFuncSetAttribute(gemm_col_k<1>, cudaFuncAttributeMaxDynamicSharedMemorySize, COL_SMEM);
        cudaStreamCreateWithFlags(&s1, cudaStreamNonBlocking);
        cudaStreamCreateWithFlags(&s2, cudaStreamNonBlocking);
        cudaEventCreateWithFlags(&evRoot, cudaEventDisableTiming);
        cudaEventCreateWithFlags(&evW, cudaEventDisableTiming);
        cudaEventCreateWithFlags(&evF, cudaEventDisableTiming);
        cudaEventCreateWithFlags(&evOff1, cudaEventDisableTiming);
        cudaEventCreateWithFlags(&evE1, cudaEventDisableTiming);
        cudaEventCreateWithFlags(&evE2, cudaEventDisableTiming);
        init_done = 1;
    }

    __nv_bfloat16 *wahi, *walo, *fhi, *flo;
    __nv_bfloat16 *t1hi, *t1lo, *u1hi, *u1lo, *col1h, *col1l, *t2hi, *t2lo, *col2h, *col2l;
    float *buf1, *buf2, *nh1, *nh2, *off1, *off2, *ws1, *ws2;
    cudaGetSymbolAddress((void**)&wahi,  g_wahi);
    cudaGetSymbolAddress((void**)&walo,  g_walo);
    cudaGetSymbolAddress((void**)&fhi,   g_fhi);
    cudaGetSymbolAddress((void**)&flo,   g_flo);
    cudaGetSymbolAddress((void**)&t1hi,  g_t1hi);
    cudaGetSymbolAddress((void**)&t1lo,  g_t1lo);
    cudaGetSymbolAddress((void**)&u1hi,  g_u1hi);
    cudaGetSymbolAddress((void**)&u1lo,  g_u1lo);
    cudaGetSymbolAddress((void**)&col1h, g_col1h);
    cudaGetSymbolAddress((void**)&col1l, g_col1l);
    cudaGetSymbolAddress((void**)&t2hi,  g_t2hi);
    cudaGetSymbolAddress((void**)&t2lo,  g_t2lo);
    cudaGetSymbolAddress((void**)&col2h, g_col2h);
    cudaGetSymbolAddress((void**)&col2l, g_col2l);
    cudaGetSymbolAddress((void**)&buf1,  g_buf1);
    cudaGetSymbolAddress((void**)&buf2,  g_buf2);
    cudaGetSymbolAddress((void**)&nh1,   g_nh1);
    cudaGetSymbolAddress((void**)&nh2,   g_nh2);
    cudaGetSymbolAddress((void**)&off1,  g_off1);
    cudaGetSymbolAddress((void**)&off2,  g_off2);
    cudaGetSymbolAddress((void**)&ws1,   g_ws1);
    cudaGetSymbolAddress((void**)&ws2,   g_ws2);

    W12 w12;
    w12.p[0] = loc_ws;           w12.m[0] = 256;
    w12.p[1] = loc_ws + WSZ;     w12.m[1] = 256;
    w12.p[2] = loc_ws + 2 * WSZ; w12.m[2] = 256;
    w12.p[3] = cls_ws;           w12.m[3] = 256;
    w12.p[4] = cls_ws + WSZ;     w12.m[4] = 256;
    w12.p[5] = cls_ws + 2 * WSZ; w12.m[5] = 256;
    w12.p[6] = pi_w;             w12.m[6] = 256;
    w12.p[7] = pio_w;            w12.m[7] = 18;
    w12.p[8] = prd_w;            w12.m[8] = 256;
    w12.p[9] = pro_w;            w12.m[9] = 18;
    w12.p[10] = cd_w;            w12.m[10] = 256;
    w12.p[11] = co_w;            w12.m[11] = 15;

    dim3 tgrid(128, 8, 4), tblk(32, 8);
    dim3 gBig(64, 2), gSmall(64, 1);

    cudaEventRecord(evRoot, 0);
    cudaStreamWaitEvent(s1, evRoot, 0);
    cudaStreamWaitEvent(s2, evRoot, 0);

    wconv_all_k<<<768, 256, 0, s1>>>(w12, wahi, walo);
    cudaEventRecord(evW, s1);
    tsplit_k<<<tgrid, tblk, 0, s2>>>(feature, fhi, flo, nullptr, nullptr, nullptr, nullptr);
    cudaEventRecord(evF, s2);
    cudaStreamWaitEvent(s1, evF, 0);
    cudaStreamWaitEvent(s2, evW, 0);

    // ---- s1: loc subnet -> offset1 -> offset2 branch -> reppoints ----
    for (int l = 0; l < 3; l++) {
        gemm_conv_k<128, 512, 0><<<gBig, 512, BIG_SMEM, s1>>>(
            wahi + (size_t)l * PL, walo + (size_t)l * PL,
            l == 0 ? fhi : t1hi, l == 0 ? flo : t1lo, buf1, nullptr, nullptr, 256, 256 * 4096);
        gnstat_k<<<128, 256, 0, s1>>>(buf1, ws1);
        tsplit_k<<<tgrid, tblk, 0, s1>>>(buf1, t1hi, t1lo, l == 2 ? nh1 : nullptr,
                                         ws1, loc_g + l * 256, loc_b + l * 256);
    }
    gemm_conv_k<128, 512, 1><<<gBig, 512, BIG_SMEM, s1>>>(
        wahi + 6 * (size_t)PL, walo + 6 * (size_t)PL, t1hi, t1lo,
        nullptr, u1hi, u1lo, 256, 0);
    gemm_conv_k<32, 256, 0><<<gSmall, 256, SMALL_SMEM, s1>>>(
        wahi + 7 * (size_t)PL, walo + 7 * (size_t)PL, u1hi, u1lo,
        off1, nullptr, nullptr, 18, 18 * 4096);
    cudaEventRecord(evOff1, s1);

    deform_col_k<<<2048, 256, 0, s1>>>(nh1, off1, col1h, col1l);
    gemm_col_k<1><<<gBig, 512, COL_SMEM, s1>>>(
        wahi + 8 * (size_t)PL, walo + 8 * (size_t)PL, col1h, col1l,
        nullptr, t1hi, t1lo, 256, 0);
    gemm_conv_k<32, 256, 0><<<gSmall, 256, SMALL_SMEM, s1>>>(
        wahi + 9 * (size_t)PL, walo + 9 * (size_t)PL, t1hi, t1lo,
        off2, nullptr, nullptr, 18, 18 * 4096);
    reppoints_k<<<(OFFN + 255) / 256, 256, 0, s1>>>(off1, off2, out);
    cudaEventRecord(evE1, s1);

    // ---- s2: cls subnet -> classification branch ----
    for (int l = 0; l < 3; l++) {
        gemm_conv_k<128, 512, 0><<<gBig, 512, BIG_SMEM, s2>>>(
            wahi + (size_t)(3 + l) * PL, walo + (size_t)(3 + l) * PL,
            l == 0 ? fhi : t2hi, l == 0 ? flo : t2lo, buf2, nullptr, nullptr, 256, 256 * 4096);
        gnstat_k<<<128, 256, 0, s2>>>(buf2, ws2);
        tsplit_k<<<tgrid, tblk, 0, s2>>>(buf2, l == 2 ? nullptr : t2hi, l == 2 ? nullptr : t2lo,
                                         l == 2 ? nh2 : nullptr,
                                         ws2, cls_g + l * 256, cls_b + l * 256);
    }
    cudaStreamWaitEvent(s2, evOff1, 0);
    deform_col_k<<<2048, 256, 0, s2>>>(nh2, off1, col2h, col2l);
    gemm_col_k<1><<<gBig, 512, COL_SMEM, s2>>>(
        wahi + 10 * (size_t)PL, walo + 10 * (size_t)PL, col2h, col2l,
        nullptr, t2hi, t2lo, 256, 0);
    gemm_conv_k<32, 256, 0><<<gSmall, 256, SMALL_SMEM, s2>>>(
        wahi + 11 * (size_t)PL, walo + 11 * (size_t)PL, t2hi, t2lo,
        out + 2 * OFFN, nullptr, nullptr, 15, 15 * 4096);
    cudaEventRecord(evE2, s2);

    cudaStreamWaitEvent(0, evE1, 0);
    cudaStreamWaitEvent(0, evE2, 0);
}

// round 15
// speedup vs baseline: 1.6656x; 1.0710x over previous
#include <cuda_runtime.h>
#include <cuda_bf16.h>
#include <cstdint>
#include <math.h>

#define NG 16384
#define OFFN (18*16384)
#define KDIM 2304
#define WSZ (256*256*9)
#define PL 589824
#define COL_SMEM 197632
#define SPL2 16896           // slab plane: 264 pix * 64B (4 rows x 66)
#define BIG2_SMEM 101376     // 2*16KB A + 2*2*SPL2 slab + pad
#define SPL 25344            // small-kernel slab plane: 396 pix * 64B
#define SMALL_SMEM 110592

// ---------------- scratch ----------------
__device__ __nv_bfloat16 g_wahi[(size_t)12*PL];
__device__ __nv_bfloat16 g_walo[(size_t)12*PL];
__device__ __nv_bfloat16 g_fhi[(size_t)NG*256];
__device__ __nv_bfloat16 g_flo[(size_t)NG*256];
__device__ __nv_bfloat16 g_t1hi[(size_t)NG*256];
__device__ __nv_bfloat16 g_t1lo[(size_t)NG*256];
__device__ __nv_bfloat16 g_u1hi[(size_t)NG*256];
__device__ __nv_bfloat16 g_u1lo[(size_t)NG*256];
__device__ float g_buf1[(size_t)NG*256];
__device__ float g_nh1[(size_t)NG*256];
__device__ __nv_bfloat16 g_col1h[(size_t)NG*KDIM];
__device__ __nv_bfloat16 g_col1l[(size_t)NG*KDIM];
__device__ float g_ws1[256];
__device__ __nv_bfloat16 g_t2hi[(size_t)NG*256];
__device__ __nv_bfloat16 g_t2lo[(size_t)NG*256];
__device__ float g_buf2[(size_t)NG*256];
__device__ float g_nh2[(size_t)NG*256];
__device__ __nv_bfloat16 g_col2h[(size_t)NG*KDIM];
__device__ __nv_bfloat16 g_col2l[(size_t)NG*KDIM];
__device__ float g_ws2[256];
__device__ float g_off1[OFFN];
__device__ float g_off2[OFFN];

// ---------------- PTX helpers ----------------
__device__ __forceinline__ uint32_t smem_u32(const void* p) {
    uint32_t a;
    asm("{ .reg .u64 t; cvta.to.shared.u64 t, %1; cvt.u32.u64 %0, t; }" : "=r"(a) : "l"(p));
    return a;
}
#define SWZ(o)   ((o) ^ (((o) >> 3) & 0x70))
#define SWZ64(o) ((o) ^ (((o) >> 3) & 0x30))

__device__ __forceinline__ void cp16(uint32_t dst, const void* src, int ss) {
    asm volatile("cp.async.cg.shared.global [%0], [%1], 16, %2;\n" :: "r"(dst), "l"(src), "r"(ss));
}
__device__ __forceinline__ void cp_commit() { asm volatile("cp.async.commit_group;\n" ::: "memory"); }
__device__ __forceinline__ void cp_wait0()  { asm volatile("cp.async.wait_group 0;\n" ::: "memory"); }
__device__ __forceinline__ void cp_wait1()  { asm volatile("cp.async.wait_group 1;\n" ::: "memory"); }

__device__ __forceinline__ void ldm4(uint32_t* r, uint32_t addr) {
    asm volatile("ldmatrix.sync.aligned.m8n8.x4.shared.b16 {%0,%1,%2,%3}, [%4];"
        : "=r"(r[0]), "=r"(r[1]), "=r"(r[2]), "=r"(r[3]) : "r"(addr));
}
__device__ __forceinline__ void mma16816(float* d, const uint32_t* a, const uint32_t* b) {
    asm volatile("mma.sync.aligned.m16n8k16.row.col.f32.bf16.bf16.f32 "
        "{%0,%1,%2,%3}, {%4,%5,%6,%7}, {%8,%9}, {%0,%1,%2,%3};"
        : "+f"(d[0]), "+f"(d[1]), "+f"(d[2]), "+f"(d[3])
        : "r"(a[0]), "r"(a[1]), "r"(a[2]), "r"(a[3]), "r"(b[0]), "r"(b[1]));
}
__device__ __forceinline__ unsigned short bfbits(float x) {
    __nv_bfloat16 h = __float2bfloat16(x);
    return *reinterpret_cast<unsigned short*>(&h);
}

// ---------------- epilogues ----------------
template<int IM>
__device__ __forceinline__ void epilogue_nchw(float acc[IM][4][4], float* out, int bstride,
                                              int M, int m0, int n0, int wm, int wn, int lane) {
    int b = n0 >> 12, ij0 = n0 & 4095;
    float* outb = out + (size_t)b * bstride + ij0;
#pragma unroll
    for (int im = 0; im < IM; im++) {
        int mrow = m0 + wm + im * 16 + (lane >> 2);
#pragma unroll
        for (int jn = 0; jn < 4; jn++) {
            int ncol = wn + jn * 8 + (lane & 3) * 2;
            if (mrow < M) {
                float2 v = make_float2(acc[im][jn][0], acc[im][jn][1]);
                *(float2*)(outb + (size_t)mrow * 4096 + ncol) = v;
            }
            if (mrow + 8 < M) {
                float2 v = make_float2(acc[im][jn][2], acc[im][jn][3]);
                *(float2*)(outb + (size_t)(mrow + 8) * 4096 + ncol) = v;
            }
        }
    }
}

// 256-thread CTA, 8 warps, IM=4, tile 128m x 128n -> NHWC hi/lo planes.
__device__ __forceinline__ void epilogue_split128(float acc[4][4][4],
                                                  __nv_bfloat16* ohi, __nv_bfloat16* olo,
                                                  float* smemf, int m0, int n0,
                                                  int tid, int wid, int wm, int wn, int lane) {
    for (int ch = 0; ch < 4; ch++) {
        __syncthreads();
        if ((wid & 3) == ch) {
#pragma unroll
            for (int im = 0; im < 4; im++) {
                int m = wm + im * 16 + (lane >> 2);
#pragma unroll
                for (int jn = 0; jn < 4; jn++) {
                    int nl = jn * 8 + (lane & 3) * 2;
                    smemf[m * 33 + nl] = acc[im][jn][0];
                    smemf[m * 33 + nl + 1] = acc[im][jn][1];
                    smemf[(m + 8) * 33 + nl] = acc[im][jn][2];
                    smemf[(m + 8) * 33 + nl + 1] = acc[im][jn][3];
                }
            }
        }
        __syncthreads();
#pragma unroll
        for (int it2 = 0; it2 < 2; it2++) {
            int item = tid + it2 * 256;
            int p = item >> 4;            // 0..31 pixel in chunk
            int cq = (item & 15) * 8;     // 8 channels
            size_t base = (size_t)(n0 + ch * 32 + p) * 256 + m0 + cq;
            uint32_t hw[4], lw[4];
#pragma unroll
            for (int i = 0; i < 4; i++) {
                float v0 = smemf[(cq + 2 * i) * 33 + p];
                float v1 = smemf[(cq + 2 * i + 1) * 33 + p];
                unsigned short h0 = bfbits(v0), h1 = bfbits(v1);
                float r0 = v0 - __bfloat162float(*reinterpret_cast<__nv_bfloat16*>(&h0));
                float r1 = v1 - __bfloat162float(*reinterpret_cast<__nv_bfloat16*>(&h1));
                hw[i] = (uint32_t)h0 | ((uint32_t)h1 << 16);
                lw[i] = (uint32_t)bfbits(r0) | ((uint32_t)bfbits(r1) << 16);
            }
            *(uint4*)(ohi + base) = make_uint4(hw[0], hw[1], hw[2], hw[3]);
            *(uint4*)(olo + base) = make_uint4(lw[0], lw[1], lw[2], lw[3]);
        }
    }
}

// 512-thread version (col GEMM split epilogue, 256-n tile) — unchanged from R9.
__device__ __forceinline__ void epilogue_split(float acc[4][4][4],
                                               __nv_bfloat16* ohi, __nv_bfloat16* olo,
                                               float* smemf, int m0, int n0,
                                               int tid, int wid, int wm, int wn, int lane) {
    for (int ch = 0; ch < 8; ch++) {
        __syncthreads();
        if ((wid & 7) == ch) {
#pragma unroll
            for (int im = 0; im < 4; im++) {
                int m = wm + im * 16 + (lane >> 2);
#pragma unroll
                for (int jn = 0; jn < 4; jn++) {
                    int nl = jn * 8 + (lane & 3) * 2;
                    smemf[m * 33 + nl] = acc[im][jn][0];
                    smemf[m * 33 + nl + 1] = acc[im][jn][1];
                    smemf[(m + 8) * 33 + nl] = acc[im][jn][2];
                    smemf[(m + 8) * 33 + nl + 1] = acc[im][jn][3];
                }
            }
        }
        __syncthreads();
        int p = tid >> 4;
        int cq = (tid & 15) * 8;
        size_t base = (size_t)(n0 + ch * 32 + p) * 256 + m0 + cq;
        uint32_t hw[4], lw[4];
#pragma unroll
        for (int i = 0; i < 4; i++) {
            float v0 = smemf[(cq + 2 * i) * 33 + p];
            float v1 = smemf[(cq + 2 * i + 1) * 33 + p];
            unsigned short h0 = bfbits(v0), h1 = bfbits(v1);
            float r0 = v0 - __bfloat162float(*reinterpret_cast<__nv_bfloat16*>(&h0));
            float r1 = v1 - __bfloat162float(*reinterpret_cast<__nv_bfloat16*>(&h1));
            hw[i] = (uint32_t)h0 | ((uint32_t)h1 << 16);
            lw[i] = (uint32_t)bfbits(r0) | ((uint32_t)bfbits(r1) << 16);
        }
        *(uint4*)(ohi + base) = make_uint4(hw[0], hw[1], hw[2], hw[3]);
        *(uint4*)(olo + base) = make_uint4(lw[0], lw[1], lw[2], lw[3]);
    }
}

// ---------------- all-weights convert ----------------
struct W12 { const float* p[12]; int m[12]; };
__global__ __launch_bounds__(256) void wconv_all_k(W12 w,
                                                   __nv_bfloat16* __restrict__ hi,
                                                   __nv_bfloat16* __restrict__ lo) {
    __shared__ float rows[4][KDIM];
    int t = blockIdx.x >> 6;
    int rb = blockIdx.x & 63;
    int tid = threadIdx.x;
    int m0 = rb * 4;
    const float* src = w.p[t];
    int Mv = w.m[t];
    for (int i = tid; i < 4 * KDIM; i += 256) {
        int r = i / KDIM, k = i - r * KDIM;
        int m = m0 + r;
        rows[r][k] = (m < Mv) ? src[(size_t)m * KDIM + k] : 0.f;
    }
    __syncthreads();
    for (int i = tid; i < 4 * KDIM; i += 256) {
        int r = i / KDIM, k = i - r * KDIM;
        int kk = k >> 8, c = k & 255;
        float v = rows[r][c * 9 + kk];
        size_t dst = (size_t)t * PL + (size_t)(m0 + r) * KDIM + k;
        __nv_bfloat16 h = __float2bfloat16(v);
        hi[dst] = h;
        lo[dst] = __float2bfloat16(v - __bfloat162float(h));
    }
}

// ---------------- GN stats ----------------
__global__ __launch_bounds__(256) void gnstat_k(const float* __restrict__ in,
                                                float* __restrict__ ws) {
    int bg = blockIdx.x;
    int b = bg >> 5, g = bg & 31;
    int tid = threadIdx.x;
    const float4* p = (const float4*)(in + ((size_t)b * 256 + g * 8) * 4096);
    float s = 0.f, s2 = 0.f;
    for (int i = tid; i < 8192; i += 256) {
        float4 v = p[i];
        s += v.x + v.y + v.z + v.w;
        s2 += v.x * v.x + v.y * v.y + v.z * v.z + v.w * v.w;
    }
    __shared__ float sA[256], sB[256];
    sA[tid] = s; sB[tid] = s2;
    __syncthreads();
    for (int st = 128; st > 0; st >>= 1) {
        if (tid < st) { sA[tid] += sA[tid + st]; sB[tid] += sB[tid + st]; }
        __syncthreads();
    }
    if (tid == 0) {
        float mean = sA[0] * (1.f / 32768.f);
        float var = sB[0] * (1.f / 32768.f) - mean * mean;
        ws[bg * 2] = mean;
        ws[bg * 2 + 1] = rsqrtf(var + 1e-5f);
    }
}

// ---------------- NCHW fp32 -> (GN affine) -> NHWC hi/lo bf16 (+fp32) ----------------
__global__ void tsplit_k(const float* __restrict__ in,
                         __nv_bfloat16* __restrict__ hi, __nv_bfloat16* __restrict__ lo,
                         float* __restrict__ f32o,
                         const float* __restrict__ ws,
                         const float* __restrict__ gamma, const float* __restrict__ beta) {
    __shared__ float t[32][33];
    int b = blockIdx.z, hw0 = blockIdx.x * 32, c0 = blockIdx.y * 32;
    int tx = threadIdx.x, ty = threadIdx.y;
    const float* ip = in + (size_t)b * 256 * 4096;
    for (int r = ty; r < 32; r += 8)
        t[r][tx] = ip[(size_t)(c0 + r) * 4096 + hw0 + tx];
    __syncthreads();
    int ch = c0 + tx;
    float sc = 1.f, sh = 0.f;
    if (ws) {
        int bg = b * 32 + (ch >> 3);
        float mean = ws[bg * 2], rstd = ws[bg * 2 + 1];
        sc = rstd * gamma[ch];
        sh = beta[ch] - mean * sc;
    }
    for (int r = ty; r < 32; r += 8) {
        float v = t[tx][r] * sc + sh;
        size_t idx = (size_t)b * 4096 * 256 + (size_t)(hw0 + r) * 256 + ch;
        if (hi) {
            __nv_bfloat16 h = __float2bfloat16(v);
            hi[idx] = h;
            lo[idx] = __float2bfloat16(v - __bfloat162float(h));
        }
        if (f32o) f32o[idx] = v;
    }
}

// ---------------- big implicit-conv GEMM: 128M x 128N, 256 thr, 2 CTA/SM ----------------
template<int EPI>
__global__ __launch_bounds__(256, 2) void gemm_big_k(
    const __nv_bfloat16* __restrict__ Ahi, const __nv_bfloat16* __restrict__ Alo,
    const __nv_bfloat16* __restrict__ Bhi, const __nv_bfloat16* __restrict__ Blo,
    float* __restrict__ out, __nv_bfloat16* __restrict__ ohi, __nv_bfloat16* __restrict__ olo,
    int M, int bstride) {
    constexpr int APL = 8192;       // A plane: 128 rows * 64B
    constexpr int AST = 2 * APL;
    constexpr int SST = 2 * SPL2;

    extern __shared__ char smx[];
    uint32_t smb = (smem_u32(smx) + 1023) & ~1023u;
    uint32_t aB = smb, sB = smb + 2 * AST;

    int tid = threadIdx.x;
    int lane = tid & 31;
    int wid = tid >> 5;
    int wm = (wid >> 2) * 64;
    int wn = (wid & 3) * 32;
    int n0 = blockIdx.x * 128;
    int m0 = blockIdx.y * 128;
    int b = n0 >> 12, ij0 = n0 & 4095;
    int i0 = ij0 >> 6;

    auto load_A = [&](int t, uint32_t dst) {
        int cg = t / 9, tap = t - cg * 9;
        int koff = tap * 256 + cg * 32;
#pragma unroll
        for (int idx = tid; idx < 1024; idx += 256) {
            int plane = idx >= 512;
            int q = idx - plane * 512;
            int row = q >> 2, c16 = q & 3;
            const __nv_bfloat16* src =
                (plane ? Alo : Ahi) + (size_t)(m0 + row) * KDIM + koff + c16 * 8;
            cp16(dst + plane * APL + SWZ64(row * 64 + c16 * 16), src, 16);
        }
    };
    // slab: 264 pixels (4 rows x 66) * 4 chunks = 1056 per plane, 2112 total
    auto load_slab = [&](int cg, uint32_t dst) {
        for (int idx = tid; idx < 2112; idx += 256) {
            int plane = idx >= 1056;
            int q = idx - plane * 1056;
            int pix = q >> 2, c16 = q & 3;
            int sy = pix / 66, sx = pix - sy * 66;
            int y = i0 - 1 + sy, x = sx - 1;
            bool v = ((unsigned)y < 64u) && ((unsigned)x < 64u);
            int yy = v ? y : 0, xx = v ? x : 0;
            const __nv_bfloat16* src = (plane ? Blo : Bhi) +
                ((((size_t)b * 64 + yy) * 64 + xx) << 8) + cg * 32 + c16 * 8;
            cp16(dst + plane * SPL2 + SWZ64(pix * 64 + c16 * 16), src, v ? 16 : 0);
        }
    };

    float acc[4][4][4];
#pragma unroll
    for (int im = 0; im < 4; im++)
#pragma unroll
        for (int jn = 0; jn < 4; jn++)
#pragma unroll
            for (int q = 0; q < 4; q++) acc[im][jn][q] = 0.f;

    int arow = lane & 15;
    int abyte = (lane >> 4) * 16;
    int mi = lane >> 3;
    int brow_off = (mi >> 1) * 8 + (lane & 7);
    int bbyte = (mi & 1) * 16;
    int b66[2];
#pragma unroll
    for (int jp = 0; jp < 2; jp++) {
        int rowb = wn + jp * 16 + brow_off;
        b66[jp] = (rowb >> 6) * 66 + (rowb & 63);
    }

    load_slab(0, sB);
    load_A(0, aB);
    cp_commit();

    for (int t = 0; t < 72; t++) {
        int cg = t / 9, tap = t - cg * 9;
        if (t + 1 < 72) {
            load_A(t + 1, aB + ((t + 1) & 1) * AST);
            if (tap == 4 && cg < 7) load_slab(cg + 1, sB + ((cg + 1) & 1) * SST);
            cp_commit();
            cp_wait1();
        } else {
            cp_wait0();
        }
        __syncthreads();

        uint32_t ab = aB + (t & 1) * AST;
        uint32_t sb = sB + (cg & 1) * SST;
        int kd = (tap * 11) >> 5;
        int tapoff = kd * 66 + (tap - kd * 3);
#pragma unroll
        for (int s = 0; s < 2; s++) {
            uint32_t bh[4][2], bl[4][2];
#pragma unroll
            for (int jp = 0; jp < 2; jp++) {
                int pix = b66[jp] + tapoff;
                uint32_t off = SWZ64(pix * 64 + s * 32 + bbyte);
                uint32_t r4[4];
                ldm4(r4, sb + off);
                bh[jp * 2][0] = r4[0]; bh[jp * 2][1] = r4[1];
                bh[jp * 2 + 1][0] = r4[2]; bh[jp * 2 + 1][1] = r4[3];
                ldm4(r4, sb + SPL2 + off);
                bl[jp * 2][0] = r4[0]; bl[jp * 2][1] = r4[1];
                bl[jp * 2 + 1][0] = r4[2]; bl[jp * 2 + 1][1] = r4[3];
            }
#pragma unroll
            for (int im = 0; im < 4; im++) {
                int rowa = wm + im * 16 + arow;
                uint32_t offa = SWZ64(rowa * 64 + s * 32 + abyte);
                uint32_t ah[4], al[4];
                ldm4(ah, ab + offa);
                ldm4(al, ab + APL + offa);
#pragma unroll
                for (int jn = 0; jn < 4; jn++) {
                    mma16816(acc[im][jn], ah, bh[jn]);
                    mma16816(acc[im][jn], ah, bl[jn]);
                    mma16816(acc[im][jn], al, bh[jn]);
                }
            }
        }
        __syncthreads();
    }

    if (EPI == 0) {
        epilogue_nchw<4>(acc, out, bstride, M, m0, n0, wm, wn, lane);
    } else {
        epilogue_split128(acc, ohi, olo, (float*)smx, m0, n0, tid, wid, wm, wn, lane);
    }
}

// ---------------- small implicit-conv GEMM (M=18/15): R9 template path ----------------
template<int MROWS, int NTHREADS>
__global__ __launch_bounds__(NTHREADS, 1) void gemm_conv_k(
    const __nv_bfloat16* __restrict__ Ahi, const __nv_bfloat16* __restrict__ Alo,
    const __nv_bfloat16* __restrict__ Bhi, const __nv_bfloat16* __restrict__ Blo,
    float* __restrict__ out, int M, int bstride) {
    constexpr int MW = NTHREADS / 256;
    constexpr int IM = MROWS / (MW * 16);
    constexpr int APL = MROWS * 64;
    constexpr int AST = 2 * APL;
    constexpr int SST = 2 * SPL;

    extern __shared__ char smx[];
    uint32_t smb = (smem_u32(smx) + 1023) & ~1023u;
    uint32_t aB = smb, sB = smb + 2 * AST;

    int tid = threadIdx.x;
    int lane = tid & 31;
    int wid = tid >> 5;
    int wm = (wid >> 3) * (IM * 16);
    int wn = (wid & 7) * 32;
    int n0 = blockIdx.x * 256;
    int m0 = blockIdx.y * MROWS;
    int b = n0 >> 12, ij0 = n0 & 4095;
    int i0 = ij0 >> 6;

    auto load_A = [&](int t, uint32_t dst) {
        int cg = t / 9, tap = t - cg * 9;
        int koff = tap * 256 + cg * 32;
#pragma unroll
        for (int idx = tid; idx < MROWS * 8; idx += NTHREADS) {
            int plane = idx >= MROWS * 4;
            int q = idx - plane * (MROWS * 4);
            int row = q >> 2, c16 = q & 3;
            const __nv_bfloat16* src =
                (plane ? Alo : Ahi) + (size_t)(m0 + row) * KDIM + koff + c16 * 8;
            cp16(dst + plane * APL + SWZ64(row * 64 + c16 * 16), src, 16);
        }
    };
    auto load_slab = [&](int cg, uint32_t dst) {
        for (int idx = tid; idx < 3168; idx += NTHREADS) {
            int plane = idx >= 1584;
            int q = idx - plane * 1584;
            int pix = q >> 2, c16 = q & 3;
            int sy = pix / 66, sx = pix - sy * 66;
            int y = i0 - 1 + sy, x = sx - 1;
            bool v = ((unsigned)y < 64u) && ((unsigned)x < 64u);
            int yy = v ? y : 0, xx = v ? x : 0;
            const __nv_bfloat16* src = (plane ? Blo : Bhi) +
                ((((size_t)b * 64 + yy) * 64 + xx) << 8) + cg * 32 + c16 * 8;
            cp16(dst + plane * SPL + SWZ64(pix * 64 + c16 * 16), src, v ? 16 : 0);
        }
    };

    float acc[IM][4][4];
#pragma unroll
    for (int im = 0; im < IM; im++)
#pragma unroll
        for (int jn = 0; jn < 4; jn++)
#pragma unroll
            for (int q = 0; q < 4; q++) acc[im][jn][q] = 0.f;

    int arow = lane & 15;
    int abyte = (lane >> 4) * 16;
    int mi = lane >> 3;
    int brow_off = (mi >> 1) * 8 + (lane & 7);
    int bbyte = (mi & 1) * 16;
    int b66[2];
#pragma unroll
    for (int jp = 0; jp < 2; jp++) {
        int rowb = wn + jp * 16 + brow_off;
        b66[jp] = (rowb >> 6) * 66 + (rowb & 63);
    }

    load_slab(0, sB);
    load_A(0, aB);
    cp_commit();

    for (int t = 0; t < 72; t++) {
        int cg = t / 9, tap = t - cg * 9;
        if (t + 1 < 72) {
            load_A(t + 1, aB + ((t + 1) & 1) * AST);
            if (tap == 4 && cg < 7) load_slab(cg + 1, sB + ((cg + 1) & 1) * SST);
            cp_commit();
            cp_wait1();
        } else {
            cp_wait0();
        }
        __syncthreads();

        uint32_t ab = aB + (t & 1) * AST;
        uint32_t sb = sB + (cg & 1) * SST;
        int kd = (tap * 11) >> 5;
        int tapoff = kd * 66 + (tap - kd * 3);
#pragma unroll
        for (int s = 0; s < 2; s++) {
            uint32_t bh[4][2], bl[4][2];
#pragma unroll
            for (int jp = 0; jp < 2; jp++) {
                int pix = b66[jp] + tapoff;
                uint32_t off = SWZ64(pix * 64 + s * 32 + bbyte);
                uint32_t r4[4];
                ldm4(r4, sb + off);
                bh[jp * 2][0] = r4[0]; bh[jp * 2][1] = r4[1];
                bh[jp * 2 + 1][0] = r4[2]; bh[jp * 2 + 1][1] = r4[3];
                ldm4(r4, sb + SPL + off);
                bl[jp * 2][0] = r4[0]; bl[jp * 2][1] = r4[1];
                bl[jp * 2 + 1][0] = r4[2]; bl[jp * 2 + 1][1] = r4[3];
            }
#pragma unroll
            for (int im = 0; im < IM; im++) {
                int rowa = wm + im * 16 + arow;
                uint32_t offa = SWZ64(rowa * 64 + s * 32 + abyte);
                uint32_t ah[4], al[4];
                ldm4(ah, ab + offa);
                ldm4(al, ab + APL + offa);
#pragma unroll
                for (int jn = 0; jn < 4; jn++) {
                    mma16816(acc[im][jn], ah, bh[jn]);
                    mma16816(acc[im][jn], ah, bl[jn]);
                    mma16816(acc[im][jn], al, bh[jn]);
                }
            }
        }
        __syncthreads();
    }

    epilogue_nchw<IM>(acc, out, bstride, M, m0, n0, wm, wn, lane);
}

// ---------------- col-based GEMM for deform convs (R9, unchanged) ----------------
template<int EPI>
__global__ __launch_bounds__(512, 1) void gemm_col_k(const __nv_bfloat16* __restrict__ Ahi,
                                                     const __nv_bfloat16* __restrict__ Alo,
                                                     const __nv_bfloat16* __restrict__ Bhi,
                                                     const __nv_bfloat16* __restrict__ Blo,
                                                     float* __restrict__ out,
                                                     __nv_bfloat16* __restrict__ ohi,
                                                     __nv_bfloat16* __restrict__ olo,
                                                     int M, int bstride) {
    extern __shared__ char smx[];
    uint32_t smb = (smem_u32(smx) + 1023) & ~1023u;
    int tid = threadIdx.x;
    int lane = tid & 31;
    int wid = tid >> 5;
    int wm = (wid >> 3) * 64;
    int wn = (wid & 7) * 32;
    int n0 = blockIdx.x * 256;
    int m0 = blockIdx.y * 128;

    auto load_stage = [&](int t, uint32_t sb) {
        int kk = t >> 2, cg = t & 3;
        int koff = kk * 256 + cg * 64;
#pragma unroll
        for (int qi = 0; qi < 12; qi++) {
            int q = qi * 512 + tid;
            if (qi < 4) {
                int plane = (q >> 10) & 1;
                int qq = q & 1023;
                int row = qq >> 3, c16 = qq & 7;
                const __nv_bfloat16* src =
                    (plane ? Alo : Ahi) + (size_t)(m0 + row) * KDIM + koff + c16 * 8;
                cp16(sb + plane * 16384 + SWZ(row * 128 + c16 * 16), src, 16);
            } else {
                int qb = q - 2048;
                int plane = qb >> 11;
                int qq = qb & 2047;
                int row = qq >> 3, c16 = qq & 7;
                const __nv_bfloat16* src =
                    (plane ? Blo : Bhi) + (size_t)(n0 + row) * KDIM + koff + c16 * 8;
                cp16(sb + 32768 + plane * 32768 + SWZ(row * 128 + c16 * 16), src, 16);
            }
        }
    };

    float acc[4][4][4];
#pragma unroll
    for (int im = 0; im < 4; im++)
#pragma unroll
        for (int jn = 0; jn < 4; jn++)
#pragma unroll
            for (int q = 0; q < 4; q++) acc[im][jn][q] = 0.f;

    load_stage(0, smb);
    cp_commit();

    int arow_off = (lane & 15);
    int abyte = (lane >> 4) * 16;
    int mi = lane >> 3;
    int brow_off = (mi >> 1) * 8 + (lane & 7);
    int bbyte = (mi & 1) * 16;

    for (int t = 0; t < 36; t++) {
        if (t + 1 < 36) {
            load_stage(t + 1, smb + ((t + 1) & 1) * 98304);
            cp_commit();
            cp_wait1();
        } else {
            cp_wait0();
        }
        __syncthreads();

        uint32_t sb = smb + (t & 1) * 98304;
        uint32_t ahB = sb, alB = sb + 16384, bhB = sb + 32768, blB = sb + 65536;
#pragma unroll
        for (int s = 0; s < 4; s++) {
            uint32_t bh[4][2], bl[4][2];
#pragma unroll
            for (int jp = 0; jp < 2; jp++) {
                int rowb = wn + jp * 16 + brow_off;
                uint32_t off = SWZ(rowb * 128 + s * 32 + bbyte);
                uint32_t r4[4];
                ldm4(r4, bhB + off);
                bh[jp * 2][0] = r4[0]; bh[jp * 2][1] = r4[1];
                bh[jp * 2 + 1][0] = r4[2]; bh[jp * 2 + 1][1] = r4[3];
                ldm4(r4, blB + off);
                bl[jp * 2][0] = r4[0]; bl[jp * 2][1] = r4[1];
                bl[jp * 2 + 1][0] = r4[2]; bl[jp * 2 + 1][1] = r4[3];
            }
#pragma unroll
            for (int im = 0; im < 4; im++) {
                int rowa = wm + im * 16 + arow_off;
                uint32_t off = SWZ(rowa * 128 + s * 32 + abyte);
                uint32_t ah[4], al[4];
                ldm4(ah, ahB + off);
                ldm4(al, alB + off);
#pragma unroll
                for (int jn = 0; jn < 4; jn++) {
                    mma16816(acc[im][jn], ah, bh[jn]);
                    mma16816(acc[im][jn], ah, bl[jn]);
                    mma16816(acc[im][jn], al, bh[jn]);
                }
            }
        }
        __syncthreads();
    }

    if (EPI == 0) {
        epilogue_nchw<4>(acc, out, bstride, M, m0, n0, wm, wn, lane);
    } else {
        epilogue_split(acc, ohi, olo, (float*)smx, m0, n0, tid, wid, wm, wn, lane);
    }
}

// ---------------- deformable bilinear gather -> bf16 hi/lo col planes ----------------
__global__ __launch_bounds__(256) void deform_col_k(const float* __restrict__ nhwc,
                                                    const float* __restrict__ off,
                                                    __nv_bfloat16* __restrict__ colh,
                                                    __nv_bfloat16* __restrict__ coll) {
    int warp = (blockIdx.x * 256 + threadIdx.x) >> 5;
    int lane = threadIdx.x & 31;
    if (warp >= NG) return;
    int n = warp;
    int b = n >> 12, ij = n & 4095, i = ij >> 6, j = ij & 63;
    const float* offb = off + (size_t)b * 18 * 4096 + ij;
#pragma unroll
    for (int k = 0; k < 9; k++) {
        float dy = offb[(size_t)(2 * k) << 12];
        float dx = offb[(size_t)(2 * k + 1) << 12];
        float y = dy + (float)(i - 1 + k / 3);
        float x = dx + (float)(j - 1 + k % 3);
        float y0f = floorf(y), x0f = floorf(x);
        int y0 = (int)y0f, x0 = (int)x0f;
        float wy = y - y0f, wx = x - x0f;
        bool vy0 = (unsigned)y0 < 64u;
        bool vy1 = (unsigned)(y0 + 1) < 64u;
        bool vx0 = (unsigned)x0 < 64u;
        bool vx1 = (unsigned)(x0 + 1) < 64u;
        float w00 = (vy0 && vx0) ? (1.f - wy) * (1.f - wx) : 0.f;
        float w01 = (vy0 && vx1) ? (1.f - wy) * wx : 0.f;
        float w10 = (vy1 && vx0) ? wy * (1.f - wx) : 0.f;
        float w11 = (vy1 && vx1) ? wy * wx : 0.f;
        int cy0 = min(max(y0, 0), 63), cy1 = min(max(y0 + 1, 0), 63);
        int cx0 = min(max(x0, 0), 63), cx1 = min(max(x0 + 1, 0), 63);
        const float* p00 = nhwc + (((size_t)b * 64 + cy0) * 64 + cx0) * 256;
        const float* p01 = nhwc + (((size_t)b * 64 + cy0) * 64 + cx1) * 256;
        const float* p10 = nhwc + (((size_t)b * 64 + cy1) * 64 + cx0) * 256;
        const float* p11 = nhwc + (((size_t)b * 64 + cy1) * 64 + cx1) * 256;
        __nv_bfloat16* ch = colh + (size_t)n * KDIM + k * 256;
        __nv_bfloat16* cl = coll + (size_t)n * KDIM + k * 256;
#pragma unroll
        for (int it = 0; it < 8; it++) {
            int c = lane + it * 32;
            float v = w00 * p00[c] + w01 * p01[c] + w10 * p10[c] + w11 * p11[c];
            __nv_bfloat16 h = __float2bfloat16(v);
            ch[c] = h;
            cl[c] = __float2bfloat16(v - __bfloat162float(h));
        }
    }
}

// ---------------- rep-points epilogue ----------------
__global__ __launch_bounds__(256) void reppoints_k(const float* __restrict__ off1,
                                                   const float* __restrict__ off2,
                                                   float* __restrict__ out) {
    int idx = blockIdx.x * 256 + threadIdx.x;
    if (idx >= OFFN) return;
    int rem = idx % 73728;
    int ch = rem >> 12;
    int ij = rem & 4095;
    int i = ij >> 6, j = ij & 63;
    int k = ch >> 1;
    float init = (ch & 1) ? (float)(j + (k % 3) - 1) : (float)(i + (k / 3) - 1);
    float r1 = init + off1[idx];
    out[idx] = r1;
    out[OFFN + idx] = r1 + off2[idx];
}

// ---------------- host orchestration (2-stream overlap) ----------------
extern "C" void kernel_launch(void* const* d_in, const int* in_sizes, int n_in,
                              void* d_out, int out_size) {
    const float* feature = (const float*)d_in[0];
    const float* loc_ws  = (const float*)d_in[1];
    const float* loc_g   = (const float*)d_in[2];
    const float* loc_b   = (const float*)d_in[3];
    const float* cls_ws  = (const float*)d_in[4];
    const float* cls_g   = (const float*)d_in[5];
    const float* cls_b   = (const float*)d_in[6];
    const float* pi_w    = (const float*)d_in[7];
    const float* pio_w   = (const float*)d_in[8];
    const float* prd_w   = (const float*)d_in[9];
    const float* pro_w   = (const float*)d_in[10];
    const float* cd_w    = (const float*)d_in[11];
    const float* co_w    = (const float*)d_in[12];
    float* out = (float*)d_out;

    static int init_done = 0;
    static cudaStream_t s1, s2;
    static cudaEvent_t evRoot, evW, evF, evOff1, evE1, evE2;
    if (!init_done) {
        cudaFuncSetAttribute(gemm_big_k<0>, cudaFuncAttributeMaxDynamicSharedMemorySize, BIG2_SMEM);
        cudaFuncSetAttribute(gemm_big_k<1>, cudaFuncAttributeMaxDynamicSharedMemorySize, BIG2_SMEM);
        cudaFuncSetAttribute(gemm_conv_k<32, 256>, cudaFuncAttributeMaxDynamicSharedMemorySize, SMALL_SMEM);
        cudaFuncSetAttribute(gemm_col_k<0>, cudaFuncAttributeMaxDynamicSharedMemorySize, COL_SMEM);
        cudaFuncSetAttribute(gemm_col_k<1>, cudaFuncAttributeMaxDynamicSharedMemorySize, COL_SMEM);
        cudaStreamCreateWithFlags(&s1, cudaStreamNonBlocking);
        cudaStreamCreateWithFlags(&s2, cudaStreamNonBlocking);
        cudaEventCreateWithFlags(&evRoot, cudaEventDisableTiming);
        cudaEventCreateWithFlags(&evW, cudaEventDisableTiming);
        cudaEventCreateWithFlags(&evF, cudaEventDisableTiming);
        cudaEventCreateWithFlags(&evOff1, cudaEventDisableTiming);
        cudaEventCreateWithFlags(&evE1, cudaEventDisableTiming);
        cudaEventCreateWithFlags(&evE2, cudaEventDisableTiming);
        init_done = 1;
    }

    __nv_bfloat16 *wahi, *walo, *fhi, *flo;
    __nv_bfloat16 *t1hi, *t1lo, *u1hi, *u1lo, *col1h, *col1l, *t2hi, *t2lo, *col2h, *col2l;
    float *buf1, *buf2, *nh1, *nh2, *off1, *off2, *ws1, *ws2;
    cudaGetSymbolAddress((void**)&wahi,  g_wahi);
    cudaGetSymbolAddress((void**)&walo,  g_walo);
    cudaGetSymbolAddress((void**)&fhi,   g_fhi);
    cudaGetSymbolAddress((void**)&flo,   g_flo);
    cudaGetSymbolAddress((void**)&t1hi,  g_t1hi);
    cudaGetSymbolAddress((void**)&t1lo,  g_t1lo);
    cudaGetSymbolAddress((void**)&u1hi,  g_u1hi);
    cudaGetSymbolAddress((void**)&u1lo,  g_u1lo);
    cudaGetSymbolAddress((void**)&col1h, g_col1h);
    cudaGetSymbolAddress((void**)&col1l, g_col1l);
    cudaGetSymbolAddress((void**)&t2hi,  g_t2hi);
    cudaGetSymbolAddress((void**)&t2lo,  g_t2lo);
    cudaGetSymbolAddress((void**)&col2h, g_col2h);
    cudaGetSymbolAddress((void**)&col2l, g_col2l);
    cudaGetSymbolAddress((void**)&buf1,  g_buf1);
    cudaGetSymbolAddress((void**)&buf2,  g_buf2);
    cudaGetSymbolAddress((void**)&nh1,   g_nh1);
    cudaGetSymbolAddress((void**)&nh2,   g_nh2);
    cudaGetSymbolAddress((void**)&off1,  g_off1);
    cudaGetSymbolAddress((void**)&off2,  g_off2);
    cudaGetSymbolAddress((void**)&ws1,   g_ws1);
    cudaGetSymbolAddress((void**)&ws2,   g_ws2);

    W12 w12;
    w12.p[0] = loc_ws;           w12.m[0] = 256;
    w12.p[1] = loc_ws + WSZ;     w12.m[1] = 256;
    w12.p[2] = loc_ws + 2 * WSZ; w12.m[2] = 256;
    w12.p[3] = cls_ws;           w12.m[3] = 256;
    w12.p[4] = cls_ws + WSZ;     w12.m[4] = 256;
    w12.p[5] = cls_ws + 2 * WSZ; w12.m[5] = 256;
    w12.p[6] = pi_w;             w12.m[6] = 256;
    w12.p[7] = pio_w;            w12.m[7] = 18;
    w12.p[8] = prd_w;            w12.m[8] = 256;
    w12.p[9] = pro_w;            w12.m[9] = 18;
    w12.p[10] = cd_w;            w12.m[10] = 256;
    w12.p[11] = co_w;            w12.m[11] = 15;

    dim3 tgrid(128, 8, 4), tblk(32, 8);
    dim3 gBig2(128, 2), gSmall(64, 1), gCol(64, 2);

    cudaEventRecord(evRoot, 0);
    cudaStreamWaitEvent(s1, evRoot, 0);
    cudaStreamWaitEvent(s2, evRoot, 0);

    wconv_all_k<<<768, 256, 0, s1>>>(w12, wahi, walo);
    cudaEventRecord(evW, s1);
    tsplit_k<<<tgrid, tblk, 0, s2>>>(feature, fhi, flo, nullptr, nullptr, nullptr, nullptr);
    cudaEventRecord(evF, s2);
    cudaStreamWaitEvent(s1, evF, 0);
    cudaStreamWaitEvent(s2, evW, 0);

    // ---- s1: loc subnet -> offset1 -> offset2 branch -> reppoints ----
    for (int l = 0; l < 3; l++) {
        gemm_big_k<0><<<gBig2, 256, BIG2_SMEM, s1>>>(
            wahi + (size_t)l * PL, walo + (size_t)l * PL,
            l == 0 ? fhi : t1hi, l == 0 ? flo : t1lo, buf1, nullptr, nullptr, 256, 256 * 4096);
        gnstat_k<<<128, 256, 0, s1>>>(buf1, ws1);
        tsplit_k<<<tgrid, tblk, 0, s1>>>(buf1, t1hi, t1lo, l == 2 ? nh1 : nullptr,
                                         ws1, loc_g + l * 256, loc_b + l * 256);
    }
    gemm_big_k<1><<<gBig2, 256, BIG2_SMEM, s1>>>(
        wahi + 6 * (size_t)PL, walo + 6 * (size_t)PL, t1hi, t1lo,
        nullptr, u1hi, u1lo, 256, 0);
    gemm_conv_k<32, 256><<<gSmall, 256, SMALL_SMEM, s1>>>(
        wahi + 7 * (size_t)PL, walo + 7 * (size_t)PL, u1hi, u1lo,
        off1, 18, 18 * 4096);
    cudaEventRecord(evOff1, s1);

    deform_col_k<<<2048, 256, 0, s1>>>(nh1, off1, col1h, col1l);
    gemm_col_k<1><<<gCol, 512, COL_SMEM, s1>>>(
        wahi + 8 * (size_t)PL, walo + 8 * (size_t)PL, col1h, col1l,
        nullptr, t1hi, t1lo, 256, 0);
    gemm_conv_k<32, 256><<<gSmall, 256, SMALL_SMEM, s1>>>(
        wahi + 9 * (size_t)PL, walo + 9 * (size_t)PL, t1hi, t1lo,
        off2, 18, 18 * 4096);
    reppoints_k<<<(OFFN + 255) / 256, 256, 0, s1>>>(off1, off2, out);
    cudaEventRecord(evE1, s1);

    // ---- s2: cls subnet -> classification branch ----
    for (int l = 0; l < 3; l++) {
        gemm_big_k<0><<<gBig2, 256, BIG2_SMEM, s2>>>(
            wahi + (size_t)(3 + l) * PL, walo + (size_t)(3 + l) * PL,
            l == 0 ? fhi : t2hi, l == 0 ? flo : t2lo, buf2, nullptr, nullptr, 256, 256 * 4096);
        gnstat_k<<<128, 256, 0, s2>>>(buf2, ws2);
        tsplit_k<<<tgrid, tblk, 0, s2>>>(buf2, l == 2 ? nullptr : t2hi, l == 2 ? nullptr : t2lo,
                                         l == 2 ? nh2 : nullptr,
                                         ws2, cls_g + l * 256, cls_b + l * 256);
    }
    cudaStreamWaitEvent(s2, evOff1, 0);
    deform_col_k<<<2048, 256, 0, s2>>>(nh2, off1, col2h, col2l);
    gemm_col_k<1><<<gCol, 512, COL_SMEM, s2>>>(
        wahi + 10 * (size_t)PL, walo + 10 * (size_t)PL, col2h, col2l,
        nullptr, t2hi, t2lo, 256, 0);
    gemm_conv_k<32, 256><<<gSmall, 256, SMALL_SMEM, s2>>>(
        wahi + 11 * (size_t)PL, walo + 11 * (size_t)PL, t2hi, t2lo,
        out + 2 * OFFN, 15, 15 * 4096);
    cudaEventRecord(evE2, s2);

    cudaStreamWaitEvent(0, evE1, 0);
    cudaStreamWaitEvent(0, evE2, 0);
}

// round 16
// speedup vs baseline: 1.6681x; 1.0015x over previous
#include <cuda_runtime.h>
#include <cuda_bf16.h>
#include <cstdint>
#include <math.h>

#define NG 16384
#define OFFN (18*16384)
#define KDIM 2304
#define WSZ (256*256*9)
#define PL 589824
#define COL_SMEM 197632
#define SPL2 16896           // slab plane: 264 pix * 64B (4 rows x 66)
#define BIG2_SMEM 101376     // 2*16KB A + 2*2*SPL2 slab + pad
#define SPL 25344            // small-kernel slab plane: 396 pix * 64B
#define SMALL_SMEM 110592

// ---------------- scratch ----------------
__device__ __nv_bfloat16 g_wahi[(size_t)12*PL];
__device__ __nv_bfloat16 g_walo[(size_t)12*PL];
__device__ __nv_bfloat16 g_fhi[(size_t)NG*256];
__device__ __nv_bfloat16 g_flo[(size_t)NG*256];
__device__ __nv_bfloat16 g_t1hi[(size_t)NG*256];
__device__ __nv_bfloat16 g_t1lo[(size_t)NG*256];
__device__ __nv_bfloat16 g_u1hi[(size_t)NG*256];
__device__ __nv_bfloat16 g_u1lo[(size_t)NG*256];
__device__ float g_buf1[(size_t)NG*256];
__device__ float g_nh1[(size_t)NG*256];
__device__ __nv_bfloat16 g_col1h[(size_t)NG*KDIM];
__device__ __nv_bfloat16 g_col1l[(size_t)NG*KDIM];
__device__ float g_ws1[256];
__device__ __nv_bfloat16 g_t2hi[(size_t)NG*256];
__device__ __nv_bfloat16 g_t2lo[(size_t)NG*256];
__device__ float g_buf2[(size_t)NG*256];
__device__ float g_nh2[(size_t)NG*256];
__device__ __nv_bfloat16 g_col2h[(size_t)NG*KDIM];
__device__ __nv_bfloat16 g_col2l[(size_t)NG*KDIM];
__device__ float g_ws2[256];
__device__ float g_off1[OFFN];
__device__ float g_off2[OFFN];

// ---------------- PTX helpers ----------------
__device__ __forceinline__ uint32_t smem_u32(const void* p) {
    uint32_t a;
    asm("{ .reg .u64 t; cvta.to.shared.u64 t, %1; cvt.u32.u64 %0, t; }" : "=r"(a) : "l"(p));
    return a;
}
#define SWZ(o)   ((o) ^ (((o) >> 3) & 0x70))
#define SWZ64(o) ((o) ^ (((o) >> 3) & 0x30))

__device__ __forceinline__ void cp16(uint32_t dst, const void* src, int ss) {
    asm volatile("cp.async.cg.shared.global [%0], [%1], 16, %2;\n" :: "r"(dst), "l"(src), "r"(ss));
}
__device__ __forceinline__ void cp_commit() { asm volatile("cp.async.commit_group;\n" ::: "memory"); }
__device__ __forceinline__ void cp_wait0()  { asm volatile("cp.async.wait_group 0;\n" ::: "memory"); }
__device__ __forceinline__ void cp_wait1()  { asm volatile("cp.async.wait_group 1;\n" ::: "memory"); }

__device__ __forceinline__ void ldm4(uint32_t* r, uint32_t addr) {
    asm volatile("ldmatrix.sync.aligned.m8n8.x4.shared.b16 {%0,%1,%2,%3}, [%4];"
        : "=r"(r[0]), "=r"(r[1]), "=r"(r[2]), "=r"(r[3]) : "r"(addr));
}
__device__ __forceinline__ void mma16816(float* d, const uint32_t* a, const uint32_t* b) {
    asm volatile("mma.sync.aligned.m16n8k16.row.col.f32.bf16.bf16.f32 "
        "{%0,%1,%2,%3}, {%4,%5,%6,%7}, {%8,%9}, {%0,%1,%2,%3};"
        : "+f"(d[0]), "+f"(d[1]), "+f"(d[2]), "+f"(d[3])
        : "r"(a[0]), "r"(a[1]), "r"(a[2]), "r"(a[3]), "r"(b[0]), "r"(b[1]));
}
__device__ __forceinline__ unsigned short bfbits(float x) {
    __nv_bfloat16 h = __float2bfloat16(x);
    return *reinterpret_cast<unsigned short*>(&h);
}

// ---------------- epilogues ----------------
template<int IM>
__device__ __forceinline__ void epilogue_nchw(float acc[IM][4][4], float* out, int bstride,
                                              int M, int m0, int n0, int wm, int wn, int lane) {
    int b = n0 >> 12, ij0 = n0 & 4095;
    float* outb = out + (size_t)b * bstride + ij0;
#pragma unroll
    for (int im = 0; im < IM; im++) {
        int mrow = m0 + wm + im * 16 + (lane >> 2);
#pragma unroll
        for (int jn = 0; jn < 4; jn++) {
            int ncol = wn + jn * 8 + (lane & 3) * 2;
            if (mrow < M) {
                float2 v = make_float2(acc[im][jn][0], acc[im][jn][1]);
                *(float2*)(outb + (size_t)mrow * 4096 + ncol) = v;
            }
            if (mrow + 8 < M) {
                float2 v = make_float2(acc[im][jn][2], acc[im][jn][3]);
                *(float2*)(outb + (size_t)(mrow + 8) * 4096 + ncol) = v;
            }
        }
    }
}

// 256-thread CTA, 8 warps, IM=4, tile 128m x 128n -> NHWC hi/lo planes.
__device__ __forceinline__ void epilogue_split128(float acc[4][4][4],
                                                  __nv_bfloat16* ohi, __nv_bfloat16* olo,
                                                  float* smemf, int m0, int n0,
                                                  int tid, int wid, int wm, int wn, int lane) {
    for (int ch = 0; ch < 4; ch++) {
        __syncthreads();
        if ((wid & 3) == ch) {
#pragma unroll
            for (int im = 0; im < 4; im++) {
                int m = wm + im * 16 + (lane >> 2);
#pragma unroll
                for (int jn = 0; jn < 4; jn++) {
                    int nl = jn * 8 + (lane & 3) * 2;
                    smemf[m * 33 + nl] = acc[im][jn][0];
                    smemf[m * 33 + nl + 1] = acc[im][jn][1];
                    smemf[(m + 8) * 33 + nl] = acc[im][jn][2];
                    smemf[(m + 8) * 33 + nl + 1] = acc[im][jn][3];
                }
            }
        }
        __syncthreads();
#pragma unroll
        for (int it2 = 0; it2 < 2; it2++) {
            int item = tid + it2 * 256;
            int p = item >> 4;            // 0..31 pixel in chunk
            int cq = (item & 15) * 8;     // 8 channels
            size_t base = (size_t)(n0 + ch * 32 + p) * 256 + m0 + cq;
            uint32_t hw[4], lw[4];
#pragma unroll
            for (int i = 0; i < 4; i++) {
                float v0 = smemf[(cq + 2 * i) * 33 + p];
                float v1 = smemf[(cq + 2 * i + 1) * 33 + p];
                unsigned short h0 = bfbits(v0), h1 = bfbits(v1);
                float r0 = v0 - __bfloat162float(*reinterpret_cast<__nv_bfloat16*>(&h0));
                float r1 = v1 - __bfloat162float(*reinterpret_cast<__nv_bfloat16*>(&h1));
                hw[i] = (uint32_t)h0 | ((uint32_t)h1 << 16);
                lw[i] = (uint32_t)bfbits(r0) | ((uint32_t)bfbits(r1) << 16);
            }
            *(uint4*)(ohi + base) = make_uint4(hw[0], hw[1], hw[2], hw[3]);
            *(uint4*)(olo + base) = make_uint4(lw[0], lw[1], lw[2], lw[3]);
        }
    }
}

// 512-thread version (col GEMM split epilogue, 256-n tile) — unchanged from R9.
__device__ __forceinline__ void epilogue_split(float acc[4][4][4],
                                               __nv_bfloat16* ohi, __nv_bfloat16* olo,
                                               float* smemf, int m0, int n0,
                                               int tid, int wid, int wm, int wn, int lane) {
    for (int ch = 0; ch < 8; ch++) {
        __syncthreads();
        if ((wid & 7) == ch) {
#pragma unroll
            for (int im = 0; im < 4; im++) {
                int m = wm + im * 16 + (lane >> 2);
#pragma unroll
                for (int jn = 0; jn < 4; jn++) {
                    int nl = jn * 8 + (lane & 3) * 2;
                    smemf[m * 33 + nl] = acc[im][jn][0];
                    smemf[m * 33 + nl + 1] = acc[im][jn][1];
                    smemf[(m + 8) * 33 + nl] = acc[im][jn][2];
                    smemf[(m + 8) * 33 + nl + 1] = acc[im][jn][3];
                }
            }
        }
        __syncthreads();
        int p = tid >> 4;
        int cq = (tid & 15) * 8;
        size_t base = (size_t)(n0 + ch * 32 + p) * 256 + m0 + cq;
        uint32_t hw[4], lw[4];
#pragma unroll
        for (int i = 0; i < 4; i++) {
            float v0 = smemf[(cq + 2 * i) * 33 + p];
            float v1 = smemf[(cq + 2 * i + 1) * 33 + p];
            unsigned short h0 = bfbits(v0), h1 = bfbits(v1);
            float r0 = v0 - __bfloat162float(*reinterpret_cast<__nv_bfloat16*>(&h0));
            float r1 = v1 - __bfloat162float(*reinterpret_cast<__nv_bfloat16*>(&h1));
            hw[i] = (uint32_t)h0 | ((uint32_t)h1 << 16);
            lw[i] = (uint32_t)bfbits(r0) | ((uint32_t)bfbits(r1) << 16);
        }
        *(uint4*)(ohi + base) = make_uint4(hw[0], hw[1], hw[2], hw[3]);
        *(uint4*)(olo + base) = make_uint4(lw[0], lw[1], lw[2], lw[3]);
    }
}

// ---------------- all-weights convert ----------------
struct W12 { const float* p[12]; int m[12]; };
__global__ __launch_bounds__(256) void wconv_all_k(W12 w,
                                                   __nv_bfloat16* __restrict__ hi,
                                                   __nv_bfloat16* __restrict__ lo) {
    __shared__ float rows[4][KDIM];
    int t = blockIdx.x >> 6;
    int rb = blockIdx.x & 63;
    int tid = threadIdx.x;
    int m0 = rb * 4;
    const float* src = w.p[t];
    int Mv = w.m[t];
    for (int i = tid; i < 4 * KDIM; i += 256) {
        int r = i / KDIM, k = i - r * KDIM;
        int m = m0 + r;
        rows[r][k] = (m < Mv) ? src[(size_t)m * KDIM + k] : 0.f;
    }
    __syncthreads();
    for (int i = tid; i < 4 * KDIM; i += 256) {
        int r = i / KDIM, k = i - r * KDIM;
        int kk = k >> 8, c = k & 255;
        float v = rows[r][c * 9 + kk];
        size_t dst = (size_t)t * PL + (size_t)(m0 + r) * KDIM + k;
        __nv_bfloat16 h = __float2bfloat16(v);
        hi[dst] = h;
        lo[dst] = __float2bfloat16(v - __bfloat162float(h));
    }
}

// ---------------- GN stats ----------------
__global__ __launch_bounds__(256) void gnstat_k(const float* __restrict__ in,
                                                float* __restrict__ ws) {
    int bg = blockIdx.x;
    int b = bg >> 5, g = bg & 31;
    int tid = threadIdx.x;
    const float4* p = (const float4*)(in + ((size_t)b * 256 + g * 8) * 4096);
    float s = 0.f, s2 = 0.f;
    for (int i = tid; i < 8192; i += 256) {
        float4 v = p[i];
        s += v.x + v.y + v.z + v.w;
        s2 += v.x * v.x + v.y * v.y + v.z * v.z + v.w * v.w;
    }
    __shared__ float sA[256], sB[256];
    sA[tid] = s; sB[tid] = s2;
    __syncthreads();
    for (int st = 128; st > 0; st >>= 1) {
        if (tid < st) { sA[tid] += sA[tid + st]; sB[tid] += sB[tid + st]; }
        __syncthreads();
    }
    if (tid == 0) {
        float mean = sA[0] * (1.f / 32768.f);
        float var = sB[0] * (1.f / 32768.f) - mean * mean;
        ws[bg * 2] = mean;
        ws[bg * 2 + 1] = rsqrtf(var + 1e-5f);
    }
}

// ---------------- NCHW fp32 -> (GN affine) -> NHWC hi/lo bf16 (+fp32) ----------------
__global__ void tsplit_k(const float* __restrict__ in,
                         __nv_bfloat16* __restrict__ hi, __nv_bfloat16* __restrict__ lo,
                         float* __restrict__ f32o,
                         const float* __restrict__ ws,
                         const float* __restrict__ gamma, const float* __restrict__ beta) {
    __shared__ float t[32][33];
    int b = blockIdx.z, hw0 = blockIdx.x * 32, c0 = blockIdx.y * 32;
    int tx = threadIdx.x, ty = threadIdx.y;
    const float* ip = in + (size_t)b * 256 * 4096;
    for (int r = ty; r < 32; r += 8)
        t[r][tx] = ip[(size_t)(c0 + r) * 4096 + hw0 + tx];
    __syncthreads();
    int ch = c0 + tx;
    float sc = 1.f, sh = 0.f;
    if (ws) {
        int bg = b * 32 + (ch >> 3);
        float mean = ws[bg * 2], rstd = ws[bg * 2 + 1];
        sc = rstd * gamma[ch];
        sh = beta[ch] - mean * sc;
    }
    for (int r = ty; r < 32; r += 8) {
        float v = t[tx][r] * sc + sh;
        size_t idx = (size_t)b * 4096 * 256 + (size_t)(hw0 + r) * 256 + ch;
        if (hi) {
            __nv_bfloat16 h = __float2bfloat16(v);
            hi[idx] = h;
            lo[idx] = __float2bfloat16(v - __bfloat162float(h));
        }
        if (f32o) f32o[idx] = v;
    }
}

// ---------------- big implicit-conv GEMM: 128M x 128N, 256 thr, 2 CTA/SM ----------------
template<int EPI>
__global__ __launch_bounds__(256, 2) void gemm_big_k(
    const __nv_bfloat16* __restrict__ Ahi, const __nv_bfloat16* __restrict__ Alo,
    const __nv_bfloat16* __restrict__ Bhi, const __nv_bfloat16* __restrict__ Blo,
    float* __restrict__ out, __nv_bfloat16* __restrict__ ohi, __nv_bfloat16* __restrict__ olo,
    int M, int bstride) {
    constexpr int APL = 8192;       // A plane: 128 rows * 64B
    constexpr int AST = 2 * APL;
    constexpr int SST = 2 * SPL2;

    extern __shared__ char smx[];
    uint32_t smb = (smem_u32(smx) + 1023) & ~1023u;
    uint32_t aB = smb, sB = smb + 2 * AST;

    int tid = threadIdx.x;
    int lane = tid & 31;
    int wid = tid >> 5;
    int wm = (wid >> 2) * 64;
    int wn = (wid & 3) * 32;
    int n0 = blockIdx.x * 128;
    int m0 = blockIdx.y * 128;
    int b = n0 >> 12, ij0 = n0 & 4095;
    int i0 = ij0 >> 6;

    auto load_A = [&](int t, uint32_t dst) {
        int cg = t / 9, tap = t - cg * 9;
        int koff = tap * 256 + cg * 32;
#pragma unroll
        for (int idx = tid; idx < 1024; idx += 256) {
            int plane = idx >= 512;
            int q = idx - plane * 512;
            int row = q >> 2, c16 = q & 3;
            const __nv_bfloat16* src =
                (plane ? Alo : Ahi) + (size_t)(m0 + row) * KDIM + koff + c16 * 8;
            cp16(dst + plane * APL + SWZ64(row * 64 + c16 * 16), src, 16);
        }
    };
    // slab: 264 pixels (4 rows x 66) * 4 chunks = 1056 per plane, 2112 total
    auto load_slab = [&](int cg, uint32_t dst) {
        for (int idx = tid; idx < 2112; idx += 256) {
            int plane = idx >= 1056;
            int q = idx - plane * 1056;
            int pix = q >> 2, c16 = q & 3;
            int sy = pix / 66, sx = pix - sy * 66;
            int y = i0 - 1 + sy, x = sx - 1;
            bool v = ((unsigned)y < 64u) && ((unsigned)x < 64u);
            int yy = v ? y : 0, xx = v ? x : 0;
            const __nv_bfloat16* src = (plane ? Blo : Bhi) +
                ((((size_t)b * 64 + yy) * 64 + xx) << 8) + cg * 32 + c16 * 8;
            cp16(dst + plane * SPL2 + SWZ64(pix * 64 + c16 * 16), src, v ? 16 : 0);
        }
    };

    float acc[4][4][4];
#pragma unroll
    for (int im = 0; im < 4; im++)
#pragma unroll
        for (int jn = 0; jn < 4; jn++)
#pragma unroll
            for (int q = 0; q < 4; q++) acc[im][jn][q] = 0.f;

    int arow = lane & 15;
    int abyte = (lane >> 4) * 16;
    int mi = lane >> 3;
    int brow_off = (mi >> 1) * 8 + (lane & 7);
    int bbyte = (mi & 1) * 16;
    int b66[2];
#pragma unroll
    for (int jp = 0; jp < 2; jp++) {
        int rowb = wn + jp * 16 + brow_off;
        b66[jp] = (rowb >> 6) * 66 + (rowb & 63);
    }

    load_slab(0, sB);
    load_A(0, aB);
    cp_commit();

    for (int t = 0; t < 72; t++) {
        int cg = t / 9, tap = t - cg * 9;
        if (t + 1 < 72) {
            load_A(t + 1, aB + ((t + 1) & 1) * AST);
            if (tap == 4 && cg < 7) load_slab(cg + 1, sB + ((cg + 1) & 1) * SST);
            cp_commit();
            cp_wait1();
        } else {
            cp_wait0();
        }
        __syncthreads();

        uint32_t ab = aB + (t & 1) * AST;
        uint32_t sb = sB + (cg & 1) * SST;
        int kd = (tap * 11) >> 5;
        int tapoff = kd * 66 + (tap - kd * 3);
#pragma unroll
        for (int s = 0; s < 2; s++) {
            uint32_t bh[4][2], bl[4][2];
#pragma unroll
            for (int jp = 0; jp < 2; jp++) {
                int pix = b66[jp] + tapoff;
                uint32_t off = SWZ64(pix * 64 + s * 32 + bbyte);
                uint32_t r4[4];
                ldm4(r4, sb + off);
                bh[jp * 2][0] = r4[0]; bh[jp * 2][1] = r4[1];
                bh[jp * 2 + 1][0] = r4[2]; bh[jp * 2 + 1][1] = r4[3];
                ldm4(r4, sb + SPL2 + off);
                bl[jp * 2][0] = r4[0]; bl[jp * 2][1] = r4[1];
                bl[jp * 2 + 1][0] = r4[2]; bl[jp * 2 + 1][1] = r4[3];
            }
#pragma unroll
            for (int im = 0; im < 4; im++) {
                int rowa = wm + im * 16 + arow;
                uint32_t offa = SWZ64(rowa * 64 + s * 32 + abyte);
                uint32_t ah[4], al[4];
                ldm4(ah, ab + offa);
                ldm4(al, ab + APL + offa);
#pragma unroll
                for (int jn = 0; jn < 4; jn++) {
                    mma16816(acc[im][jn], ah, bh[jn]);
                    mma16816(acc[im][jn], ah, bl[jn]);
                    mma16816(acc[im][jn], al, bh[jn]);
                }
            }
        }
        __syncthreads();
    }

    if (EPI == 0) {
        epilogue_nchw<4>(acc, out, bstride, M, m0, n0, wm, wn, lane);
    } else {
        epilogue_split128(acc, ohi, olo, (float*)smx, m0, n0, tid, wid, wm, wn, lane);
    }
}

// ---------------- small implicit-conv GEMM (M=18/15): R9 template path ----------------
template<int MROWS, int NTHREADS>
__global__ __launch_bounds__(NTHREADS, 1) void gemm_conv_k(
    const __nv_bfloat16* __restrict__ Ahi, const __nv_bfloat16* __restrict__ Alo,
    const __nv_bfloat16* __restrict__ Bhi, const __nv_bfloat16* __restrict__ Blo,
    float* __restrict__ out, int M, int bstride) {
    constexpr int MW = NTHREADS / 256;
    constexpr int IM = MROWS / (MW * 16);
    constexpr int APL = MROWS * 64;
    constexpr int AST = 2 * APL;
    constexpr int SST = 2 * SPL;

    extern __shared__ char smx[];
    uint32_t smb = (smem_u32(smx) + 1023) & ~1023u;
    uint32_t aB = smb, sB = smb + 2 * AST;

    int tid = threadIdx.x;
    int lane = tid & 31;
    int wid = tid >> 5;
    int wm = (wid >> 3) * (IM * 16);
    int wn = (wid & 7) * 32;
    int n0 = blockIdx.x * 256;
    int m0 = blockIdx.y * MROWS;
    int b = n0 >> 12, ij0 = n0 & 4095;
    int i0 = ij0 >> 6;

    auto load_A = [&](int t, uint32_t dst) {
        int cg = t / 9, tap = t - cg * 9;
        int koff = tap * 256 + cg * 32;
#pragma unroll
        for (int idx = tid; idx < MROWS * 8; idx += NTHREADS) {
            int plane = idx >= MROWS * 4;
            int q = idx - plane * (MROWS * 4);
            int row = q >> 2, c16 = q & 3;
            const __nv_bfloat16* src =
                (plane ? Alo : Ahi) + (size_t)(m0 + row) * KDIM + koff + c16 * 8;
            cp16(dst + plane * APL + SWZ64(row * 64 + c16 * 16), src, 16);
        }
    };
    auto load_slab = [&](int cg, uint32_t dst) {
        for (int idx = tid; idx < 3168; idx += NTHREADS) {
            int plane = idx >= 1584;
            int q = idx - plane * 1584;
            int pix = q >> 2, c16 = q & 3;
            int sy = pix / 66, sx = pix - sy * 66;
            int y = i0 - 1 + sy, x = sx - 1;
            bool v = ((unsigned)y < 64u) && ((unsigned)x < 64u);
            int yy = v ? y : 0, xx = v ? x : 0;
            const __nv_bfloat16* src = (plane ? Blo : Bhi) +
                ((((size_t)b * 64 + yy) * 64 + xx) << 8) + cg * 32 + c16 * 8;
            cp16(dst + plane * SPL + SWZ64(pix * 64 + c16 * 16), src, v ? 16 : 0);
        }
    };

    float acc[IM][4][4];
#pragma unroll
    for (int im = 0; im < IM; im++)
#pragma unroll
        for (int jn = 0; jn < 4; jn++)
#pragma unroll
            for (int q = 0; q < 4; q++) acc[im][jn][q] = 0.f;

    int arow = lane & 15;
    int abyte = (lane >> 4) * 16;
    int mi = lane >> 3;
    int brow_off = (mi >> 1) * 8 + (lane & 7);
    int bbyte = (mi & 1) * 16;
    int b66[2];
#pragma unroll
    for (int jp = 0; jp < 2; jp++) {
        int rowb = wn + jp * 16 + brow_off;
        b66[jp] = (rowb >> 6) * 66 + (rowb & 63);
    }

    load_slab(0, sB);
    load_A(0, aB);
    cp_commit();

    for (int t = 0; t < 72; t++) {
        int cg = t / 9, tap = t - cg * 9;
        if (t + 1 < 72) {
            load_A(t + 1, aB + ((t + 1) & 1) * AST);
            if (tap == 4 && cg < 7) load_slab(cg + 1, sB + ((cg + 1) & 1) * SST);
            cp_commit();
            cp_wait1();
        } else {
            cp_wait0();
        }
        __syncthreads();

        uint32_t ab = aB + (t & 1) * AST;
        uint32_t sb = sB + (cg & 1) * SST;
        int kd = (tap * 11) >> 5;
        int tapoff = kd * 66 + (tap - kd * 3);
#pragma unroll
        for (int s = 0; s < 2; s++) {
            uint32_t bh[4][2], bl[4][2];
#pragma unroll
            for (int jp = 0; jp < 2; jp++) {
                int pix = b66[jp] + tapoff;
                uint32_t off = SWZ64(pix * 64 + s * 32 + bbyte);
                uint32_t r4[4];
                ldm4(r4, sb + off);
                bh[jp * 2][0] = r4[0]; bh[jp * 2][1] = r4[1];
                bh[jp * 2 + 1][0] = r4[2]; bh[jp * 2 + 1][1] = r4[3];
                ldm4(r4, sb + SPL + off);
                bl[jp * 2][0] = r4[0]; bl[jp * 2][1] = r4[1];
                bl[jp * 2 + 1][0] = r4[2]; bl[jp * 2 + 1][1] = r4[3];
            }
#pragma unroll
            for (int im = 0; im < IM; im++) {
                int rowa = wm + im * 16 + arow;
                uint32_t offa = SWZ64(rowa * 64 + s * 32 + abyte);
                uint32_t ah[4], al[4];
                ldm4(ah, ab + offa);
                ldm4(al, ab + APL + offa);
#pragma unroll
                for (int jn = 0; jn < 4; jn++) {
                    mma16816(acc[im][jn], ah, bh[jn]);
                    mma16816(acc[im][jn], ah, bl[jn]);
                    mma16816(acc[im][jn], al, bh[jn]);
                }
            }
        }
        __syncthreads();
    }

    epilogue_nchw<IM>(acc, out, bstride, M, m0, n0, wm, wn, lane);
}

// ---------------- col-based GEMM for deform convs (R9, unchanged) ----------------
template<int EPI>
__global__ __launch_bounds__(512, 1) void gemm_col_k(const __nv_bfloat16* __restrict__ Ahi,
                                                     const __nv_bfloat16* __restrict__ Alo,
                                                     const __nv_bfloat16* __restrict__ Bhi,
                                                     const __nv_bfloat16* __restrict__ Blo,
                                                     float* __restrict__ out,
                                                     __nv_bfloat16* __restrict__ ohi,
                                                     __nv_bfloat16* __restrict__ olo,
                                                     int M, int bstride) {
    extern __shared__ char smx[];
    uint32_t smb = (smem_u32(smx) + 1023) & ~1023u;
    int tid = threadIdx.x;
    int lane = tid & 31;
    int wid = tid >> 5;
    int wm = (wid >> 3) * 64;
    int wn = (wid & 7) * 32;
    int n0 = blockIdx.x * 256;
    int m0 = blockIdx.y * 128;

    auto load_stage = [&](int t, uint32_t sb) {
        int kk = t >> 2, cg = t & 3;
        int koff = kk * 256 + cg * 64;
#pragma unroll
        for (int qi = 0; qi < 12; qi++) {
            int q = qi * 512 + tid;
            if (qi < 4) {
                int plane = (q >> 10) & 1;
                int qq = q & 1023;
                int row = qq >> 3, c16 = qq & 7;
                const __nv_bfloat16* src =
                    (plane ? Alo : Ahi) + (size_t)(m0 + row) * KDIM + koff + c16 * 8;
                cp16(sb + plane * 16384 + SWZ(row * 128 + c16 * 16), src, 16);
            } else {
                int qb = q - 2048;
                int plane = qb >> 11;
                int qq = qb & 2047;
                int row = qq >> 3, c16 = qq & 7;
                const __nv_bfloat16* src =
                    (plane ? Blo : Bhi) + (size_t)(n0 + row) * KDIM + koff + c16 * 8;
                cp16(sb + 32768 + plane * 32768 + SWZ(row * 128 + c16 * 16), src, 16);
            }
        }
    };

    float acc[4][4][4];
#pragma unroll
    for (int im = 0; im < 4; im++)
#pragma unroll
        for (int jn = 0; jn < 4; jn++)
#pragma unroll
            for (int q = 0; q < 4; q++) acc[im][jn][q] = 0.f;

    load_stage(0, smb);
    cp_commit();

    int arow_off = (lane & 15);
    int abyte = (lane >> 4) * 16;
    int mi = lane >> 3;
    int brow_off = (mi >> 1) * 8 + (lane & 7);
    int bbyte = (mi & 1) * 16;

    for (int t = 0; t < 36; t++) {
        if (t + 1 < 36) {
            load_stage(t + 1, smb + ((t + 1) & 1) * 98304);
            cp_commit();
            cp_wait1();
        } else {
            cp_wait0();
        }
        __syncthreads();

        uint32_t sb = smb + (t & 1) * 98304;
        uint32_t ahB = sb, alB = sb + 16384, bhB = sb + 32768, blB = sb + 65536;
#pragma unroll
        for (int s = 0; s < 4; s++) {
            uint32_t bh[4][2], bl[4][2];
#pragma unroll
            for (int jp = 0; jp < 2; jp++) {
                int rowb = wn + jp * 16 + brow_off;
                uint32_t off = SWZ(rowb * 128 + s * 32 + bbyte);
                uint32_t r4[4];
                ldm4(r4, bhB + off);
                bh[jp * 2][0] = r4[0]; bh[jp * 2][1] = r4[1];
                bh[jp * 2 + 1][0] = r4[2]; bh[jp * 2 + 1][1] = r4[3];
                ldm4(r4, blB + off);
                bl[jp * 2][0] = r4[0]; bl[jp * 2][1] = r4[1];
                bl[jp * 2 + 1][0] = r4[2]; bl[jp * 2 + 1][1] = r4[3];
            }
#pragma unroll
            for (int im = 0; im < 4; im++) {
                int rowa = wm + im * 16 + arow_off;
                uint32_t off = SWZ(rowa * 128 + s * 32 + abyte);
                uint32_t ah[4], al[4];
                ldm4(ah, ahB + off);
                ldm4(al, alB + off);
#pragma unroll
                for (int jn = 0; jn < 4; jn++) {
                    mma16816(acc[im][jn], ah, bh[jn]);
                    mma16816(acc[im][jn], ah, bl[jn]);
                    mma16816(acc[im][jn], al, bh[jn]);
                }
            }
        }
        __syncthreads();
    }

    if (EPI == 0) {
        epilogue_nchw<4>(acc, out, bstride, M, m0, n0, wm, wn, lane);
    } else {
        epilogue_split(acc, ohi, olo, (float*)smx, m0, n0, tid, wid, wm, wn, lane);
    }
}

// ---------------- deformable bilinear gather -> bf16 hi/lo col planes ----------------
__global__ __launch_bounds__(256) void deform_col_k(const float* __restrict__ nhwc,
                                                    const float* __restrict__ off,
                                                    __nv_bfloat16* __restrict__ colh,
                                                    __nv_bfloat16* __restrict__ coll) {
    int warp = (blockIdx.x * 256 + threadIdx.x) >> 5;
    int lane = threadIdx.x & 31;
    if (warp >= NG) return;
    int n = warp;
    int b = n >> 12, ij = n & 4095, i = ij >> 6, j = ij & 63;
    const float* offb = off + (size_t)b * 18 * 4096 + ij;
#pragma unroll
    for (int k = 0; k < 9; k++) {
        float dy = offb[(size_t)(2 * k) << 12];
        float dx = offb[(size_t)(2 * k + 1) << 12];
        float y = dy + (float)(i - 1 + k / 3);
        float x = dx + (float)(j - 1 + k % 3);
        float y0f = floorf(y), x0f = floorf(x);
        int y0 = (int)y0f, x0 = (int)x0f;
        float wy = y - y0f, wx = x - x0f;
        bool vy0 = (unsigned)y0 < 64u;
        bool vy1 = (unsigned)(y0 + 1) < 64u;
        bool vx0 = (unsigned)x0 < 64u;
        bool vx1 = (unsigned)(x0 + 1) < 64u;
        float w00 = (vy0 && vx0) ? (1.f - wy) * (1.f - wx) : 0.f;
        float w01 = (vy0 && vx1) ? (1.f - wy) * wx : 0.f;
        float w10 = (vy1 && vx0) ? wy * (1.f - wx) : 0.f;
        float w11 = (vy1 && vx1) ? wy * wx : 0.f;
        int cy0 = min(max(y0, 0), 63), cy1 = min(max(y0 + 1, 0), 63);
        int cx0 = min(max(x0, 0), 63), cx1 = min(max(x0 + 1, 0), 63);
        const float* p00 = nhwc + (((size_t)b * 64 + cy0) * 64 + cx0) * 256;
        const float* p01 = nhwc + (((size_t)b * 64 + cy0) * 64 + cx1) * 256;
        const float* p10 = nhwc + (((size_t)b * 64 + cy1) * 64 + cx0) * 256;
        const float* p11 = nhwc + (((size_t)b * 64 + cy1) * 64 + cx1) * 256;
        __nv_bfloat16* ch = colh + (size_t)n * KDIM + k * 256;
        __nv_bfloat16* cl = coll + (size_t)n * KDIM + k * 256;
#pragma unroll
        for (int it = 0; it < 8; it++) {
            int c = lane + it * 32;
            float v = w00 * p00[c] + w01 * p01[c] + w10 * p10[c] + w11 * p11[c];
            __nv_bfloat16 h = __float2bfloat16(v);
            ch[c] = h;
            cl[c] = __float2bfloat16(v - __bfloat162float(h));
        }
    }
}

// ---------------- rep-points epilogue ----------------
__global__ __launch_bounds__(256) void reppoints_k(const float* __restrict__ off1,
                                                   const float* __restrict__ off2,
                                                   float* __restrict__ out) {
    int idx = blockIdx.x * 256 + threadIdx.x;
    if (idx >= OFFN) return;
    int rem = idx % 73728;
    int ch = rem >> 12;
    int ij = rem & 4095;
    int i = ij >> 6, j = ij & 63;
    int k = ch >> 1;
    float init = (ch & 1) ? (float)(j + (k % 3) - 1) : (float)(i + (k / 3) - 1);
    float r1 = init + off1[idx];
    out[idx] = r1;
    out[OFFN + idx] = r1 + off2[idx];
}

// ---------------- host orchestration (2-stream overlap) ----------------
extern "C" void kernel_launch(void* const* d_in, const int* in_sizes, int n_in,
                              void* d_out, int out_size) {
    const float* feature = (const float*)d_in[0];
    const float* loc_ws  = (const float*)d_in[1];
    const float* loc_g   = (const float*)d_in[2];
    const float* loc_b   = (const float*)d_in[3];
    const float* cls_ws  = (const float*)d_in[4];
    const float* cls_g   = (const float*)d_in[5];
    const float* cls_b   = (const float*)d_in[6];
    const float* pi_w    = (const float*)d_in[7];
    const float* pio_w   = (const float*)d_in[8];
    const float* prd_w   = (const float*)d_in[9];
    const float* pro_w   = (const float*)d_in[10];
    const float* cd_w    = (const float*)d_in[11];
    const float* co_w    = (const float*)d_in[12];
    float* out = (float*)d_out;

    static int init_done = 0;
    static cudaStream_t s1, s2;
    static cudaEvent_t evRoot, evW, evF, evOff1, evE1, evE2;
    if (!init_done) {
        cudaFuncSetAttribute(gemm_big_k<0>, cudaFuncAttributeMaxDynamicSharedMemorySize, BIG2_SMEM);
        cudaFuncSetAttribute(gemm_big_k<1>, cudaFuncAttributeMaxDynamicSharedMemorySize, BIG2_SMEM);
        cudaFuncSetAttribute(gemm_conv_k<32, 256>, cudaFuncAttributeMaxDynamicSharedMemorySize, SMALL_SMEM);
        cudaFuncSetAttribute(gemm_col_k<0>, cudaFuncAttributeMaxDynamicSharedMemorySize, COL_SMEM);
        cudaFuncSetAttribute(gemm_col_k<1>, cudaFuncAttributeMaxDynamicSharedMemorySize, COL_SMEM);
        cudaStreamCreateWithFlags(&s1, cudaStreamNonBlocking);
        cudaStreamCreateWithFlags(&s2, cudaStreamNonBlocking);
        cudaEventCreateWithFlags(&evRoot, cudaEventDisableTiming);
        cudaEventCreateWithFlags(&evW, cudaEventDisableTiming);
        cudaEventCreateWithFlags(&evF, cudaEventDisableTiming);
        cudaEventCreateWithFlags(&evOff1, cudaEventDisableTiming);
        cudaEventCreateWithFlags(&evE1, cudaEventDisableTiming);
        cudaEventCreateWithFlags(&evE2, cudaEventDisableTiming);
        init_done = 1;
    }

    __nv_bfloat16 *wahi, *walo, *fhi, *flo;
    __nv_bfloat16 *t1hi, *t1lo, *u1hi, *u1lo, *col1h, *col1l, *t2hi, *t2lo, *col2h, *col2l;
    float *buf1, *buf2, *nh1, *nh2, *off1, *off2, *ws1, *ws2;
    cudaGetSymbolAddress((void**)&wahi,  g_wahi);
    cudaGetSymbolAddress((void**)&walo,  g_walo);
    cudaGetSymbolAddress((void**)&fhi,   g_fhi);
    cudaGetSymbolAddress((void**)&flo,   g_flo);
    cudaGetSymbolAddress((void**)&t1hi,  g_t1hi);
    cudaGetSymbolAddress((void**)&t1lo,  g_t1lo);
    cudaGetSymbolAddress((void**)&u1hi,  g_u1hi);
    cudaGetSymbolAddress((void**)&u1lo,  g_u1lo);
    cudaGetSymbolAddress((void**)&col1h, g_col1h);
    cudaGetSymbolAddress((void**)&col1l, g_col1l);
    cudaGetSymbolAddress((void**)&t2hi,  g_t2hi);
    cudaGetSymbolAddress((void**)&t2lo,  g_t2lo);
    cudaGetSymbolAddress((void**)&col2h, g_col2h);
    cudaGetSymbolAddress((void**)&col2l, g_col2l);
    cudaGetSymbolAddress((void**)&buf1,  g_buf1);
    cudaGetSymbolAddress((void**)&buf2,  g_buf2);
    cudaGetSymbolAddress((void**)&nh1,   g_nh1);
    cudaGetSymbolAddress((void**)&nh2,   g_nh2);
    cudaGetSymbolAddress((void**)&off1,  g_off1);
    cudaGetSymbolAddress((void**)&off2,  g_off2);
    cudaGetSymbolAddress((void**)&ws1,   g_ws1);
    cudaGetSymbolAddress((void**)&ws2,   g_ws2);

    W12 w12;
    w12.p[0] = loc_ws;           w12.m[0] = 256;
    w12.p[1] = loc_ws + WSZ;     w12.m[1] = 256;
    w12.p[2] = loc_ws + 2 * WSZ; w12.m[2] = 256;
    w12.p[3] = cls_ws;           w12.m[3] = 256;
    w12.p[4] = cls_ws + WSZ;     w12.m[4] = 256;
    w12.p[5] = cls_ws + 2 * WSZ; w12.m[5] = 256;
    w12.p[6] = pi_w;             w12.m[6] = 256;
    w12.p[7] = pio_w;            w12.m[7] = 18;
    w12.p[8] = prd_w;            w12.m[8] = 256;
    w12.p[9] = pro_w;            w12.m[9] = 18;
    w12.p[10] = cd_w;            w12.m[10] = 256;
    w12.p[11] = co_w;            w12.m[11] = 15;

    dim3 tgrid(128, 8, 4), tblk(32, 8);
    dim3 gBig2(128, 2), gSmall(64, 1), gCol(64, 2);

    cudaEventRecord(evRoot, 0);
    cudaStreamWaitEvent(s1, evRoot, 0);
    cudaStreamWaitEvent(s2, evRoot, 0);

    wconv_all_k<<<768, 256, 0, s1>>>(w12, wahi, walo);
    cudaEventRecord(evW, s1);
    tsplit_k<<<tgrid, tblk, 0, s2>>>(feature, fhi, flo, nullptr, nullptr, nullptr, nullptr);
    cudaEventRecord(evF, s2);
    cudaStreamWaitEvent(s1, evF, 0);
    cudaStreamWaitEvent(s2, evW, 0);

    // ---- s1: loc subnet -> offset1 -> offset2 branch -> reppoints ----
    for (int l = 0; l < 3; l++) {
        gemm_big_k<0><<<gBig2, 256, BIG2_SMEM, s1>>>(
            wahi + (size_t)l * PL, walo + (size_t)l * PL,
            l == 0 ? fhi : t1hi, l == 0 ? flo : t1lo, buf1, nullptr, nullptr, 256, 256 * 4096);
        gnstat_k<<<128, 256, 0, s1>>>(buf1, ws1);
        tsplit_k<<<tgrid, tblk, 0, s1>>>(buf1, t1hi, t1lo, l == 2 ? nh1 : nullptr,
                                         ws1, loc_g + l * 256, loc_b + l * 256);
    }
    gemm_big_k<1><<<gBig2, 256, BIG2_SMEM, s1>>>(
        wahi + 6 * (size_t)PL, walo + 6 * (size_t)PL, t1hi, t1lo,
        nullptr, u1hi, u1lo, 256, 0);
    gemm_conv_k<32, 256><<<gSmall, 256, SMALL_SMEM, s1>>>(
        wahi + 7 * (size_t)PL, walo + 7 * (size_t)PL, u1hi, u1lo,
        off1, 18, 18 * 4096);
    cudaEventRecord(evOff1, s1);

    deform_col_k<<<2048, 256, 0, s1>>>(nh1, off1, col1h, col1l);
    gemm_col_k<1><<<gCol, 512, COL_SMEM, s1>>>(
        wahi + 8 * (size_t)PL, walo + 8 * (size_t)PL, col1h, col1l,
        nullptr, t1hi, t1lo, 256, 0);
    gemm_conv_k<32, 256><<<gSmall, 256, SMALL_SMEM, s1>>>(
        wahi + 9 * (size_t)PL, walo + 9 * (size_t)PL, t1hi, t1lo,
        off2, 18, 18 * 4096);
    reppoints_k<<<(OFFN + 255) / 256, 256, 0, s1>>>(off1, off2, out);
    cudaEventRecord(evE1, s1);

    // ---- s2: cls subnet -> classification branch ----
    for (int l = 0; l < 3; l++) {
        gemm_big_k<0><<<gBig2, 256, BIG2_SMEM, s2>>>(
            wahi + (size_t)(3 + l) * PL, walo + (size_t)(3 + l) * PL,
            l == 0 ? fhi : t2hi, l == 0 ? flo : t2lo, buf2, nullptr, nullptr, 256, 256 * 4096);
        gnstat_k<<<128, 256, 0, s2>>>(buf2, ws2);
        tsplit_k<<<tgrid, tblk, 0, s2>>>(buf2, l == 2 ? nullptr : t2hi, l == 2 ? nullptr : t2lo,
                                         l == 2 ? nh2 : nullptr,
                                         ws2, cls_g + l * 256, cls_b + l * 256);
    }
    cudaStreamWaitEvent(s2, evOff1, 0);
    deform_col_k<<<2048, 256, 0, s2>>>(nh2, off1, col2h, col2l);
    gemm_col_k<1><<<gCol, 512, COL_SMEM, s2>>>(
        wahi + 10 * (size_t)PL, walo + 10 * (size_t)PL, col2h, col2l,
        nullptr, t2hi, t2lo, 256, 0);
    gemm_conv_k<32, 256><<<gSmall, 256, SMALL_SMEM, s2>>>(
        wahi + 11 * (size_t)PL, walo + 11 * (size_t)PL, t2hi, t2lo,
        out + 2 * OFFN, 15, 15 * 4096);
    cudaEventRecord(evE2, s2);

    cudaStreamWaitEvent(0, evE1, 0);
    cudaStreamWaitEvent(0, evE2, 0);
}

// round 17
// speedup vs baseline: 1.6701x; 1.0012x over previous
#include <cuda_runtime.h>
#include <cuda_bf16.h>
#include <cstdint>
#include <math.h>

#define NG 16384
#define OFFN (18*16384)
#define KDIM 2304
#define WSZ (256*256*9)
#define PL 589824
#define COL_SMEM 197632
#define SPL2 16896           // slab plane: 264 pix * 64B (4 rows x 66)
#define BIG2_SMEM 101376     // 2*16KB A + 2*2*SPL2 slab + pad
#define SPL 25344            // small-kernel slab plane: 396 pix * 64B
#define SMALL_SMEM 110592

// ---------------- scratch ----------------
__device__ __nv_bfloat16 g_wahi[(size_t)12*PL];
__device__ __nv_bfloat16 g_walo[(size_t)12*PL];
__device__ __nv_bfloat16 g_fhi[(size_t)NG*256];
__device__ __nv_bfloat16 g_flo[(size_t)NG*256];
__device__ __nv_bfloat16 g_t1hi[(size_t)NG*256];
__device__ __nv_bfloat16 g_t1lo[(size_t)NG*256];
__device__ __nv_bfloat16 g_u1hi[(size_t)NG*256];
__device__ __nv_bfloat16 g_u1lo[(size_t)NG*256];
__device__ float g_buf1[(size_t)NG*256];
__device__ float g_nh1[(size_t)NG*256];
__device__ __nv_bfloat16 g_col1h[(size_t)NG*KDIM];
__device__ __nv_bfloat16 g_col1l[(size_t)NG*KDIM];
__device__ float g_ws1[256];
__device__ __nv_bfloat16 g_t2hi[(size_t)NG*256];
__device__ __nv_bfloat16 g_t2lo[(size_t)NG*256];
__device__ float g_buf2[(size_t)NG*256];
__device__ float g_nh2[(size_t)NG*256];
__device__ __nv_bfloat16 g_col2h[(size_t)NG*KDIM];
__device__ __nv_bfloat16 g_col2l[(size_t)NG*KDIM];
__device__ float g_ws2[256];
__device__ float g_off1[OFFN];
__device__ float g_off2[OFFN];

// ---------------- PTX helpers ----------------
__device__ __forceinline__ uint32_t smem_u32(const void* p) {
    uint32_t a;
    asm("{ .reg .u64 t; cvta.to.shared.u64 t, %1; cvt.u32.u64 %0, t; }" : "=r"(a) : "l"(p));
    return a;
}
#define SWZ(o)   ((o) ^ (((o) >> 3) & 0x70))
#define SWZ64(o) ((o) ^ (((o) >> 3) & 0x30))

__device__ __forceinline__ void cp16(uint32_t dst, const void* src, int ss) {
    asm volatile("cp.async.cg.shared.global [%0], [%1], 16, %2;\n" :: "r"(dst), "l"(src), "r"(ss));
}
__device__ __forceinline__ void cp_commit() { asm volatile("cp.async.commit_group;\n" ::: "memory"); }
__device__ __forceinline__ void cp_wait0()  { asm volatile("cp.async.wait_group 0;\n" ::: "memory"); }
__device__ __forceinline__ void cp_wait1()  { asm volatile("cp.async.wait_group 1;\n" ::: "memory"); }

__device__ __forceinline__ void ldm4(uint32_t* r, uint32_t addr) {
    asm volatile("ldmatrix.sync.aligned.m8n8.x4.shared.b16 {%0,%1,%2,%3}, [%4];"
        : "=r"(r[0]), "=r"(r[1]), "=r"(r[2]), "=r"(r[3]) : "r"(addr));
}
__device__ __forceinline__ void mma16816(float* d, const uint32_t* a, const uint32_t* b) {
    asm volatile("mma.sync.aligned.m16n8k16.row.col.f32.bf16.bf16.f32 "
        "{%0,%1,%2,%3}, {%4,%5,%6,%7}, {%8,%9}, {%0,%1,%2,%3};"
        : "+f"(d[0]), "+f"(d[1]), "+f"(d[2]), "+f"(d[3])
        : "r"(a[0]), "r"(a[1]), "r"(a[2]), "r"(a[3]), "r"(b[0]), "r"(b[1]));
}
__device__ __forceinline__ unsigned short bfbits(float x) {
    __nv_bfloat16 h = __float2bfloat16(x);
    return *reinterpret_cast<unsigned short*>(&h);
}

// ---------------- epilogues ----------------
template<int IM>
__device__ __forceinline__ void epilogue_nchw(float acc[IM][4][4], float* out, int bstride,
                                              int M, int m0, int n0, int wm, int wn, int lane) {
    int b = n0 >> 12, ij0 = n0 & 4095;
    float* outb = out + (size_t)b * bstride + ij0;
#pragma unroll
    for (int im = 0; im < IM; im++) {
        int mrow = m0 + wm + im * 16 + (lane >> 2);
#pragma unroll
        for (int jn = 0; jn < 4; jn++) {
            int ncol = wn + jn * 8 + (lane & 3) * 2;
            if (mrow < M) {
                float2 v = make_float2(acc[im][jn][0], acc[im][jn][1]);
                *(float2*)(outb + (size_t)mrow * 4096 + ncol) = v;
            }
            if (mrow + 8 < M) {
                float2 v = make_float2(acc[im][jn][2], acc[im][jn][3]);
                *(float2*)(outb + (size_t)(mrow + 8) * 4096 + ncol) = v;
            }
        }
    }
}

// 256-thread CTA, 8 warps, IM=4, tile 128m x 128n -> NHWC hi/lo planes.
__device__ __forceinline__ void epilogue_split128(float acc[4][4][4],
                                                  __nv_bfloat16* ohi, __nv_bfloat16* olo,
                                                  float* smemf, int m0, int n0,
                                                  int tid, int wid, int wm, int wn, int lane) {
    for (int ch = 0; ch < 4; ch++) {
        __syncthreads();
        if ((wid & 3) == ch) {
#pragma unroll
            for (int im = 0; im < 4; im++) {
                int m = wm + im * 16 + (lane >> 2);
#pragma unroll
                for (int jn = 0; jn < 4; jn++) {
                    int nl = jn * 8 + (lane & 3) * 2;
                    smemf[m * 33 + nl] = acc[im][jn][0];
                    smemf[m * 33 + nl + 1] = acc[im][jn][1];
                    smemf[(m + 8) * 33 + nl] = acc[im][jn][2];
                    smemf[(m + 8) * 33 + nl + 1] = acc[im][jn][3];
                }
            }
        }
        __syncthreads();
#pragma unroll
        for (int it2 = 0; it2 < 2; it2++) {
            int item = tid + it2 * 256;
            int p = item >> 4;            // 0..31 pixel in chunk
            int cq = (item & 15) * 8;     // 8 channels
            size_t base = (size_t)(n0 + ch * 32 + p) * 256 + m0 + cq;
            uint32_t hw[4], lw[4];
#pragma unroll
            for (int i = 0; i < 4; i++) {
                float v0 = smemf[(cq + 2 * i) * 33 + p];
                float v1 = smemf[(cq + 2 * i + 1) * 33 + p];
                unsigned short h0 = bfbits(v0), h1 = bfbits(v1);
                float r0 = v0 - __bfloat162float(*reinterpret_cast<__nv_bfloat16*>(&h0));
                float r1 = v1 - __bfloat162float(*reinterpret_cast<__nv_bfloat16*>(&h1));
                hw[i] = (uint32_t)h0 | ((uint32_t)h1 << 16);
                lw[i] = (uint32_t)bfbits(r0) | ((uint32_t)bfbits(r1) << 16);
            }
            *(uint4*)(ohi + base) = make_uint4(hw[0], hw[1], hw[2], hw[3]);
            *(uint4*)(olo + base) = make_uint4(lw[0], lw[1], lw[2], lw[3]);
        }
    }
}

// 512-thread version (col GEMM split epilogue, 256-n tile) — unchanged from R9.
__device__ __forceinline__ void epilogue_split(float acc[4][4][4],
                                               __nv_bfloat16* ohi, __nv_bfloat16* olo,
                                               float* smemf, int m0, int n0,
                                               int tid, int wid, int wm, int wn, int lane) {
    for (int ch = 0; ch < 8; ch++) {
        __syncthreads();
        if ((wid & 7) == ch) {
#pragma unroll
            for (int im = 0; im < 4; im++) {
                int m = wm + im * 16 + (lane >> 2);
#pragma unroll
                for (int jn = 0; jn < 4; jn++) {
                    int nl = jn * 8 + (lane & 3) * 2;
                    smemf[m * 33 + nl] = acc[im][jn][0];
                    smemf[m * 33 + nl + 1] = acc[im][jn][1];
                    smemf[(m + 8) * 33 + nl] = acc[im][jn][2];
                    smemf[(m + 8) * 33 + nl + 1] = acc[im][jn][3];
                }
            }
        }
        __syncthreads();
        int p = tid >> 4;
        int cq = (tid & 15) * 8;
        size_t base = (size_t)(n0 + ch * 32 + p) * 256 + m0 + cq;
        uint32_t hw[4], lw[4];
#pragma unroll
        for (int i = 0; i < 4; i++) {
            float v0 = smemf[(cq + 2 * i) * 33 + p];
            float v1 = smemf[(cq + 2 * i + 1) * 33 + p];
            unsigned short h0 = bfbits(v0), h1 = bfbits(v1);
            float r0 = v0 - __bfloat162float(*reinterpret_cast<__nv_bfloat16*>(&h0));
            float r1 = v1 - __bfloat162float(*reinterpret_cast<__nv_bfloat16*>(&h1));
            hw[i] = (uint32_t)h0 | ((uint32_t)h1 << 16);
            lw[i] = (uint32_t)bfbits(r0) | ((uint32_t)bfbits(r1) << 16);
        }
        *(uint4*)(ohi + base) = make_uint4(hw[0], hw[1], hw[2], hw[3]);
        *(uint4*)(olo + base) = make_uint4(lw[0], lw[1], lw[2], lw[3]);
    }
}

// ---------------- all-weights convert ----------------
struct W12 { const float* p[12]; int m[12]; };
__global__ __launch_bounds__(256) void wconv_all_k(W12 w,
                                                   __nv_bfloat16* __restrict__ hi,
                                                   __nv_bfloat16* __restrict__ lo) {
    __shared__ float rows[4][KDIM];
    int t = blockIdx.x >> 6;
    int rb = blockIdx.x & 63;
    int tid = threadIdx.x;
    int m0 = rb * 4;
    const float* src = w.p[t];
    int Mv = w.m[t];
    for (int i = tid; i < 4 * KDIM; i += 256) {
        int r = i / KDIM, k = i - r * KDIM;
        int m = m0 + r;
        rows[r][k] = (m < Mv) ? src[(size_t)m * KDIM + k] : 0.f;
    }
    __syncthreads();
    for (int i = tid; i < 4 * KDIM; i += 256) {
        int r = i / KDIM, k = i - r * KDIM;
        int kk = k >> 8, c = k & 255;
        float v = rows[r][c * 9 + kk];
        size_t dst = (size_t)t * PL + (size_t)(m0 + r) * KDIM + k;
        __nv_bfloat16 h = __float2bfloat16(v);
        hi[dst] = h;
        lo[dst] = __float2bfloat16(v - __bfloat162float(h));
    }
}

// ---------------- GN stats ----------------
__global__ __launch_bounds__(256) void gnstat_k(const float* __restrict__ in,
                                                float* __restrict__ ws) {
    int bg = blockIdx.x;
    int b = bg >> 5, g = bg & 31;
    int tid = threadIdx.x;
    const float4* p = (const float4*)(in + ((size_t)b * 256 + g * 8) * 4096);
    float s = 0.f, s2 = 0.f;
    for (int i = tid; i < 8192; i += 256) {
        float4 v = p[i];
        s += v.x + v.y + v.z + v.w;
        s2 += v.x * v.x + v.y * v.y + v.z * v.z + v.w * v.w;
    }
    __shared__ float sA[256], sB[256];
    sA[tid] = s; sB[tid] = s2;
    __syncthreads();
    for (int st = 128; st > 0; st >>= 1) {
        if (tid < st) { sA[tid] += sA[tid + st]; sB[tid] += sB[tid + st]; }
        __syncthreads();
    }
    if (tid == 0) {
        float mean = sA[0] * (1.f / 32768.f);
        float var = sB[0] * (1.f / 32768.f) - mean * mean;
        ws[bg * 2] = mean;
        ws[bg * 2 + 1] = rsqrtf(var + 1e-5f);
    }
}

// ---------------- NCHW fp32 -> (GN affine) -> NHWC hi/lo bf16 (+fp32) ----------------
__global__ void tsplit_k(const float* __restrict__ in,
                         __nv_bfloat16* __restrict__ hi, __nv_bfloat16* __restrict__ lo,
                         float* __restrict__ f32o,
                         const float* __restrict__ ws,
                         const float* __restrict__ gamma, const float* __restrict__ beta) {
    __shared__ float t[32][33];
    int b = blockIdx.z, hw0 = blockIdx.x * 32, c0 = blockIdx.y * 32;
    int tx = threadIdx.x, ty = threadIdx.y;
    const float* ip = in + (size_t)b * 256 * 4096;
    for (int r = ty; r < 32; r += 8)
        t[r][tx] = ip[(size_t)(c0 + r) * 4096 + hw0 + tx];
    __syncthreads();
    int ch = c0 + tx;
    float sc = 1.f, sh = 0.f;
    if (ws) {
        int bg = b * 32 + (ch >> 3);
        float mean = ws[bg * 2], rstd = ws[bg * 2 + 1];
        sc = rstd * gamma[ch];
        sh = beta[ch] - mean * sc;
    }
    for (int r = ty; r < 32; r += 8) {
        float v = t[tx][r] * sc + sh;
        size_t idx = (size_t)b * 4096 * 256 + (size_t)(hw0 + r) * 256 + ch;
        if (hi) {
            __nv_bfloat16 h = __float2bfloat16(v);
            hi[idx] = h;
            lo[idx] = __float2bfloat16(v - __bfloat162float(h));
        }
        if (f32o) f32o[idx] = v;
    }
}

// ---------------- big implicit-conv GEMM: 128M x 128N, 256 thr, 2 CTA/SM ----------------
template<int EPI>
__global__ __launch_bounds__(256, 2) void gemm_big_k(
    const __nv_bfloat16* __restrict__ Ahi, const __nv_bfloat16* __restrict__ Alo,
    const __nv_bfloat16* __restrict__ Bhi, const __nv_bfloat16* __restrict__ Blo,
    float* __restrict__ out, __nv_bfloat16* __restrict__ ohi, __nv_bfloat16* __restrict__ olo,
    int M, int bstride) {
    constexpr int APL = 8192;       // A plane: 128 rows * 64B
    constexpr int AST = 2 * APL;
    constexpr int SST = 2 * SPL2;

    extern __shared__ char smx[];
    uint32_t smb = (smem_u32(smx) + 1023) & ~1023u;
    uint32_t aB = smb, sB = smb + 2 * AST;

    int tid = threadIdx.x;
    int lane = tid & 31;
    int wid = tid >> 5;
    int wm = (wid >> 2) * 64;
    int wn = (wid & 3) * 32;
    int n0 = blockIdx.x * 128;
    int m0 = blockIdx.y * 128;
    int b = n0 >> 12, ij0 = n0 & 4095;
    int i0 = ij0 >> 6;

    auto load_A = [&](int t, uint32_t dst) {
        int cg = t / 9, tap = t - cg * 9;
        int koff = tap * 256 + cg * 32;
#pragma unroll
        for (int idx = tid; idx < 1024; idx += 256) {
            int plane = idx >= 512;
            int q = idx - plane * 512;
            int row = q >> 2, c16 = q & 3;
            const __nv_bfloat16* src =
                (plane ? Alo : Ahi) + (size_t)(m0 + row) * KDIM + koff + c16 * 8;
            cp16(dst + plane * APL + SWZ64(row * 64 + c16 * 16), src, 16);
        }
    };
    // slab: 264 pixels (4 rows x 66) * 4 chunks = 1056 per plane, 2112 total
    auto load_slab = [&](int cg, uint32_t dst) {
        for (int idx = tid; idx < 2112; idx += 256) {
            int plane = idx >= 1056;
            int q = idx - plane * 1056;
            int pix = q >> 2, c16 = q & 3;
            int sy = pix / 66, sx = pix - sy * 66;
            int y = i0 - 1 + sy, x = sx - 1;
            bool v = ((unsigned)y < 64u) && ((unsigned)x < 64u);
            int yy = v ? y : 0, xx = v ? x : 0;
            const __nv_bfloat16* src = (plane ? Blo : Bhi) +
                ((((size_t)b * 64 + yy) * 64 + xx) << 8) + cg * 32 + c16 * 8;
            cp16(dst + plane * SPL2 + SWZ64(pix * 64 + c16 * 16), src, v ? 16 : 0);
        }
    };

    float acc[4][4][4];
#pragma unroll
    for (int im = 0; im < 4; im++)
#pragma unroll
        for (int jn = 0; jn < 4; jn++)
#pragma unroll
            for (int q = 0; q < 4; q++) acc[im][jn][q] = 0.f;

    int arow = lane & 15;
    int abyte = (lane >> 4) * 16;
    int mi = lane >> 3;
    int brow_off = (mi >> 1) * 8 + (lane & 7);
    int bbyte = (mi & 1) * 16;
    int b66[2];
#pragma unroll
    for (int jp = 0; jp < 2; jp++) {
        int rowb = wn + jp * 16 + brow_off;
        b66[jp] = (rowb >> 6) * 66 + (rowb & 63);
    }

    load_slab(0, sB);
    load_A(0, aB);
    cp_commit();

    for (int t = 0; t < 72; t++) {
        int cg = t / 9, tap = t - cg * 9;
        if (t + 1 < 72) {
            load_A(t + 1, aB + ((t + 1) & 1) * AST);
            if (tap == 4 && cg < 7) load_slab(cg + 1, sB + ((cg + 1) & 1) * SST);
            cp_commit();
            cp_wait1();
        } else {
            cp_wait0();
        }
        __syncthreads();

        uint32_t ab = aB + (t & 1) * AST;
        uint32_t sb = sB + (cg & 1) * SST;
        int kd = (tap * 11) >> 5;
        int tapoff = kd * 66 + (tap - kd * 3);
#pragma unroll
        for (int s = 0; s < 2; s++) {
            uint32_t bh[4][2], bl[4][2];
#pragma unroll
            for (int jp = 0; jp < 2; jp++) {
                int pix = b66[jp] + tapoff;
                uint32_t off = SWZ64(pix * 64 + s * 32 + bbyte);
                uint32_t r4[4];
                ldm4(r4, sb + off);
                bh[jp * 2][0] = r4[0]; bh[jp * 2][1] = r4[1];
                bh[jp * 2 + 1][0] = r4[2]; bh[jp * 2 + 1][1] = r4[3];
                ldm4(r4, sb + SPL2 + off);
                bl[jp * 2][0] = r4[0]; bl[jp * 2][1] = r4[1];
                bl[jp * 2 + 1][0] = r4[2]; bl[jp * 2 + 1][1] = r4[3];
            }
#pragma unroll
            for (int im = 0; im < 4; im++) {
                int rowa = wm + im * 16 + arow;
                uint32_t offa = SWZ64(rowa * 64 + s * 32 + abyte);
                uint32_t ah[4], al[4];
                ldm4(ah, ab + offa);
                ldm4(al, ab + APL + offa);
#pragma unroll
                for (int jn = 0; jn < 4; jn++) {
                    mma16816(acc[im][jn], ah, bh[jn]);
                    mma16816(acc[im][jn], ah, bl[jn]);
                    mma16816(acc[im][jn], al, bh[jn]);
                }
            }
        }
        __syncthreads();
    }

    if (EPI == 0) {
        epilogue_nchw<4>(acc, out, bstride, M, m0, n0, wm, wn, lane);
    } else {
        epilogue_split128(acc, ohi, olo, (float*)smx, m0, n0, tid, wid, wm, wn, lane);
    }
}

// ---------------- small implicit-conv GEMM (M=18/15): R9 template path ----------------
template<int MROWS, int NTHREADS>
__global__ __launch_bounds__(NTHREADS, 1) void gemm_conv_k(
    const __nv_bfloat16* __restrict__ Ahi, const __nv_bfloat16* __restrict__ Alo,
    const __nv_bfloat16* __restrict__ Bhi, const __nv_bfloat16* __restrict__ Blo,
    float* __restrict__ out, int M, int bstride) {
    constexpr int MW = NTHREADS / 256;
    constexpr int IM = MROWS / (MW * 16);
    constexpr int APL = MROWS * 64;
    constexpr int AST = 2 * APL;
    constexpr int SST = 2 * SPL;

    extern __shared__ char smx[];
    uint32_t smb = (smem_u32(smx) + 1023) & ~1023u;
    uint32_t aB = smb, sB = smb + 2 * AST;

    int tid = threadIdx.x;
    int lane = tid & 31;
    int wid = tid >> 5;
    int wm = (wid >> 3) * (IM * 16);
    int wn = (wid & 7) * 32;
    int n0 = blockIdx.x * 256;
    int m0 = blockIdx.y * MROWS;
    int b = n0 >> 12, ij0 = n0 & 4095;
    int i0 = ij0 >> 6;

    auto load_A = [&](int t, uint32_t dst) {
        int cg = t / 9, tap = t - cg * 9;
        int koff = tap * 256 + cg * 32;
#pragma unroll
        for (int idx = tid; idx < MROWS * 8; idx += NTHREADS) {
            int plane = idx >= MROWS * 4;
            int q = idx - plane * (MROWS * 4);
            int row = q >> 2, c16 = q & 3;
            const __nv_bfloat16* src =
                (plane ? Alo : Ahi) + (size_t)(m0 + row) * KDIM + koff + c16 * 8;
            cp16(dst + plane * APL + SWZ64(row * 64 + c16 * 16), src, 16);
        }
    };
    auto load_slab = [&](int cg, uint32_t dst) {
        for (int idx = tid; idx < 3168; idx += NTHREADS) {
            int plane = idx >= 1584;
            int q = idx - plane * 1584;
            int pix = q >> 2, c16 = q & 3;
            int sy = pix / 66, sx = pix - sy * 66;
            int y = i0 - 1 + sy, x = sx - 1;
            bool v = ((unsigned)y < 64u) && ((unsigned)x < 64u);
            int yy = v ? y : 0, xx = v ? x : 0;
            const __nv_bfloat16* src = (plane ? Blo : Bhi) +
                ((((size_t)b * 64 + yy) * 64 + xx) << 8) + cg * 32 + c16 * 8;
            cp16(dst + plane * SPL + SWZ64(pix * 64 + c16 * 16), src, v ? 16 : 0);
        }
    };

    float acc[IM][4][4];
#pragma unroll
    for (int im = 0; im < IM; im++)
#pragma unroll
        for (int jn = 0; jn < 4; jn++)
#pragma unroll
            for (int q = 0; q < 4; q++) acc[im][jn][q] = 0.f;

    int arow = lane & 15;
    int abyte = (lane >> 4) * 16;
    int mi = lane >> 3;
    int brow_off = (mi >> 1) * 8 + (lane & 7);
    int bbyte = (mi & 1) * 16;
    int b66[2];
#pragma unroll
    for (int jp = 0; jp < 2; jp++) {
        int rowb = wn + jp * 16 + brow_off;
        b66[jp] = (rowb >> 6) * 66 + (rowb & 63);
    }

    load_slab(0, sB);
    load_A(0, aB);
    cp_commit();

    for (int t = 0; t < 72; t++) {
        int cg = t / 9, tap = t - cg * 9;
        if (t + 1 < 72) {
            load_A(t + 1, aB + ((t + 1) & 1) * AST);
            if (tap == 4 && cg < 7) load_slab(cg + 1, sB + ((cg + 1) & 1) * SST);
            cp_commit();
            cp_wait1();
        } else {
            cp_wait0();
        }
        __syncthreads();

        uint32_t ab = aB + (t & 1) * AST;
        uint32_t sb = sB + (cg & 1) * SST;
        int kd = (tap * 11) >> 5;
        int tapoff = kd * 66 + (tap - kd * 3);
#pragma unroll
        for (int s = 0; s < 2; s++) {
            uint32_t bh[4][2], bl[4][2];
#pragma unroll
            for (int jp = 0; jp < 2; jp++) {
                int pix = b66[jp] + tapoff;
                uint32_t off = SWZ64(pix * 64 + s * 32 + bbyte);
                uint32_t r4[4];
                ldm4(r4, sb + off);
                bh[jp * 2][0] = r4[0]; bh[jp * 2][1] = r4[1];
                bh[jp * 2 + 1][0] = r4[2]; bh[jp * 2 + 1][1] = r4[3];
                ldm4(r4, sb + SPL + off);
                bl[jp * 2][0] = r4[0]; bl[jp * 2][1] = r4[1];
                bl[jp * 2 + 1][0] = r4[2]; bl[jp * 2 + 1][1] = r4[3];
            }
#pragma unroll
            for (int im = 0; im < IM; im++) {
                int rowa = wm + im * 16 + arow;
                uint32_t offa = SWZ64(rowa * 64 + s * 32 + abyte);
                uint32_t ah[4], al[4];
                ldm4(ah, ab + offa);
                ldm4(al, ab + APL + offa);
#pragma unroll
                for (int jn = 0; jn < 4; jn++) {
                    mma16816(acc[im][jn], ah, bh[jn]);
                    mma16816(acc[im][jn], ah, bl[jn]);
                    mma16816(acc[im][jn], al, bh[jn]);
                }
            }
        }
        __syncthreads();
    }

    epilogue_nchw<IM>(acc, out, bstride, M, m0, n0, wm, wn, lane);
}

// ---------------- col-based GEMM for deform convs (R9, unchanged) ----------------
template<int EPI>
__global__ __launch_bounds__(512, 1) void gemm_col_k(const __nv_bfloat16* __restrict__ Ahi,
                                                     const __nv_bfloat16* __restrict__ Alo,
                                                     const __nv_bfloat16* __restrict__ Bhi,
                                                     const __nv_bfloat16* __restrict__ Blo,
                                                     float* __restrict__ out,
                                                     __nv_bfloat16* __restrict__ ohi,
                                                     __nv_bfloat16* __restrict__ olo,
                                                     int M, int bstride) {
    extern __shared__ char smx[];
    uint32_t smb = (smem_u32(smx) + 1023) & ~1023u;
    int tid = threadIdx.x;
    int lane = tid & 31;
    int wid = tid >> 5;
    int wm = (wid >> 3) * 64;
    int wn = (wid & 7) * 32;
    int n0 = blockIdx.x * 256;
    int m0 = blockIdx.y * 128;

    auto load_stage = [&](int t, uint32_t sb) {
        int kk = t >> 2, cg = t & 3;
        int koff = kk * 256 + cg * 64;
#pragma unroll
        for (int qi = 0; qi < 12; qi++) {
            int q = qi * 512 + tid;
            if (qi < 4) {
                int plane = (q >> 10) & 1;
                int qq = q & 1023;
                int row = qq >> 3, c16 = qq & 7;
                const __nv_bfloat16* src =
                    (plane ? Alo : Ahi) + (size_t)(m0 + row) * KDIM + koff + c16 * 8;
                cp16(sb + plane * 16384 + SWZ(row * 128 + c16 * 16), src, 16);
            } else {
                int qb = q - 2048;
                int plane = qb >> 11;
                int qq = qb & 2047;
                int row = qq >> 3, c16 = qq & 7;
                const __nv_bfloat16* src =
                    (plane ? Blo : Bhi) + (size_t)(n0 + row) * KDIM + koff + c16 * 8;
                cp16(sb + 32768 + plane * 32768 + SWZ(row * 128 + c16 * 16), src, 16);
            }
        }
    };

    float acc[4][4][4];
#pragma unroll
    for (int im = 0; im < 4; im++)
#pragma unroll
        for (int jn = 0; jn < 4; jn++)
#pragma unroll
            for (int q = 0; q < 4; q++) acc[im][jn][q] = 0.f;

    load_stage(0, smb);
    cp_commit();

    int arow_off = (lane & 15);
    int abyte = (lane >> 4) * 16;
    int mi = lane >> 3;
    int brow_off = (mi >> 1) * 8 + (lane & 7);
    int bbyte = (mi & 1) * 16;

    for (int t = 0; t < 36; t++) {
        if (t + 1 < 36) {
            load_stage(t + 1, smb + ((t + 1) & 1) * 98304);
            cp_commit();
            cp_wait1();
        } else {
            cp_wait0();
        }
        __syncthreads();

        uint32_t sb = smb + (t & 1) * 98304;
        uint32_t ahB = sb, alB = sb + 16384, bhB = sb + 32768, blB = sb + 65536;
#pragma unroll
        for (int s = 0; s < 4; s++) {
            uint32_t bh[4][2], bl[4][2];
#pragma unroll
            for (int jp = 0; jp < 2; jp++) {
                int rowb = wn + jp * 16 + brow_off;
                uint32_t off = SWZ(rowb * 128 + s * 32 + bbyte);
                uint32_t r4[4];
                ldm4(r4, bhB + off);
                bh[jp * 2][0] = r4[0]; bh[jp * 2][1] = r4[1];
                bh[jp * 2 + 1][0] = r4[2]; bh[jp * 2 + 1][1] = r4[3];
                ldm4(r4, blB + off);
                bl[jp * 2][0] = r4[0]; bl[jp * 2][1] = r4[1];
                bl[jp * 2 + 1][0] = r4[2]; bl[jp * 2 + 1][1] = r4[3];
            }
#pragma unroll
            for (int im = 0; im < 4; im++) {
                int rowa = wm + im * 16 + arow_off;
                uint32_t off = SWZ(rowa * 128 + s * 32 + abyte);
                uint32_t ah[4], al[4];
                ldm4(ah, ahB + off);
                ldm4(al, alB + off);
#pragma unroll
                for (int jn = 0; jn < 4; jn++) {
                    mma16816(acc[im][jn], ah, bh[jn]);
                    mma16816(acc[im][jn], ah, bl[jn]);
                    mma16816(acc[im][jn], al, bh[jn]);
                }
            }
        }
        __syncthreads();
    }

    if (EPI == 0) {
        epilogue_nchw<4>(acc, out, bstride, M, m0, n0, wm, wn, lane);
    } else {
        epilogue_split(acc, ohi, olo, (float*)smx, m0, n0, tid, wid, wm, wn, lane);
    }
}

// ---------------- deformable bilinear gather -> bf16 hi/lo col planes ----------------
__global__ __launch_bounds__(256) void deform_col_k(const float* __restrict__ nhwc,
                                                    const float* __restrict__ off,
                                                    __nv_bfloat16* __restrict__ colh,
                                                    __nv_bfloat16* __restrict__ coll) {
    int warp = (blockIdx.x * 256 + threadIdx.x) >> 5;
    int lane = threadIdx.x & 31;
    if (warp >= NG) return;
    int n = warp;
    int b = n >> 12, ij = n & 4095, i = ij >> 6, j = ij & 63;
    const float* offb = off + (size_t)b * 18 * 4096 + ij;
#pragma unroll
    for (int k = 0; k < 9; k++) {
        float dy = offb[(size_t)(2 * k) << 12];
        float dx = offb[(size_t)(2 * k + 1) << 12];
        float y = dy + (float)(i - 1 + k / 3);
        float x = dx + (float)(j - 1 + k % 3);
        float y0f = floorf(y), x0f = floorf(x);
        int y0 = (int)y0f, x0 = (int)x0f;
        float wy = y - y0f, wx = x - x0f;
        bool vy0 = (unsigned)y0 < 64u;
        bool vy1 = (unsigned)(y0 + 1) < 64u;
        bool vx0 = (unsigned)x0 < 64u;
        bool vx1 = (unsigned)(x0 + 1) < 64u;
        float w00 = (vy0 && vx0) ? (1.f - wy) * (1.f - wx) : 0.f;
        float w01 = (vy0 && vx1) ? (1.f - wy) * wx : 0.f;
        float w10 = (vy1 && vx0) ? wy * (1.f - wx) : 0.f;
        float w11 = (vy1 && vx1) ? wy * wx : 0.f;
        int cy0 = min(max(y0, 0), 63), cy1 = min(max(y0 + 1, 0), 63);
        int cx0 = min(max(x0, 0), 63), cx1 = min(max(x0 + 1, 0), 63);
        const float* p00 = nhwc + (((size_t)b * 64 + cy0) * 64 + cx0) * 256;
        const float* p01 = nhwc + (((size_t)b * 64 + cy0) * 64 + cx1) * 256;
        const float* p10 = nhwc + (((size_t)b * 64 + cy1) * 64 + cx0) * 256;
        const float* p11 = nhwc + (((size_t)b * 64 + cy1) * 64 + cx1) * 256;
        __nv_bfloat16* ch = colh + (size_t)n * KDIM + k * 256;
        __nv_bfloat16* cl = coll + (size_t)n * KDIM + k * 256;
#pragma unroll
        for (int it = 0; it < 8; it++) {
            int c = lane + it * 32;
            float v = w00 * p00[c] + w01 * p01[c] + w10 * p10[c] + w11 * p11[c];
            __nv_bfloat16 h = __float2bfloat16(v);
            ch[c] = h;
            cl[c] = __float2bfloat16(v - __bfloat162float(h));
        }
    }
}

// ---------------- rep-points epilogue ----------------
__global__ __launch_bounds__(256) void reppoints_k(const float* __restrict__ off1,
                                                   const float* __restrict__ off2,
                                                   float* __restrict__ out) {
    int idx = blockIdx.x * 256 + threadIdx.x;
    if (idx >= OFFN) return;
    int rem = idx % 73728;
    int ch = rem >> 12;
    int ij = rem & 4095;
    int i = ij >> 6, j = ij & 63;
    int k = ch >> 1;
    float init = (ch & 1) ? (float)(j + (k % 3) - 1) : (float)(i + (k / 3) - 1);
    float r1 = init + off1[idx];
    out[idx] = r1;
    out[OFFN + idx] = r1 + off2[idx];
}

// ---------------- host orchestration (2-stream overlap) ----------------
extern "C" void kernel_launch(void* const* d_in, const int* in_sizes, int n_in,
                              void* d_out, int out_size) {
    const float* feature = (const float*)d_in[0];
    const float* loc_ws  = (const float*)d_in[1];
    const float* loc_g   = (const float*)d_in[2];
    const float* loc_b   = (const float*)d_in[3];
    const float* cls_ws  = (const float*)d_in[4];
    const float* cls_g   = (const float*)d_in[5];
    const float* cls_b   = (const float*)d_in[6];
    const float* pi_w    = (const float*)d_in[7];
    const float* pio_w   = (const float*)d_in[8];
    const float* prd_w   = (const float*)d_in[9];
    const float* pro_w   = (const float*)d_in[10];
    const float* cd_w    = (const float*)d_in[11];
    const float* co_w    = (const float*)d_in[12];
    float* out = (float*)d_out;

    static int init_done = 0;
    static cudaStream_t s1, s2;
    static cudaEvent_t evRoot, evW, evF, evOff1, evE1, evE2;
    if (!init_done) {
        cudaFuncSetAttribute(gemm_big_k<0>, cudaFuncAttributeMaxDynamicSharedMemorySize, BIG2_SMEM);
        cudaFuncSetAttribute(gemm_big_k<1>, cudaFuncAttributeMaxDynamicSharedMemorySize, BIG2_SMEM);
        cudaFuncSetAttribute(gemm_conv_k<32, 256>, cudaFuncAttributeMaxDynamicSharedMemorySize, SMALL_SMEM);
        cudaFuncSetAttribute(gemm_col_k<0>, cudaFuncAttributeMaxDynamicSharedMemorySize, COL_SMEM);
        cudaFuncSetAttribute(gemm_col_k<1>, cudaFuncAttributeMaxDynamicSharedMemorySize, COL_SMEM);
        cudaStreamCreateWithFlags(&s1, cudaStreamNonBlocking);
        cudaStreamCreateWithFlags(&s2, cudaStreamNonBlocking);
        cudaEventCreateWithFlags(&evRoot, cudaEventDisableTiming);
        cudaEventCreateWithFlags(&evW, cudaEventDisableTiming);
        cudaEventCreateWithFlags(&evF, cudaEventDisableTiming);
        cudaEventCreateWithFlags(&evOff1, cudaEventDisableTiming);
        cudaEventCreateWithFlags(&evE1, cudaEventDisableTiming);
        cudaEventCreateWithFlags(&evE2, cudaEventDisableTiming);
        init_done = 1;
    }

    __nv_bfloat16 *wahi, *walo, *fhi, *flo;
    __nv_bfloat16 *t1hi, *t1lo, *u1hi, *u1lo, *col1h, *col1l, *t2hi, *t2lo, *col2h, *col2l;
    float *buf1, *buf2, *nh1, *nh2, *off1, *off2, *ws1, *ws2;
    cudaGetSymbolAddress((void**)&wahi,  g_wahi);
    cudaGetSymbolAddress((void**)&walo,  g_walo);
    cudaGetSymbolAddress((void**)&fhi,   g_fhi);
    cudaGetSymbolAddress((void**)&flo,   g_flo);
    cudaGetSymbolAddress((void**)&t1hi,  g_t1hi);
    cudaGetSymbolAddress((void**)&t1lo,  g_t1lo);
    cudaGetSymbolAddress((void**)&u1hi,  g_u1hi);
    cudaGetSymbolAddress((void**)&u1lo,  g_u1lo);
    cudaGetSymbolAddress((void**)&col1h, g_col1h);
    cudaGetSymbolAddress((void**)&col1l, g_col1l);
    cudaGetSymbolAddress((void**)&t2hi,  g_t2hi);
    cudaGetSymbolAddress((void**)&t2lo,  g_t2lo);
    cudaGetSymbolAddress((void**)&col2h, g_col2h);
    cudaGetSymbolAddress((void**)&col2l, g_col2l);
    cudaGetSymbolAddress((void**)&buf1,  g_buf1);
    cudaGetSymbolAddress((void**)&buf2,  g_buf2);
    cudaGetSymbolAddress((void**)&nh1,   g_nh1);
    cudaGetSymbolAddress((void**)&nh2,   g_nh2);
    cudaGetSymbolAddress((void**)&off1,  g_off1);
    cudaGetSymbolAddress((void**)&off2,  g_off2);
    cudaGetSymbolAddress((void**)&ws1,   g_ws1);
    cudaGetSymbolAddress((void**)&ws2,   g_ws2);

    W12 w12;
    w12.p[0] = loc_ws;           w12.m[0] = 256;
    w12.p[1] = loc_ws + WSZ;     w12.m[1] = 256;
    w12.p[2] = loc_ws + 2 * WSZ; w12.m[2] = 256;
    w12.p[3] = cls_ws;           w12.m[3] = 256;
    w12.p[4] = cls_ws + WSZ;     w12.m[4] = 256;
    w12.p[5] = cls_ws + 2 * WSZ; w12.m[5] = 256;
    w12.p[6] = pi_w;             w12.m[6] = 256;
    w12.p[7] = pio_w;            w12.m[7] = 18;
    w12.p[8] = prd_w;            w12.m[8] = 256;
    w12.p[9] = pro_w;            w12.m[9] = 18;
    w12.p[10] = cd_w;            w12.m[10] = 256;
    w12.p[11] = co_w;            w12.m[11] = 15;

    dim3 tgrid(128, 8, 4), tblk(32, 8);
    dim3 gBig2(128, 2), gSmall(64, 1), gCol(64, 2);

    cudaEventRecord(evRoot, 0);
    cudaStreamWaitEvent(s1, evRoot, 0);
    cudaStreamWaitEvent(s2, evRoot, 0);

    wconv_all_k<<<768, 256, 0, s1>>>(w12, wahi, walo);
    cudaEventRecord(evW, s1);
    tsplit_k<<<tgrid, tblk, 0, s2>>>(feature, fhi, flo, nullptr, nullptr, nullptr, nullptr);
    cudaEventRecord(evF, s2);
    cudaStreamWaitEvent(s1, evF, 0);
    cudaStreamWaitEvent(s2, evW, 0);

    // ---- s1: loc subnet -> offset1 -> offset2 branch -> reppoints ----
    for (int l = 0; l < 3; l++) {
        gemm_big_k<0><<<gBig2, 256, BIG2_SMEM, s1>>>(
            wahi + (size_t)l * PL, walo + (size_t)l * PL,
            l == 0 ? fhi : t1hi, l == 0 ? flo : t1lo, buf1, nullptr, nullptr, 256, 256 * 4096);
        gnstat_k<<<128, 256, 0, s1>>>(buf1, ws1);
        tsplit_k<<<tgrid, tblk, 0, s1>>>(buf1, t1hi, t1lo, l == 2 ? nh1 : nullptr,
                                         ws1, loc_g + l * 256, loc_b + l * 256);
    }
    gemm_big_k<1><<<gBig2, 256, BIG2_SMEM, s1>>>(
        wahi + 6 * (size_t)PL, walo + 6 * (size_t)PL, t1hi, t1lo,
        nullptr, u1hi, u1lo, 256, 0);
    gemm_conv_k<32, 256><<<gSmall, 256, SMALL_SMEM, s1>>>(
        wahi + 7 * (size_t)PL, walo + 7 * (size_t)PL, u1hi, u1lo,
        off1, 18, 18 * 4096);
    cudaEventRecord(evOff1, s1);

    deform_col_k<<<2048, 256, 0, s1>>>(nh1, off1, col1h, col1l);
    gemm_col_k<1><<<gCol, 512, COL_SMEM, s1>>>(
        wahi + 8 * (size_t)PL, walo + 8 * (size_t)PL, col1h, col1l,
        nullptr, t1hi, t1lo, 256, 0);
    gemm_conv_k<32, 256><<<gSmall, 256, SMALL_SMEM, s1>>>(
        wahi + 9 * (size_t)PL, walo + 9 * (size_t)PL, t1hi, t1lo,
        off2, 18, 18 * 4096);
    reppoints_k<<<(OFFN + 255) / 256, 256, 0, s1>>>(off1, off2, out);
    cudaEventRecord(evE1, s1);

    // ---- s2: cls subnet -> classification branch ----
    for (int l = 0; l < 3; l++) {
        gemm_big_k<0><<<gBig2, 256, BIG2_SMEM, s2>>>(
            wahi + (size_t)(3 + l) * PL, walo + (size_t)(3 + l) * PL,
            l == 0 ? fhi : t2hi, l == 0 ? flo : t2lo, buf2, nullptr, nullptr, 256, 256 * 4096);
        gnstat_k<<<128, 256, 0, s2>>>(buf2, ws2);
        tsplit_k<<<tgrid, tblk, 0, s2>>>(buf2, l == 2 ? nullptr : t2hi, l == 2 ? nullptr : t2lo,
                                         l == 2 ? nh2 : nullptr,
                                         ws2, cls_g + l * 256, cls_b + l * 256);
    }
    cudaStreamWaitEvent(s2, evOff1, 0);
    deform_col_k<<<2048, 256, 0, s2>>>(nh2, off1, col2h, col2l);
    gemm_col_k<1><<<gCol, 512, COL_SMEM, s2>>>(
        wahi + 10 * (size_t)PL, walo + 10 * (size_t)PL, col2h, col2l,
        nullptr, t2hi, t2lo, 256, 0);
    gemm_conv_k<32, 256><<<gSmall, 256, SMALL_SMEM, s2>>>(
        wahi + 11 * (size_t)PL, walo + 11 * (size_t)PL, t2hi, t2lo,
        out + 2 * OFFN, 15, 15 * 4096);
    cudaEventRecord(evE2, s2);

    cudaStreamWaitEvent(0, evE1, 0);
    cudaStreamWaitEvent(0, evE2, 0);
}